// round 9
// baseline (speedup 1.0000x reference)
#include <cuda_runtime.h>
#include <cuda_bf16.h>
#include <math.h>
#include <stdint.h>

#define B_ROWS 16384
#define IN_DIM 768
#define ENC_DIM 500
#define ZE_NPAD 512
#define KCLS 43
#define VDIM 1024
#define CAT_RAW 1067
#define CAT_LD  1088   // multiple of 64

// ---------------- scratch ----------------
__device__ uint32_t g_xh [(size_t)B_ROWS * IN_DIM / 2];
__device__ uint32_t g_xl [(size_t)B_ROWS * IN_DIM / 2];
__device__ uint32_t g_weh[(size_t)ZE_NPAD * IN_DIM / 2];
__device__ uint32_t g_wel[(size_t)ZE_NPAD * IN_DIM / 2];
__device__ uint32_t g_w1h[(size_t)VDIM * IN_DIM / 2];
__device__ uint32_t g_w1l[(size_t)VDIM * IN_DIM / 2];
__device__ uint32_t g_wdh[(size_t)IN_DIM * CAT_LD / 2];
__device__ uint32_t g_wdl[(size_t)IN_DIM * CAT_LD / 2];
__device__ float    g_hf [(size_t)B_ROWS * VDIM];            // fp32 h
__device__ int8_t   g_q1a[(size_t)B_ROWS * VDIM];            // h quant slices
__device__ int8_t   g_q2a[(size_t)B_ROWS * VDIM];
__device__ int8_t   g_q1b[(size_t)2 * VDIM * VDIM];          // W2 quant slices
__device__ int8_t   g_q2b[(size_t)2 * VDIM * VDIM];
__device__ float    g_sa [B_ROWS];
__device__ float    g_sb [2 * VDIM];
__device__ uint32_t g_cath[(size_t)B_ROWS * CAT_LD / 2];
__device__ uint32_t g_catl[(size_t)B_ROWS * CAT_LD / 2];
__device__ float g_ml [(size_t)B_ROWS * 2 * VDIM];
__device__ float g_G  [(size_t)KCLS * IN_DIM];
__device__ float g_lb [KCLS];
__device__ float g_klp[B_ROWS];
__device__ float g_ze_s[(size_t)B_ROWS * ENC_DIM];
__device__ float g_zq_s[(size_t)B_ROWS * ENC_DIM];
__device__ float g_lg_s[(size_t)B_ROWS * KCLS];
__device__ float g_kl_s[1];
__device__ int   g_mask_mode;

// ---------------- helpers ----------------
__device__ __forceinline__ uint32_t smem_to_u32(const void* p) {
    uint32_t a;
    asm("{ .reg .u64 t; cvta.to.shared.u64 t, %1; cvt.u32.u64 %0, t; }" : "=r"(a) : "l"(p));
    return a;
}
#define SWZ(b) ((b) ^ (((b) >> 3) & 0x70))
#define CP16(d, s)  asm volatile("cp.async.cg.shared.global [%0], [%1], 16;" :: "r"(d), "l"(s) : "memory")
#define CP_COMMIT() asm volatile("cp.async.commit_group;" ::: "memory")
#define CP_WAIT0()  asm volatile("cp.async.wait_group 0;" ::: "memory")
#define CP_WAIT1()  asm volatile("cp.async.wait_group 1;" ::: "memory")

__device__ __forceinline__ void ldsm_x4(uint32_t* r, uint32_t addr) {
    asm volatile("ldmatrix.sync.aligned.m8n8.x4.shared.b16 {%0,%1,%2,%3}, [%4];"
        : "=r"(r[0]), "=r"(r[1]), "=r"(r[2]), "=r"(r[3]) : "r"(addr));
}
__device__ __forceinline__ void mma16816(float* c, const uint32_t* a, const uint32_t* b) {
    asm volatile("mma.sync.aligned.m16n8k16.row.col.f32.bf16.bf16.f32 "
        "{%0,%1,%2,%3}, {%4,%5,%6,%7}, {%8,%9}, {%0,%1,%2,%3};"
        : "+f"(c[0]), "+f"(c[1]), "+f"(c[2]), "+f"(c[3])
        : "r"(a[0]), "r"(a[1]), "r"(a[2]), "r"(a[3]), "r"(b[0]), "r"(b[1]));
}
__device__ __forceinline__ void mma_s8(int* c, const uint32_t* a, const uint32_t* b) {
    asm volatile("mma.sync.aligned.m16n8k32.row.col.s32.s8.s8.s32 "
        "{%0,%1,%2,%3}, {%4,%5,%6,%7}, {%8,%9}, {%0,%1,%2,%3};"
        : "+r"(c[0]), "+r"(c[1]), "+r"(c[2]), "+r"(c[3])
        : "r"(a[0]), "r"(a[1]), "r"(a[2]), "r"(a[3]), "r"(b[0]), "r"(b[1]));
}
__device__ __forceinline__ void split2(float v0, float v1, uint32_t& H, uint32_t& L) {
    uint32_t u0 = __float_as_uint(v0), u1 = __float_as_uint(v1);
    H = __byte_perm(u0, u1, 0x7632);
    float l0 = v0 - __uint_as_float(u0 & 0xFFFF0000u);
    float l1 = v1 - __uint_as_float(u1 & 0xFFFF0000u);
    asm("cvt.rn.bf16x2.f32 %0, %1, %2;" : "=r"(L) : "f"(l1), "f"(l0));
}
__device__ __forceinline__ float fast_exp(float x) {
    float r;
    asm("ex2.approx.ftz.f32 %0, %1;" : "=f"(r) : "f"(x * 1.4426950408889634f));
    return r;
}

// ---------------- 2-stage pipelined mma.sync bf16x3 GEMM (proven) ----------------
#define ST_BYTES 65536u
#define GEMM_DYN (2 * 65536 + 1024)

__device__ __forceinline__ void load_chunk(uint32_t base, int tid, int m0, int n0, int k0,
    const uint16_t* Ah, const uint16_t* Al, int lda,
    const uint16_t* Bh, const uint16_t* Bl, int ldb)
{
#pragma unroll
    for (int it = 0; it < 4; it++) {
        int idx = it * 256 + tid;
        int row = idx >> 3, u = idx & 7;
        uint32_t off = SWZ((uint32_t)(row * 128 + u * 16));
        size_t ao = (size_t)(m0 + row) * lda + k0 + u * 8;
        size_t bo = (size_t)(n0 + row) * ldb + k0 + u * 8;
        CP16(base + off,           Ah + ao);
        CP16(base + 16384u + off,  Al + ao);
        CP16(base + 32768u + off,  Bh + bo);
        CP16(base + 49152u + off,  Bl + bo);
    }
}

// mode: 0 = fp32 C (+bias,+relu,col-guard), 1 = split bf16 hi/lo C
__global__ __launch_bounds__(256, 1)
void gemm_bf3(const uint16_t* __restrict__ Ah, const uint16_t* __restrict__ Al, int lda,
              const uint16_t* __restrict__ Bh, const uint16_t* __restrict__ Bl, int ldb,
              const float* __restrict__ bias,
              float* __restrict__ Cf, uint16_t* __restrict__ Ch, uint16_t* __restrict__ Cl,
              int ldc, int nOut, int K, int relu, int mode)
{
    extern __shared__ char smem[];
    const uint32_t tiles = (smem_to_u32(smem) + 1023) & ~1023u;
    const int tid = threadIdx.x, wid = tid >> 5, lane = tid & 31;
    const int m0 = blockIdx.y * 128, n0 = blockIdx.x * 128;
    const int wm = (wid >> 2) * 64, wn = (wid & 3) * 32;

    float acc[4][4][4];
#pragma unroll
    for (int i = 0; i < 4; i++)
#pragma unroll
        for (int j = 0; j < 4; j++)
#pragma unroll
            for (int q = 0; q < 4; q++) acc[i][j][q] = 0.f;

    const uint32_t aRowByte = (uint32_t)(wm + (lane & 15)) * 128u;
    const uint32_t aKoff    = (uint32_t)((lane >> 4) * 16);
    const uint32_t bRowByte = (uint32_t)(wn + (lane & 7) + ((lane >> 4) << 3)) * 128u;
    const uint32_t bKoff    = (uint32_t)(((lane >> 3) & 1) * 16);

    const int S = K / 64;
    load_chunk(tiles, tid, m0, n0, 0, Ah, Al, lda, Bh, Bl, ldb);
    CP_COMMIT();

    for (int s = 0; s < S; s++) {
        if (s + 1 < S) {
            load_chunk(tiles + ((s + 1) & 1) * ST_BYTES, tid, m0, n0, (s + 1) * 64,
                       Ah, Al, lda, Bh, Bl, ldb);
            CP_COMMIT();
            CP_WAIT1();
        } else {
            CP_WAIT0();
        }
        __syncthreads();

        const uint32_t pah = tiles + (s & 1) * ST_BYTES;
        const uint32_t pal = pah + 16384u, pbh = pah + 32768u, pbl = pah + 49152u;
#pragma unroll
        for (int kk = 0; kk < 4; kk++) {
            const uint32_t kb = (uint32_t)(kk * 32);
            uint32_t ah[4][4], al[4][4], bh[2][4], bl[2][4];
#pragma unroll
            for (int mt = 0; mt < 4; mt++) {
                uint32_t ro = SWZ(aRowByte + (uint32_t)(mt * 2048) + kb + aKoff);
                ldsm_x4(ah[mt], pah + ro);
                ldsm_x4(al[mt], pal + ro);
            }
#pragma unroll
            for (int nb = 0; nb < 2; nb++) {
                uint32_t ro = SWZ(bRowByte + (uint32_t)(nb * 2048) + kb + bKoff);
                ldsm_x4(bh[nb], pbh + ro);
                ldsm_x4(bl[nb], pbl + ro);
            }
#pragma unroll
            for (int mt = 0; mt < 4; mt++)
#pragma unroll
                for (int nt = 0; nt < 4; nt++) {
                    const uint32_t* bhp = &bh[nt >> 1][(nt & 1) * 2];
                    const uint32_t* blp = &bl[nt >> 1][(nt & 1) * 2];
                    mma16816(acc[mt][nt], ah[mt], bhp);
                    mma16816(acc[mt][nt], al[mt], bhp);
                    mma16816(acc[mt][nt], ah[mt], blp);
                }
        }
        __syncthreads();
    }

    if (mode == 0) {
#pragma unroll
        for (int mt = 0; mt < 4; mt++) {
            const int r0 = m0 + wm + mt * 16 + (lane >> 2);
            float* crow0 = Cf + (size_t)r0 * ldc;
            float* crow8 = Cf + (size_t)(r0 + 8) * ldc;
#pragma unroll
            for (int nt = 0; nt < 4; nt++) {
                const int c = n0 + wn + nt * 8 + (lane & 3) * 2;
                if (c >= nOut) continue;
                float b0 = bias[c], b1 = bias[c + 1];
                float v0 = acc[mt][nt][0] + b0, v1 = acc[mt][nt][1] + b1;
                float v2 = acc[mt][nt][2] + b0, v3 = acc[mt][nt][3] + b1;
                if (relu) {
                    v0 = fmaxf(v0, 0.f); v1 = fmaxf(v1, 0.f);
                    v2 = fmaxf(v2, 0.f); v3 = fmaxf(v3, 0.f);
                }
                *reinterpret_cast<float2*>(crow0 + c) = make_float2(v0, v1);
                *reinterpret_cast<float2*>(crow8 + c) = make_float2(v2, v3);
            }
        }
    } else {
#pragma unroll
        for (int mt = 0; mt < 4; mt++) {
            const int r0 = m0 + wm + mt * 16 + (lane >> 2);
#pragma unroll
            for (int nt = 0; nt < 4; nt++) {
                const int c = n0 + wn + nt * 8 + (lane & 3) * 2;
                float b0 = bias[c], b1 = bias[c + 1];
                float v0 = acc[mt][nt][0] + b0, v1 = acc[mt][nt][1] + b1;
                float v2 = acc[mt][nt][2] + b0, v3 = acc[mt][nt][3] + b1;
                if (relu) {
                    v0 = fmaxf(v0, 0.f); v1 = fmaxf(v1, 0.f);
                    v2 = fmaxf(v2, 0.f); v3 = fmaxf(v3, 0.f);
                }
                uint32_t H, L;
                split2(v0, v1, H, L);
                *reinterpret_cast<uint32_t*>(Ch + (size_t)r0 * ldc + c) = H;
                *reinterpret_cast<uint32_t*>(Cl + (size_t)r0 * ldc + c) = L;
                split2(v2, v3, H, L);
                *reinterpret_cast<uint32_t*>(Ch + (size_t)(r0 + 8) * ldc + c) = H;
                *reinterpret_cast<uint32_t*>(Cl + (size_t)(r0 + 8) * ldc + c) = L;
            }
        }
    }
}

// ---------------- int8 Ozaki GEMM (ml): C = sa*sb*(Q1P1 + (Q1P2+Q2P1)/254) + bias ----------------
// Same tile geometry; K chunk = 128 int8 (128B rows). S = K/128.
__device__ __forceinline__ void load_chunk_i8(uint32_t base, int tid, int m0, int n0, int k0,
    const int8_t* A1, const int8_t* A2, int lda,
    const int8_t* B1, const int8_t* B2, int ldb)
{
#pragma unroll
    for (int it = 0; it < 4; it++) {
        int idx = it * 256 + tid;
        int row = idx >> 3, u = idx & 7;
        uint32_t off = SWZ((uint32_t)(row * 128 + u * 16));
        size_t ao = (size_t)(m0 + row) * lda + k0 + u * 16;
        size_t bo = (size_t)(n0 + row) * ldb + k0 + u * 16;
        CP16(base + off,           A1 + ao);
        CP16(base + 16384u + off,  A2 + ao);
        CP16(base + 32768u + off,  B1 + bo);
        CP16(base + 49152u + off,  B2 + bo);
    }
}

__global__ __launch_bounds__(256, 1)
void gemm_i8(const int8_t* __restrict__ A1, const int8_t* __restrict__ A2, int lda,
             const int8_t* __restrict__ B1, const int8_t* __restrict__ B2, int ldb,
             const float* __restrict__ sa, const float* __restrict__ sb,
             const float* __restrict__ bias, float* __restrict__ Cf, int ldc, int K)
{
    extern __shared__ char smem[];
    const uint32_t tiles = (smem_to_u32(smem) + 1023) & ~1023u;
    const int tid = threadIdx.x, wid = tid >> 5, lane = tid & 31;
    const int m0 = blockIdx.y * 128, n0 = blockIdx.x * 128;
    const int wm = (wid >> 2) * 64, wn = (wid & 3) * 32;

    int p1[4][4][4], pc[4][4][4];
#pragma unroll
    for (int i = 0; i < 4; i++)
#pragma unroll
        for (int j = 0; j < 4; j++)
#pragma unroll
            for (int q = 0; q < 4; q++) { p1[i][j][q] = 0; pc[i][j][q] = 0; }

    const uint32_t aRowByte = (uint32_t)(wm + (lane & 15)) * 128u;
    const uint32_t aKoff    = (uint32_t)((lane >> 4) * 16);
    const uint32_t bRowByte = (uint32_t)(wn + (lane & 7) + ((lane >> 4) << 3)) * 128u;
    const uint32_t bKoff    = (uint32_t)(((lane >> 3) & 1) * 16);

    const int S = K / 128;
    load_chunk_i8(tiles, tid, m0, n0, 0, A1, A2, lda, B1, B2, ldb);
    CP_COMMIT();

    for (int s = 0; s < S; s++) {
        if (s + 1 < S) {
            load_chunk_i8(tiles + ((s + 1) & 1) * ST_BYTES, tid, m0, n0, (s + 1) * 128,
                          A1, A2, lda, B1, B2, ldb);
            CP_COMMIT();
            CP_WAIT1();
        } else {
            CP_WAIT0();
        }
        __syncthreads();

        const uint32_t pa1 = tiles + (s & 1) * ST_BYTES;
        const uint32_t pa2 = pa1 + 16384u, pb1 = pa1 + 32768u, pb2 = pa1 + 49152u;
#pragma unroll
        for (int kk = 0; kk < 4; kk++) {
            const uint32_t kb = (uint32_t)(kk * 32);
            uint32_t a1[4][4], a2[4][4], b1[2][4], b2[2][4];
#pragma unroll
            for (int mt = 0; mt < 4; mt++) {
                uint32_t ro = SWZ(aRowByte + (uint32_t)(mt * 2048) + kb + aKoff);
                ldsm_x4(a1[mt], pa1 + ro);
                ldsm_x4(a2[mt], pa2 + ro);
            }
#pragma unroll
            for (int nb = 0; nb < 2; nb++) {
                uint32_t ro = SWZ(bRowByte + (uint32_t)(nb * 2048) + kb + bKoff);
                ldsm_x4(b1[nb], pb1 + ro);
                ldsm_x4(b2[nb], pb2 + ro);
            }
#pragma unroll
            for (int mt = 0; mt < 4; mt++)
#pragma unroll
                for (int nt = 0; nt < 4; nt++) {
                    const uint32_t* b1p = &b1[nt >> 1][(nt & 1) * 2];
                    const uint32_t* b2p = &b2[nt >> 1][(nt & 1) * 2];
                    mma_s8(p1[mt][nt], a1[mt], b1p);
                    mma_s8(pc[mt][nt], a1[mt], b2p);
                    mma_s8(pc[mt][nt], a2[mt], b1p);
                }
        }
        __syncthreads();
    }

    const float inv254 = 1.0f / 254.0f;
#pragma unroll
    for (int mt = 0; mt < 4; mt++) {
        const int r0 = m0 + wm + mt * 16 + (lane >> 2);
        const float sa0 = sa[r0], sa8 = sa[r0 + 8];
        float* crow0 = Cf + (size_t)r0 * ldc;
        float* crow8 = Cf + (size_t)(r0 + 8) * ldc;
#pragma unroll
        for (int nt = 0; nt < 4; nt++) {
            const int c = n0 + wn + nt * 8 + (lane & 3) * 2;
            const float sb0 = sb[c], sb1 = sb[c + 1];
            const float b0 = bias[c], b1v = bias[c + 1];
            float v0 = sa0 * sb0 * ((float)p1[mt][nt][0] + (float)pc[mt][nt][0] * inv254) + b0;
            float v1 = sa0 * sb1 * ((float)p1[mt][nt][1] + (float)pc[mt][nt][1] * inv254) + b1v;
            float v2 = sa8 * sb0 * ((float)p1[mt][nt][2] + (float)pc[mt][nt][2] * inv254) + b0;
            float v3 = sa8 * sb1 * ((float)p1[mt][nt][3] + (float)pc[mt][nt][3] * inv254) + b1v;
            *reinterpret_cast<float2*>(crow0 + c) = make_float2(v0, v1);
            *reinterpret_cast<float2*>(crow8 + c) = make_float2(v2, v3);
        }
    }
}

// ---------------- row quantization: fp32 row -> 2x int8 slices + scale ----------------
__global__ void quant_rows(const float* __restrict__ src, int Kd,
                           int8_t* __restrict__ q1, int8_t* __restrict__ q2,
                           float* __restrict__ sig)
{
    const int r = blockIdx.x, t = threadIdx.x;
    const float* row = src + (size_t)r * Kd;
    float mx = 0.f;
    for (int i = t; i < Kd; i += 256) mx = fmaxf(mx, fabsf(row[i]));
    __shared__ float sm[256];
    sm[t] = mx;
    __syncthreads();
    for (int st = 128; st > 0; st >>= 1) { if (t < st) sm[t] = fmaxf(sm[t], sm[t + st]); __syncthreads(); }
    float s = fmaxf(sm[0], 1e-30f) / 127.0f;
    float inv = 1.0f / s;
    int8_t* q1r = q1 + (size_t)r * Kd;
    int8_t* q2r = q2 + (size_t)r * Kd;
    for (int i = t; i < Kd; i += 256) {
        float a = row[i];
        float f1 = rintf(a * inv);
        float f2 = rintf((a - s * f1) * inv * 254.0f);
        q1r[i] = (int8_t)(int)f1;
        q2r[i] = (int8_t)(int)f2;
    }
    if (t == 0) sig[r] = s;
}

// ---------------- logits SGEMM: 64x64 tile, exact fp32 ----------------
__global__ __launch_bounds__(128)
void sgemm64(const float* __restrict__ A, const float* __restrict__ G,
             const float* __restrict__ lb, float* __restrict__ C)
{
    __shared__ float As[16][64];
    __shared__ float Bs[16][64];
    const int tid = threadIdx.x;
    const int m0 = blockIdx.x * 64;
    const int tx = tid & 15, ty = tid >> 4;
    const int lrow = tid >> 1, lhalf = tid & 1;
    float acc[8][4];
#pragma unroll
    for (int i = 0; i < 8; i++)
#pragma unroll
        for (int j = 0; j < 4; j++) acc[i][j] = 0.f;

    for (int k0 = 0; k0 < IN_DIM; k0 += 16) {
#pragma unroll
        for (int h = 0; h < 2; h++) {
            int kk = lhalf * 8 + h * 4;
            float4 va = *reinterpret_cast<const float4*>(A + (size_t)(m0 + lrow) * IN_DIM + k0 + kk);
            As[kk + 0][lrow] = va.x; As[kk + 1][lrow] = va.y;
            As[kk + 2][lrow] = va.z; As[kk + 3][lrow] = va.w;
            float4 vb = make_float4(0.f, 0.f, 0.f, 0.f);
            if (lrow < KCLS)
                vb = *reinterpret_cast<const float4*>(G + (size_t)lrow * IN_DIM + k0 + kk);
            Bs[kk + 0][lrow] = vb.x; Bs[kk + 1][lrow] = vb.y;
            Bs[kk + 2][lrow] = vb.z; Bs[kk + 3][lrow] = vb.w;
        }
        __syncthreads();
#pragma unroll
        for (int k = 0; k < 16; k++) {
            float4 a0 = *reinterpret_cast<const float4*>(&As[k][ty * 4]);
            float4 a1 = *reinterpret_cast<const float4*>(&As[k][32 + ty * 4]);
            float4 b  = *reinterpret_cast<const float4*>(&Bs[k][tx * 4]);
            float a[8] = {a0.x, a0.y, a0.z, a0.w, a1.x, a1.y, a1.z, a1.w};
            float bb[4] = {b.x, b.y, b.z, b.w};
#pragma unroll
            for (int i = 0; i < 8; i++)
#pragma unroll
                for (int j = 0; j < 4; j++)
                    acc[i][j] = fmaf(a[i], bb[j], acc[i][j]);
        }
        __syncthreads();
    }
#pragma unroll
    for (int i = 0; i < 8; i++) {
        int row = m0 + ((i < 4) ? (ty * 4 + i) : (32 + ty * 4 + i - 4));
#pragma unroll
        for (int j = 0; j < 4; j++) {
            int col = tx * 4 + j;
            if (col < KCLS) C[(size_t)row * KCLS + col] = acc[i][j] + lb[col];
        }
    }
}

// ---------------- prep kernels ----------------
__global__ void split_mat(const float* __restrict__ src, uint32_t* __restrict__ dh,
                          uint32_t* __restrict__ dl, long nPairs, long srcPairs)
{
    long i = (long)blockIdx.x * blockDim.x + threadIdx.x;
    if (i >= nPairs) return;
    float v0 = 0.f, v1 = 0.f;
    if (i < srcPairs) {
        float2 v = reinterpret_cast<const float2*>(src)[i];
        v0 = v.x; v1 = v.y;
    }
    uint32_t H, L;
    split2(v0, v1, H, L);
    dh[i] = H; dl[i] = L;
}

__global__ void split_wd(const float* __restrict__ Wd)
{
    int i = blockIdx.x * blockDim.x + threadIdx.x;
    const int ppr = CAT_LD / 2;
    if (i >= IN_DIM * ppr) return;
    int r = i / ppr, p = i - r * ppr;
    int c0 = 2 * p;
    float v0 = (c0 < CAT_RAW) ? Wd[(size_t)r * CAT_RAW + c0] : 0.f;
    float v1 = (c0 + 1 < CAT_RAW) ? Wd[(size_t)r * CAT_RAW + c0 + 1] : 0.f;
    uint32_t H, L;
    split2(v0, v1, H, L);
    g_wdh[i] = H; g_wdl[i] = L;
}

__global__ void build_G(const float* __restrict__ W_enc, const float* __restrict__ cb)
{
    int c = blockIdx.x;
    int i = blockIdx.y * 128 + threadIdx.x;
    float s = 0.f;
#pragma unroll 4
    for (int d = 0; d < ENC_DIM; d++)
        s = fmaf(cb[c * ENC_DIM + d], W_enc[(size_t)d * IN_DIM + i], s);
    g_G[(size_t)c * IN_DIM + i] = s;
}
__global__ void build_lb(const float* __restrict__ b_enc, const float* __restrict__ cb)
{
    int c = blockIdx.x;
    int t = threadIdx.x;
    float s = 0.f;
    for (int d = t; d < ENC_DIM; d += 128) s = fmaf(b_enc[d], cb[c * ENC_DIM + d], s);
    __shared__ float sm[128];
    sm[t] = s;
    __syncthreads();
    for (int st = 64; st > 0; st >>= 1) { if (t < st) sm[t] += sm[t + st]; __syncthreads(); }
    if (t == 0) g_lb[c] = sm[0];
}

__global__ void detect_mask_kernel(const unsigned int* __restrict__ w)
{
    __shared__ int s_int, s_flt;
    if (threadIdx.x == 0) { s_int = 1; s_flt = 1; }
    __syncthreads();
    int li = 1, lf = 1;
    for (int i = threadIdx.x; i < 4096; i += blockDim.x) {
        unsigned v = w[i];
        if (v > 1u) li = 0;
        if (v != 0u && v != 0x3F800000u) lf = 0;
    }
    if (!li) atomicAnd(&s_int, 0);
    if (!lf) atomicAnd(&s_flt, 0);
    __syncthreads();
    if (threadIdx.x == 0) g_mask_mode = s_int ? 1 : (s_flt ? 2 : 0);
}

__global__ void argmax_y_kernel(const float* __restrict__ logits,
                                const void* __restrict__ mask,
                                const int* __restrict__ labels,
                                const float* __restrict__ codebook,
                                float* __restrict__ zq)
{
    const int b = blockIdx.x;
    const int lane = threadIdx.x;
    const float NEG = __int_as_float(0xff800000u);
    const float* lr = logits + (size_t)b * KCLS;
    const int k0 = 2 * lane, k1 = 2 * lane + 1;
    float va = (k0 < KCLS) ? lr[k0] : NEG;
    float vb = (k1 < KCLS) ? lr[k1] : NEG;
    float m; int mi;
    if (va >= vb) { m = va; mi = k0; } else { m = vb; mi = k1; }
#pragma unroll
    for (int off = 16; off > 0; off >>= 1) {
        float om = __shfl_xor_sync(0xffffffffu, m, off);
        int oi = __shfl_xor_sync(0xffffffffu, mi, off);
        if (om > m || (om == m && oi < mi)) { m = om; mi = oi; }
    }
    float ea = (k0 < KCLS) ? expf(va - m) : 0.f;
    float eb = (k1 < KCLS) ? expf(vb - m) : 0.f;
    float s = ea + eb;
#pragma unroll
    for (int off = 16; off > 0; off >>= 1) s += __shfl_xor_sync(0xffffffffu, s, off);
    float inv = 1.0f / s;

    int mode = g_mask_mode;
    bool known;
    if (mode == 1)      known = ((const int*)mask)[b] != 0;
    else if (mode == 2) known = ((const float*)mask)[b] != 0.f;
    else                known = ((const unsigned char*)mask)[b] != 0;
    int lab = labels[b];

    float y0 = (k0 < KCLS) ? (known ? (k0 == lab ? 1.f : 0.f) : ea * inv) : 0.f;
    float y1 = (k1 < KCLS) ? (known ? (k1 == lab ? 1.f : 0.f) : eb * inv) : 0.f;
    uint32_t H, L;
    split2(y0, y1, H, L);
    const size_t pi = (size_t)b * (CAT_LD / 2) + (VDIM / 2) + lane;
    g_cath[pi] = H; g_catl[pi] = L;

    const float* cr = codebook + (size_t)mi * ENC_DIM;
    float* zr = zq + (size_t)b * ENC_DIM;
    for (int i = lane; i < ENC_DIM; i += 32) zr[i] = cr[i];
}

__global__ void vae_post_kernel(const float* __restrict__ eps)
{
    const int b = blockIdx.x;
    const int t = threadIdx.x;
    const float* mlr = g_ml + (size_t)b * (2 * VDIM);
    const float* er = eps + (size_t)b * VDIM;
    float kl = 0.f;
#pragma unroll
    for (int p = t; p < VDIM / 2; p += 256) {
        int i0 = 2 * p;
        float2 mu = *reinterpret_cast<const float2*>(mlr + i0);
        float2 lv = *reinterpret_cast<const float2*>(mlr + VDIM + i0);
        float2 ep = *reinterpret_cast<const float2*>(er + i0);
        kl += 0.5f * (fast_exp(lv.x) + mu.x * mu.x - 1.0f - lv.x);
        kl += 0.5f * (fast_exp(lv.y) + mu.y * mu.y - 1.0f - lv.y);
        float v0 = fmaf(fast_exp(0.5f * lv.x), ep.x, mu.x);
        float v1 = fmaf(fast_exp(0.5f * lv.y), ep.y, mu.y);
        uint32_t H, L;
        split2(v0, v1, H, L);
        const size_t pi = (size_t)b * (CAT_LD / 2) + p;
        g_cath[pi] = H; g_catl[pi] = L;
    }
    __shared__ float sm[256];
    sm[t] = kl;
    __syncthreads();
    for (int st = 128; st > 0; st >>= 1) { if (t < st) sm[t] += sm[t + st]; __syncthreads(); }
    if (t == 0) g_klp[b] = sm[0];
}

__global__ void kl_reduce_kernel(float* __restrict__ out)
{
    const int t = threadIdx.x;
    float s = 0.f;
    for (int i = t; i < B_ROWS; i += 256) s += g_klp[i];
    __shared__ float sm[256];
    sm[t] = s;
    __syncthreads();
    for (int st = 128; st > 0; st >>= 1) { if (t < st) sm[t] += sm[t + st]; __syncthreads(); }
    if (t == 0) *out = sm[0] / (float)B_ROWS;
}

// ---------------- host ----------------
static void launch_gemm(const void* Ah, const void* Al, int lda,
                        const void* Bh, const void* Bl, int ldb,
                        const float* bias, float* Cf, void* Ch, void* Cl,
                        int ldc, int nPad, int nOut, int K, int relu, int mode)
{
    cudaFuncSetAttribute(gemm_bf3, cudaFuncAttributeMaxDynamicSharedMemorySize, GEMM_DYN);
    dim3 grid(nPad / 128, B_ROWS / 128);
    gemm_bf3<<<grid, 256, GEMM_DYN>>>(
        (const uint16_t*)Ah, (const uint16_t*)Al, lda,
        (const uint16_t*)Bh, (const uint16_t*)Bl, ldb,
        bias, Cf, (uint16_t*)Ch, (uint16_t*)Cl, ldc, nOut, K, relu, mode);
}

extern "C" void kernel_launch(void* const* d_in, const int* in_sizes, int n_in,
                              void* d_out, int out_size)
{
    const float* x        = (const float*)d_in[0];
    const void*  mask     = d_in[1];
    const int*   labels   = (const int*)d_in[2];
    const float* eps      = (const float*)d_in[3];
    const float* W_enc    = (const float*)d_in[4];
    const float* b_enc    = (const float*)d_in[5];
    const float* codebook = (const float*)d_in[6];
    const float* W1       = (const float*)d_in[7];
    const float* b1       = (const float*)d_in[8];
    const float* W2       = (const float*)d_in[9];
    const float* b2       = (const float*)d_in[10];
    const float* Wd       = (const float*)d_in[11];
    const float* bd       = (const float*)d_in[12];
    float* out = (float*)d_out;

    void *p_xh, *p_xl, *p_weh, *p_wel, *p_w1h, *p_w1l, *p_wdh, *p_wdl;
    void *p_hf, *p_q1a, *p_q2a, *p_q1b, *p_q2b, *p_sa, *p_sb, *p_cath, *p_catl;
    float *p_ml, *p_G, *p_lb, *p_ze, *p_zq, *p_lg, *p_kl;
    cudaGetSymbolAddress(&p_xh, g_xh);   cudaGetSymbolAddress(&p_xl, g_xl);
    cudaGetSymbolAddress(&p_weh, g_weh); cudaGetSymbolAddress(&p_wel, g_wel);
    cudaGetSymbolAddress(&p_w1h, g_w1h); cudaGetSymbolAddress(&p_w1l, g_w1l);
    cudaGetSymbolAddress(&p_wdh, g_wdh); cudaGetSymbolAddress(&p_wdl, g_wdl);
    cudaGetSymbolAddress(&p_hf, g_hf);
    cudaGetSymbolAddress(&p_q1a, g_q1a); cudaGetSymbolAddress(&p_q2a, g_q2a);
    cudaGetSymbolAddress(&p_q1b, g_q1b); cudaGetSymbolAddress(&p_q2b, g_q2b);
    cudaGetSymbolAddress(&p_sa, g_sa);   cudaGetSymbolAddress(&p_sb, g_sb);
    cudaGetSymbolAddress(&p_cath, g_cath); cudaGetSymbolAddress(&p_catl, g_catl);
    cudaGetSymbolAddress((void**)&p_ml, g_ml);
    cudaGetSymbolAddress((void**)&p_G,  g_G);
    cudaGetSymbolAddress((void**)&p_lb, g_lb);
    cudaGetSymbolAddress((void**)&p_ze, g_ze_s);
    cudaGetSymbolAddress((void**)&p_zq, g_zq_s);
    cudaGetSymbolAddress((void**)&p_lg, g_lg_s);
    cudaGetSymbolAddress((void**)&p_kl, g_kl_s);

    const size_t full_elems = (size_t)B_ROWS * (IN_DIM + ENC_DIM + ENC_DIM + KCLS) + 1;
    const bool full = ((size_t)out_size >= full_elems);
    float* xt = out;
    float* ze = full ? out + (size_t)B_ROWS * IN_DIM : p_ze;
    float* zq = full ? ze + (size_t)B_ROWS * ENC_DIM : p_zq;
    float* lg = full ? zq + (size_t)B_ROWS * ENC_DIM : p_lg;
    float* kl = full ? lg + (size_t)B_ROWS * KCLS    : p_kl;

    // ---- prep ----
    {
        long np = (long)B_ROWS * IN_DIM / 2;
        split_mat<<<(unsigned)((np + 255) / 256), 256>>>(x, (uint32_t*)p_xh, (uint32_t*)p_xl, np, np);
        long sp = (long)ENC_DIM * IN_DIM / 2, tp = (long)ZE_NPAD * IN_DIM / 2;
        split_mat<<<(unsigned)((tp + 255) / 256), 256>>>(W_enc, (uint32_t*)p_weh, (uint32_t*)p_wel, tp, sp);
        long w1p = (long)VDIM * IN_DIM / 2;
        split_mat<<<(unsigned)((w1p + 255) / 256), 256>>>(W1, (uint32_t*)p_w1h, (uint32_t*)p_w1l, w1p, w1p);
        split_wd<<<(IN_DIM * (CAT_LD / 2) + 255) / 256, 256>>>(Wd);
        // W2 -> int8 2-slice (per row)
        quant_rows<<<2 * VDIM, 256>>>(W2, VDIM, (int8_t*)p_q1b, (int8_t*)p_q2b, (float*)p_sb);
    }
    detect_mask_kernel<<<1, 256>>>((const unsigned int*)mask);
    build_G<<<dim3(KCLS, IN_DIM / 128), 128>>>(W_enc, codebook);
    build_lb<<<KCLS, 128>>>(b_enc, codebook);

    // logits (exact fp32)
    sgemm64<<<B_ROWS / 64, 128>>>(x, p_G, p_lb, lg);

    // z_e_x (bf16x3)
    launch_gemm(p_xh, p_xl, IN_DIM, p_weh, p_wel, IN_DIM, b_enc,
                ze, nullptr, nullptr, ENC_DIM, ZE_NPAD, ENC_DIM, IN_DIM, 0, 0);
    // h = relu(x@W1^T + b1) -> fp32 (for int8 quant)
    launch_gemm(p_xh, p_xl, IN_DIM, p_w1h, p_w1l, IN_DIM, b1,
                (float*)p_hf, nullptr, nullptr, VDIM, VDIM, VDIM, IN_DIM, 1, 0);
    // quantize h rows
    quant_rows<<<B_ROWS, 256>>>((const float*)p_hf, VDIM,
                                (int8_t*)p_q1a, (int8_t*)p_q2a, (float*)p_sa);
    // mu||logvar via int8 Ozaki GEMM
    {
        cudaFuncSetAttribute(gemm_i8, cudaFuncAttributeMaxDynamicSharedMemorySize, GEMM_DYN);
        dim3 grid(2 * VDIM / 128, B_ROWS / 128);
        gemm_i8<<<grid, 256, GEMM_DYN>>>(
            (const int8_t*)p_q1a, (const int8_t*)p_q2a, VDIM,
            (const int8_t*)p_q1b, (const int8_t*)p_q2b, VDIM,
            (const float*)p_sa, (const float*)p_sb, b2, p_ml, 2 * VDIM, VDIM);
    }

    // argmax / y / z_q (fills cat y region)
    argmax_y_kernel<<<B_ROWS, 32>>>(lg, mask, labels, codebook, zq);
    // sampled_z (fills cat z region) + KL
    vae_post_kernel<<<B_ROWS, 256>>>(eps);
    kl_reduce_kernel<<<1, 256>>>(kl);

    // decoder (bf16x3)
    launch_gemm(p_cath, p_catl, CAT_LD, p_wdh, p_wdl, CAT_LD, bd,
                xt, nullptr, nullptr, IN_DIM, IN_DIM, IN_DIM, CAT_LD, 0, 0);
}

// round 10
// speedup vs baseline: 1.8339x; 1.8339x over previous
#include <cuda_runtime.h>
#include <cuda_bf16.h>
#include <math.h>
#include <stdint.h>

#define B_ROWS 16384
#define IN_DIM 768
#define ENC_DIM 500
#define ZE_NPAD 512
#define KCLS 43
#define VDIM 1024
#define CAT_RAW 1067
#define CAT_LD  1088   // multiple of 64

// ---------------- scratch (bf16 pairs stored as uint32) ----------------
__device__ uint32_t g_xh [(size_t)B_ROWS * IN_DIM / 2];
__device__ uint32_t g_xl [(size_t)B_ROWS * IN_DIM / 2];
__device__ uint32_t g_weh[(size_t)ZE_NPAD * IN_DIM / 2];
__device__ uint32_t g_wel[(size_t)ZE_NPAD * IN_DIM / 2];
__device__ uint32_t g_w1h[(size_t)VDIM * IN_DIM / 2];
__device__ uint32_t g_w1l[(size_t)VDIM * IN_DIM / 2];
__device__ uint32_t g_w2h[(size_t)2 * VDIM * VDIM / 2];
__device__ uint32_t g_w2l[(size_t)2 * VDIM * VDIM / 2];
__device__ uint32_t g_wdh[(size_t)IN_DIM * CAT_LD / 2];
__device__ uint32_t g_wdl[(size_t)IN_DIM * CAT_LD / 2];
__device__ uint32_t g_hh [(size_t)B_ROWS * VDIM / 2];
__device__ uint32_t g_hl [(size_t)B_ROWS * VDIM / 2];
__device__ uint32_t g_cath[(size_t)B_ROWS * CAT_LD / 2];
__device__ uint32_t g_catl[(size_t)B_ROWS * CAT_LD / 2];
__device__ float g_ml [(size_t)B_ROWS * 2 * VDIM];
__device__ float g_G  [(size_t)KCLS * IN_DIM];
__device__ float g_lb [KCLS];
__device__ float g_klp[B_ROWS];
__device__ float g_ze_s[(size_t)B_ROWS * ENC_DIM];
__device__ float g_zq_s[(size_t)B_ROWS * ENC_DIM];
__device__ float g_lg_s[(size_t)B_ROWS * KCLS];
__device__ float g_kl_s[1];
__device__ int   g_mask_mode;

// ---------------- helpers ----------------
__device__ __forceinline__ uint32_t smem_to_u32(const void* p) {
    uint32_t a;
    asm("{ .reg .u64 t; cvta.to.shared.u64 t, %1; cvt.u32.u64 %0, t; }" : "=r"(a) : "l"(p));
    return a;
}
#define SWZ(b) ((b) ^ (((b) >> 3) & 0x70))
#define CP16(d, s)  asm volatile("cp.async.cg.shared.global [%0], [%1], 16;" :: "r"(d), "l"(s) : "memory")
#define CP_COMMIT() asm volatile("cp.async.commit_group;" ::: "memory")
#define CP_WAIT0()  asm volatile("cp.async.wait_group 0;" ::: "memory")
#define CP_WAIT1()  asm volatile("cp.async.wait_group 1;" ::: "memory")

__device__ __forceinline__ void ldsm_x4(uint32_t* r, uint32_t addr) {
    asm volatile("ldmatrix.sync.aligned.m8n8.x4.shared.b16 {%0,%1,%2,%3}, [%4];"
        : "=r"(r[0]), "=r"(r[1]), "=r"(r[2]), "=r"(r[3]) : "r"(addr));
}
__device__ __forceinline__ void mma16816(float* c, const uint32_t* a, const uint32_t* b) {
    asm volatile("mma.sync.aligned.m16n8k16.row.col.f32.bf16.bf16.f32 "
        "{%0,%1,%2,%3}, {%4,%5,%6,%7}, {%8,%9}, {%0,%1,%2,%3};"
        : "+f"(c[0]), "+f"(c[1]), "+f"(c[2]), "+f"(c[3])
        : "r"(a[0]), "r"(a[1]), "r"(a[2]), "r"(a[3]), "r"(b[0]), "r"(b[1]));
}
__device__ __forceinline__ void split2(float v0, float v1, uint32_t& H, uint32_t& L) {
    uint32_t u0 = __float_as_uint(v0), u1 = __float_as_uint(v1);
    H = __byte_perm(u0, u1, 0x7632);
    float l0 = v0 - __uint_as_float(u0 & 0xFFFF0000u);
    float l1 = v1 - __uint_as_float(u1 & 0xFFFF0000u);
    asm("cvt.rn.bf16x2.f32 %0, %1, %2;" : "=r"(L) : "f"(l1), "f"(l0));
}
__device__ __forceinline__ float fast_exp(float x) {
    float r;
    asm("ex2.approx.ftz.f32 %0, %1;" : "=f"(r) : "f"(x * 1.4426950408889634f));
    return r;
}

// ---------------- 2-stage pipelined mma.sync bf16x3 GEMM ----------------
#define ST_BYTES 65536u
#define GEMM_DYN (2 * 65536 + 1024)

__device__ __forceinline__ void load_chunk(uint32_t base, int tid, int m0, int n0, int k0,
    const uint16_t* Ah, const uint16_t* Al, int lda,
    const uint16_t* Bh, const uint16_t* Bl, int ldb)
{
#pragma unroll
    for (int it = 0; it < 4; it++) {
        int idx = it * 256 + tid;
        int row = idx >> 3, u = idx & 7;
        uint32_t off = SWZ((uint32_t)(row * 128 + u * 16));
        size_t ao = (size_t)(m0 + row) * lda + k0 + u * 8;
        size_t bo = (size_t)(n0 + row) * ldb + k0 + u * 8;
        CP16(base + off,           Ah + ao);
        CP16(base + 16384u + off,  Al + ao);
        CP16(base + 32768u + off,  Bh + bo);
        CP16(base + 49152u + off,  Bl + bo);
    }
}

// mode: 0 = fp32 C (+bias,+relu,col-guard), 1 = split bf16 hi/lo C
__global__ __launch_bounds__(256, 1)
void gemm_bf3(const uint16_t* __restrict__ Ah, const uint16_t* __restrict__ Al, int lda,
              const uint16_t* __restrict__ Bh, const uint16_t* __restrict__ Bl, int ldb,
              const float* __restrict__ bias,
              float* __restrict__ Cf, uint16_t* __restrict__ Ch, uint16_t* __restrict__ Cl,
              int ldc, int nOut, int K, int relu, int mode)
{
    extern __shared__ char smem[];
    const uint32_t tiles = (smem_to_u32(smem) + 1023) & ~1023u;
    const int tid = threadIdx.x, wid = tid >> 5, lane = tid & 31;
    const int m0 = blockIdx.y * 128, n0 = blockIdx.x * 128;
    const int wm = (wid >> 2) * 64, wn = (wid & 3) * 32;

    float acc[4][4][4];
#pragma unroll
    for (int i = 0; i < 4; i++)
#pragma unroll
        for (int j = 0; j < 4; j++)
#pragma unroll
            for (int q = 0; q < 4; q++) acc[i][j][q] = 0.f;

    const uint32_t aRowByte = (uint32_t)(wm + (lane & 15)) * 128u;
    const uint32_t aKoff    = (uint32_t)((lane >> 4) * 16);
    const uint32_t bRowByte = (uint32_t)(wn + (lane & 7) + ((lane >> 4) << 3)) * 128u;
    const uint32_t bKoff    = (uint32_t)(((lane >> 3) & 1) * 16);

    const int S = K / 64;
    load_chunk(tiles, tid, m0, n0, 0, Ah, Al, lda, Bh, Bl, ldb);
    CP_COMMIT();

    for (int s = 0; s < S; s++) {
        if (s + 1 < S) {
            load_chunk(tiles + ((s + 1) & 1) * ST_BYTES, tid, m0, n0, (s + 1) * 64,
                       Ah, Al, lda, Bh, Bl, ldb);
            CP_COMMIT();
            CP_WAIT1();
        } else {
            CP_WAIT0();
        }
        __syncthreads();

        const uint32_t pah = tiles + (s & 1) * ST_BYTES;
        const uint32_t pal = pah + 16384u, pbh = pah + 32768u, pbl = pah + 49152u;
#pragma unroll
        for (int kk = 0; kk < 4; kk++) {
            const uint32_t kb = (uint32_t)(kk * 32);
            uint32_t ah[4][4], al[4][4], bh[2][4], bl[2][4];
#pragma unroll
            for (int mt = 0; mt < 4; mt++) {
                uint32_t ro = SWZ(aRowByte + (uint32_t)(mt * 2048) + kb + aKoff);
                ldsm_x4(ah[mt], pah + ro);
                ldsm_x4(al[mt], pal + ro);
            }
#pragma unroll
            for (int nb = 0; nb < 2; nb++) {
                uint32_t ro = SWZ(bRowByte + (uint32_t)(nb * 2048) + kb + bKoff);
                ldsm_x4(bh[nb], pbh + ro);
                ldsm_x4(bl[nb], pbl + ro);
            }
            // pass-outer ordering: 16 independent accumulators between
            // successive writes to the same acc -> no RAW stall on HMMA pipe
#pragma unroll
            for (int t3 = 0; t3 < 3; t3++)
#pragma unroll
                for (int mt = 0; mt < 4; mt++)
#pragma unroll
                    for (int nt = 0; nt < 4; nt++) {
                        const uint32_t* ap = (t3 == 1) ? al[mt] : ah[mt];
                        const uint32_t* bp = (t3 == 2) ? &bl[nt >> 1][(nt & 1) * 2]
                                                       : &bh[nt >> 1][(nt & 1) * 2];
                        mma16816(acc[mt][nt], ap, bp);
                    }
        }
        __syncthreads();
    }

    // ---- epilogue ----
    if (mode == 0) {
#pragma unroll
        for (int mt = 0; mt < 4; mt++) {
            const int r0 = m0 + wm + mt * 16 + (lane >> 2);
            float* crow0 = Cf + (size_t)r0 * ldc;
            float* crow8 = Cf + (size_t)(r0 + 8) * ldc;
#pragma unroll
            for (int nt = 0; nt < 4; nt++) {
                const int c = n0 + wn + nt * 8 + (lane & 3) * 2;
                if (c >= nOut) continue;
                float b0 = bias[c], b1 = bias[c + 1];
                float v0 = acc[mt][nt][0] + b0, v1 = acc[mt][nt][1] + b1;
                float v2 = acc[mt][nt][2] + b0, v3 = acc[mt][nt][3] + b1;
                if (relu) {
                    v0 = fmaxf(v0, 0.f); v1 = fmaxf(v1, 0.f);
                    v2 = fmaxf(v2, 0.f); v3 = fmaxf(v3, 0.f);
                }
                *reinterpret_cast<float2*>(crow0 + c) = make_float2(v0, v1);
                *reinterpret_cast<float2*>(crow8 + c) = make_float2(v2, v3);
            }
        }
    } else {
#pragma unroll
        for (int mt = 0; mt < 4; mt++) {
            const int r0 = m0 + wm + mt * 16 + (lane >> 2);
#pragma unroll
            for (int nt = 0; nt < 4; nt++) {
                const int c = n0 + wn + nt * 8 + (lane & 3) * 2;
                float b0 = bias[c], b1 = bias[c + 1];
                float v0 = acc[mt][nt][0] + b0, v1 = acc[mt][nt][1] + b1;
                float v2 = acc[mt][nt][2] + b0, v3 = acc[mt][nt][3] + b1;
                if (relu) {
                    v0 = fmaxf(v0, 0.f); v1 = fmaxf(v1, 0.f);
                    v2 = fmaxf(v2, 0.f); v3 = fmaxf(v3, 0.f);
                }
                uint32_t H, L;
                split2(v0, v1, H, L);
                *reinterpret_cast<uint32_t*>(Ch + (size_t)r0 * ldc + c) = H;
                *reinterpret_cast<uint32_t*>(Cl + (size_t)r0 * ldc + c) = L;
                split2(v2, v3, H, L);
                *reinterpret_cast<uint32_t*>(Ch + (size_t)(r0 + 8) * ldc + c) = H;
                *reinterpret_cast<uint32_t*>(Cl + (size_t)(r0 + 8) * ldc + c) = L;
            }
        }
    }
}

// ---------------- logits SGEMM: 64x64 tile, exact fp32 ----------------
__global__ __launch_bounds__(128)
void sgemm64(const float* __restrict__ A, const float* __restrict__ G,
             const float* __restrict__ lb, float* __restrict__ C)
{
    __shared__ float As[16][64];
    __shared__ float Bs[16][64];
    const int tid = threadIdx.x;
    const int m0 = blockIdx.x * 64;
    const int tx = tid & 15, ty = tid >> 4;
    const int lrow = tid >> 1, lhalf = tid & 1;
    float acc[8][4];
#pragma unroll
    for (int i = 0; i < 8; i++)
#pragma unroll
        for (int j = 0; j < 4; j++) acc[i][j] = 0.f;

    for (int k0 = 0; k0 < IN_DIM; k0 += 16) {
#pragma unroll
        for (int h = 0; h < 2; h++) {
            int kk = lhalf * 8 + h * 4;
            float4 va = *reinterpret_cast<const float4*>(A + (size_t)(m0 + lrow) * IN_DIM + k0 + kk);
            As[kk + 0][lrow] = va.x; As[kk + 1][lrow] = va.y;
            As[kk + 2][lrow] = va.z; As[kk + 3][lrow] = va.w;
            float4 vb = make_float4(0.f, 0.f, 0.f, 0.f);
            if (lrow < KCLS)
                vb = *reinterpret_cast<const float4*>(G + (size_t)lrow * IN_DIM + k0 + kk);
            Bs[kk + 0][lrow] = vb.x; Bs[kk + 1][lrow] = vb.y;
            Bs[kk + 2][lrow] = vb.z; Bs[kk + 3][lrow] = vb.w;
        }
        __syncthreads();
#pragma unroll
        for (int k = 0; k < 16; k++) {
            float4 a0 = *reinterpret_cast<const float4*>(&As[k][ty * 4]);
            float4 a1 = *reinterpret_cast<const float4*>(&As[k][32 + ty * 4]);
            float4 b  = *reinterpret_cast<const float4*>(&Bs[k][tx * 4]);
            float a[8] = {a0.x, a0.y, a0.z, a0.w, a1.x, a1.y, a1.z, a1.w};
            float bb[4] = {b.x, b.y, b.z, b.w};
#pragma unroll
            for (int i = 0; i < 8; i++)
#pragma unroll
                for (int j = 0; j < 4; j++)
                    acc[i][j] = fmaf(a[i], bb[j], acc[i][j]);
        }
        __syncthreads();
    }
#pragma unroll
    for (int i = 0; i < 8; i++) {
        int row = m0 + ((i < 4) ? (ty * 4 + i) : (32 + ty * 4 + i - 4));
#pragma unroll
        for (int j = 0; j < 4; j++) {
            int col = tx * 4 + j;
            if (col < KCLS) C[(size_t)row * KCLS + col] = acc[i][j] + lb[col];
        }
    }
}

// ---------------- prep kernels ----------------
__global__ void split_mat(const float* __restrict__ src, uint32_t* __restrict__ dh,
                          uint32_t* __restrict__ dl, long nPairs, long srcPairs)
{
    long i = (long)blockIdx.x * blockDim.x + threadIdx.x;
    if (i >= nPairs) return;
    float v0 = 0.f, v1 = 0.f;
    if (i < srcPairs) {
        float2 v = reinterpret_cast<const float2*>(src)[i];
        v0 = v.x; v1 = v.y;
    }
    uint32_t H, L;
    split2(v0, v1, H, L);
    dh[i] = H; dl[i] = L;
}

__global__ void split_wd(const float* __restrict__ Wd)
{
    int i = blockIdx.x * blockDim.x + threadIdx.x;
    const int ppr = CAT_LD / 2;
    if (i >= IN_DIM * ppr) return;
    int r = i / ppr, p = i - r * ppr;
    int c0 = 2 * p;
    float v0 = (c0 < CAT_RAW) ? Wd[(size_t)r * CAT_RAW + c0] : 0.f;
    float v1 = (c0 + 1 < CAT_RAW) ? Wd[(size_t)r * CAT_RAW + c0 + 1] : 0.f;
    uint32_t H, L;
    split2(v0, v1, H, L);
    g_wdh[i] = H; g_wdl[i] = L;
}

__global__ void build_G(const float* __restrict__ W_enc, const float* __restrict__ cb)
{
    int c = blockIdx.x;
    int i = blockIdx.y * 128 + threadIdx.x;
    float s = 0.f;
#pragma unroll 4
    for (int d = 0; d < ENC_DIM; d++)
        s = fmaf(cb[c * ENC_DIM + d], W_enc[(size_t)d * IN_DIM + i], s);
    g_G[(size_t)c * IN_DIM + i] = s;
}
__global__ void build_lb(const float* __restrict__ b_enc, const float* __restrict__ cb)
{
    int c = blockIdx.x;
    int t = threadIdx.x;
    float s = 0.f;
    for (int d = t; d < ENC_DIM; d += 128) s = fmaf(b_enc[d], cb[c * ENC_DIM + d], s);
    __shared__ float sm[128];
    sm[t] = s;
    __syncthreads();
    for (int st = 64; st > 0; st >>= 1) { if (t < st) sm[t] += sm[t + st]; __syncthreads(); }
    if (t == 0) g_lb[c] = sm[0];
}

__global__ void detect_mask_kernel(const unsigned int* __restrict__ w)
{
    __shared__ int s_int, s_flt;
    if (threadIdx.x == 0) { s_int = 1; s_flt = 1; }
    __syncthreads();
    int li = 1, lf = 1;
    for (int i = threadIdx.x; i < 4096; i += blockDim.x) {
        unsigned v = w[i];
        if (v > 1u) li = 0;
        if (v != 0u && v != 0x3F800000u) lf = 0;
    }
    if (!li) atomicAnd(&s_int, 0);
    if (!lf) atomicAnd(&s_flt, 0);
    __syncthreads();
    if (threadIdx.x == 0) g_mask_mode = s_int ? 1 : (s_flt ? 2 : 0);
}

__global__ void argmax_y_kernel(const float* __restrict__ logits,
                                const void* __restrict__ mask,
                                const int* __restrict__ labels,
                                const float* __restrict__ codebook,
                                float* __restrict__ zq)
{
    const int b = blockIdx.x;
    const int lane = threadIdx.x;
    const float NEG = __int_as_float(0xff800000u);
    const float* lr = logits + (size_t)b * KCLS;
    const int k0 = 2 * lane, k1 = 2 * lane + 1;
    float va = (k0 < KCLS) ? lr[k0] : NEG;
    float vb = (k1 < KCLS) ? lr[k1] : NEG;
    float m; int mi;
    if (va >= vb) { m = va; mi = k0; } else { m = vb; mi = k1; }
#pragma unroll
    for (int off = 16; off > 0; off >>= 1) {
        float om = __shfl_xor_sync(0xffffffffu, m, off);
        int oi = __shfl_xor_sync(0xffffffffu, mi, off);
        if (om > m || (om == m && oi < mi)) { m = om; mi = oi; }
    }
    float ea = (k0 < KCLS) ? expf(va - m) : 0.f;
    float eb = (k1 < KCLS) ? expf(vb - m) : 0.f;
    float s = ea + eb;
#pragma unroll
    for (int off = 16; off > 0; off >>= 1) s += __shfl_xor_sync(0xffffffffu, s, off);
    float inv = 1.0f / s;

    int mode = g_mask_mode;
    bool known;
    if (mode == 1)      known = ((const int*)mask)[b] != 0;
    else if (mode == 2) known = ((const float*)mask)[b] != 0.f;
    else                known = ((const unsigned char*)mask)[b] != 0;
    int lab = labels[b];

    float y0 = (k0 < KCLS) ? (known ? (k0 == lab ? 1.f : 0.f) : ea * inv) : 0.f;
    float y1 = (k1 < KCLS) ? (known ? (k1 == lab ? 1.f : 0.f) : eb * inv) : 0.f;
    uint32_t H, L;
    split2(y0, y1, H, L);
    const size_t pi = (size_t)b * (CAT_LD / 2) + (VDIM / 2) + lane;
    g_cath[pi] = H; g_catl[pi] = L;

    const float* cr = codebook + (size_t)mi * ENC_DIM;
    float* zr = zq + (size_t)b * ENC_DIM;
    for (int i = lane; i < ENC_DIM; i += 32) zr[i] = cr[i];
}

__global__ void vae_post_kernel(const float* __restrict__ eps)
{
    const int b = blockIdx.x;
    const int t = threadIdx.x;
    const float* mlr = g_ml + (size_t)b * (2 * VDIM);
    const float* er = eps + (size_t)b * VDIM;
    float kl = 0.f;
#pragma unroll
    for (int p = t; p < VDIM / 2; p += 256) {
        int i0 = 2 * p;
        float2 mu = *reinterpret_cast<const float2*>(mlr + i0);
        float2 lv = *reinterpret_cast<const float2*>(mlr + VDIM + i0);
        float2 ep = *reinterpret_cast<const float2*>(er + i0);
        kl += 0.5f * (fast_exp(lv.x) + mu.x * mu.x - 1.0f - lv.x);
        kl += 0.5f * (fast_exp(lv.y) + mu.y * mu.y - 1.0f - lv.y);
        float v0 = fmaf(fast_exp(0.5f * lv.x), ep.x, mu.x);
        float v1 = fmaf(fast_exp(0.5f * lv.y), ep.y, mu.y);
        uint32_t H, L;
        split2(v0, v1, H, L);
        const size_t pi = (size_t)b * (CAT_LD / 2) + p;
        g_cath[pi] = H; g_catl[pi] = L;
    }
    __shared__ float sm[256];
    sm[t] = kl;
    __syncthreads();
    for (int st = 128; st > 0; st >>= 1) { if (t < st) sm[t] += sm[t + st]; __syncthreads(); }
    if (t == 0) g_klp[b] = sm[0];
}

__global__ void kl_reduce_kernel(float* __restrict__ out)
{
    const int t = threadIdx.x;
    float s = 0.f;
    for (int i = t; i < B_ROWS; i += 256) s += g_klp[i];
    __shared__ float sm[256];
    sm[t] = s;
    __syncthreads();
    for (int st = 128; st > 0; st >>= 1) { if (t < st) sm[t] += sm[t + st]; __syncthreads(); }
    if (t == 0) *out = sm[0] / (float)B_ROWS;
}

// ---------------- host ----------------
static void launch_gemm(const void* Ah, const void* Al, int lda,
                        const void* Bh, const void* Bl, int ldb,
                        const float* bias, float* Cf, void* Ch, void* Cl,
                        int ldc, int nPad, int nOut, int K, int relu, int mode)
{
    cudaFuncSetAttribute(gemm_bf3, cudaFuncAttributeMaxDynamicSharedMemorySize, GEMM_DYN);
    dim3 grid(nPad / 128, B_ROWS / 128);
    gemm_bf3<<<grid, 256, GEMM_DYN>>>(
        (const uint16_t*)Ah, (const uint16_t*)Al, lda,
        (const uint16_t*)Bh, (const uint16_t*)Bl, ldb,
        bias, Cf, (uint16_t*)Ch, (uint16_t*)Cl, ldc, nOut, K, relu, mode);
}

extern "C" void kernel_launch(void* const* d_in, const int* in_sizes, int n_in,
                              void* d_out, int out_size)
{
    const float* x        = (const float*)d_in[0];
    const void*  mask     = d_in[1];
    const int*   labels   = (const int*)d_in[2];
    const float* eps      = (const float*)d_in[3];
    const float* W_enc    = (const float*)d_in[4];
    const float* b_enc    = (const float*)d_in[5];
    const float* codebook = (const float*)d_in[6];
    const float* W1       = (const float*)d_in[7];
    const float* b1       = (const float*)d_in[8];
    const float* W2       = (const float*)d_in[9];
    const float* b2       = (const float*)d_in[10];
    const float* Wd       = (const float*)d_in[11];
    const float* bd       = (const float*)d_in[12];
    float* out = (float*)d_out;

    void *p_xh, *p_xl, *p_weh, *p_wel, *p_w1h, *p_w1l, *p_w2h, *p_w2l, *p_wdh, *p_wdl;
    void *p_hh, *p_hl, *p_cath, *p_catl;
    float *p_ml, *p_G, *p_lb, *p_ze, *p_zq, *p_lg, *p_kl;
    cudaGetSymbolAddress(&p_xh, g_xh);   cudaGetSymbolAddress(&p_xl, g_xl);
    cudaGetSymbolAddress(&p_weh, g_weh); cudaGetSymbolAddress(&p_wel, g_wel);
    cudaGetSymbolAddress(&p_w1h, g_w1h); cudaGetSymbolAddress(&p_w1l, g_w1l);
    cudaGetSymbolAddress(&p_w2h, g_w2h); cudaGetSymbolAddress(&p_w2l, g_w2l);
    cudaGetSymbolAddress(&p_wdh, g_wdh); cudaGetSymbolAddress(&p_wdl, g_wdl);
    cudaGetSymbolAddress(&p_hh, g_hh);   cudaGetSymbolAddress(&p_hl, g_hl);
    cudaGetSymbolAddress(&p_cath, g_cath); cudaGetSymbolAddress(&p_catl, g_catl);
    cudaGetSymbolAddress((void**)&p_ml, g_ml);
    cudaGetSymbolAddress((void**)&p_G,  g_G);
    cudaGetSymbolAddress((void**)&p_lb, g_lb);
    cudaGetSymbolAddress((void**)&p_ze, g_ze_s);
    cudaGetSymbolAddress((void**)&p_zq, g_zq_s);
    cudaGetSymbolAddress((void**)&p_lg, g_lg_s);
    cudaGetSymbolAddress((void**)&p_kl, g_kl_s);

    const size_t full_elems = (size_t)B_ROWS * (IN_DIM + ENC_DIM + ENC_DIM + KCLS) + 1;
    const bool full = ((size_t)out_size >= full_elems);
    float* xt = out;
    float* ze = full ? out + (size_t)B_ROWS * IN_DIM : p_ze;
    float* zq = full ? ze + (size_t)B_ROWS * ENC_DIM : p_zq;
    float* lg = full ? zq + (size_t)B_ROWS * ENC_DIM : p_lg;
    float* kl = full ? lg + (size_t)B_ROWS * KCLS    : p_kl;

    // ---- prep: splits + logits weights + mask mode ----
    {
        long np = (long)B_ROWS * IN_DIM / 2;
        split_mat<<<(unsigned)((np + 255) / 256), 256>>>(x, (uint32_t*)p_xh, (uint32_t*)p_xl, np, np);
        long sp = (long)ENC_DIM * IN_DIM / 2, tp = (long)ZE_NPAD * IN_DIM / 2;
        split_mat<<<(unsigned)((tp + 255) / 256), 256>>>(W_enc, (uint32_t*)p_weh, (uint32_t*)p_wel, tp, sp);
        long w1p = (long)VDIM * IN_DIM / 2;
        split_mat<<<(unsigned)((w1p + 255) / 256), 256>>>(W1, (uint32_t*)p_w1h, (uint32_t*)p_w1l, w1p, w1p);
        long w2p = (long)2 * VDIM * VDIM / 2;
        split_mat<<<(unsigned)((w2p + 255) / 256), 256>>>(W2, (uint32_t*)p_w2h, (uint32_t*)p_w2l, w2p, w2p);
        split_wd<<<(IN_DIM * (CAT_LD / 2) + 255) / 256, 256>>>(Wd);
    }
    detect_mask_kernel<<<1, 256>>>((const unsigned int*)mask);
    build_G<<<dim3(KCLS, IN_DIM / 128), 128>>>(W_enc, codebook);
    build_lb<<<KCLS, 128>>>(b_enc, codebook);

    // logits (exact fp32 via G = codebook @ W_enc)
    sgemm64<<<B_ROWS / 64, 128>>>(x, p_G, p_lb, lg);

    // z_e_x
    launch_gemm(p_xh, p_xl, IN_DIM, p_weh, p_wel, IN_DIM, b_enc,
                ze, nullptr, nullptr, ENC_DIM, ZE_NPAD, ENC_DIM, IN_DIM, 0, 0);
    // h = relu(x@W1^T + b1) -> bf16 hi/lo
    launch_gemm(p_xh, p_xl, IN_DIM, p_w1h, p_w1l, IN_DIM, b1,
                nullptr, p_hh, p_hl, VDIM, VDIM, VDIM, IN_DIM, 1, 1);
    // mu||logvar
    launch_gemm(p_hh, p_hl, VDIM, p_w2h, p_w2l, VDIM, b2,
                p_ml, nullptr, nullptr, 2 * VDIM, 2 * VDIM, 2 * VDIM, VDIM, 0, 0);

    // argmax / y / z_q (fills cat y region)
    argmax_y_kernel<<<B_ROWS, 32>>>(lg, mask, labels, codebook, zq);
    // sampled_z (fills cat z region) + KL
    vae_post_kernel<<<B_ROWS, 256>>>(eps);
    kl_reduce_kernel<<<1, 256>>>(kl);

    // decoder
    launch_gemm(p_cath, p_catl, CAT_LD, p_wdh, p_wdl, CAT_LD, bd,
                xt, nullptr, nullptr, IN_DIM, IN_DIM, IN_DIM, CAT_LD, 0, 0);
}

// round 11
// speedup vs baseline: 1.9607x; 1.0692x over previous
#include <cuda_runtime.h>
#include <cuda_bf16.h>
#include <math.h>
#include <stdint.h>

#define B_ROWS 16384
#define IN_DIM 768
#define ENC_DIM 500
#define ZE_NPAD 512
#define KCLS 43
#define VDIM 1024
#define CAT_RAW 1067
#define CAT_LD  1088   // multiple of 64

// ---------------- scratch (bf16 pairs stored as uint32) ----------------
__device__ uint32_t g_xh [(size_t)B_ROWS * IN_DIM / 2];
__device__ uint32_t g_xl [(size_t)B_ROWS * IN_DIM / 2];
__device__ uint32_t g_weh[(size_t)ZE_NPAD * IN_DIM / 2];
__device__ uint32_t g_wel[(size_t)ZE_NPAD * IN_DIM / 2];
__device__ uint32_t g_w1h[(size_t)VDIM * IN_DIM / 2];
__device__ uint32_t g_w1l[(size_t)VDIM * IN_DIM / 2];
__device__ uint32_t g_w2h[(size_t)2 * VDIM * VDIM / 2];
__device__ uint32_t g_w2l[(size_t)2 * VDIM * VDIM / 2];
__device__ uint32_t g_wdh[(size_t)IN_DIM * CAT_LD / 2];
__device__ uint32_t g_wdl[(size_t)IN_DIM * CAT_LD / 2];
__device__ uint32_t g_hh [(size_t)B_ROWS * VDIM / 2];
__device__ uint32_t g_hl [(size_t)B_ROWS * VDIM / 2];
__device__ uint32_t g_cath[(size_t)B_ROWS * CAT_LD / 2];
__device__ uint32_t g_catl[(size_t)B_ROWS * CAT_LD / 2];
__device__ float g_ml [(size_t)B_ROWS * 2 * VDIM];
__device__ float g_G  [(size_t)KCLS * IN_DIM];
__device__ float g_lb [KCLS];
__device__ float g_klp[B_ROWS];
__device__ float g_ze_s[(size_t)B_ROWS * ENC_DIM];
__device__ float g_zq_s[(size_t)B_ROWS * ENC_DIM];
__device__ float g_lg_s[(size_t)B_ROWS * KCLS];
__device__ float g_kl_s[1];
__device__ int   g_mask_mode;

// ---------------- helpers ----------------
__device__ __forceinline__ uint32_t smem_to_u32(const void* p) {
    uint32_t a;
    asm("{ .reg .u64 t; cvta.to.shared.u64 t, %1; cvt.u32.u64 %0, t; }" : "=r"(a) : "l"(p));
    return a;
}
#define SWZ(b) ((b) ^ (((b) >> 3) & 0x70))
#define CP16(d, s)  asm volatile("cp.async.cg.shared.global [%0], [%1], 16;" :: "r"(d), "l"(s) : "memory")
#define CP_COMMIT() asm volatile("cp.async.commit_group;" ::: "memory")
#define CP_WAIT0()  asm volatile("cp.async.wait_group 0;" ::: "memory")
#define CP_WAIT1()  asm volatile("cp.async.wait_group 1;" ::: "memory")

__device__ __forceinline__ void ldsm_x4(uint32_t* r, uint32_t addr) {
    asm volatile("ldmatrix.sync.aligned.m8n8.x4.shared.b16 {%0,%1,%2,%3}, [%4];"
        : "=r"(r[0]), "=r"(r[1]), "=r"(r[2]), "=r"(r[3]) : "r"(addr));
}
__device__ __forceinline__ void mma16816(float* c, const uint32_t* a, const uint32_t* b) {
    asm volatile("mma.sync.aligned.m16n8k16.row.col.f32.bf16.bf16.f32 "
        "{%0,%1,%2,%3}, {%4,%5,%6,%7}, {%8,%9}, {%0,%1,%2,%3};"
        : "+f"(c[0]), "+f"(c[1]), "+f"(c[2]), "+f"(c[3])
        : "r"(a[0]), "r"(a[1]), "r"(a[2]), "r"(a[3]), "r"(b[0]), "r"(b[1]));
}
__device__ __forceinline__ void split2(float v0, float v1, uint32_t& H, uint32_t& L) {
    uint32_t u0 = __float_as_uint(v0), u1 = __float_as_uint(v1);
    H = __byte_perm(u0, u1, 0x7632);
    float l0 = v0 - __uint_as_float(u0 & 0xFFFF0000u);
    float l1 = v1 - __uint_as_float(u1 & 0xFFFF0000u);
    asm("cvt.rn.bf16x2.f32 %0, %1, %2;" : "=r"(L) : "f"(l1), "f"(l0));
}
__device__ __forceinline__ float fast_exp(float x) {
    float r;
    asm("ex2.approx.ftz.f32 %0, %1;" : "=f"(r) : "f"(x * 1.4426950408889634f));
    return r;
}

// ---------------- 2-stage pipelined mma.sync bf16x3 GEMM ----------------
// CTA tile 64(M) x 128(N), 8 warps (2x4), warp tile 32x32, K chunk 64.
// Stage: Ah(8K) Al(8K) Bh(16K) Bl(16K) = 48KB; 2 stages = 96KB -> 2 CTAs/SM.
#define ST_BYTES 49152u
#define OFF_AL 8192u
#define OFF_BH 16384u
#define OFF_BL 32768u
#define GEMM_DYN (2 * 49152 + 1024)

__device__ __forceinline__ void load_chunk(uint32_t base, int tid, int m0, int n0, int k0,
    const uint16_t* Ah, const uint16_t* Al, int lda,
    const uint16_t* Bh, const uint16_t* Bl, int ldb)
{
    // A: 64 rows x 128B per slice (512 segs each slice)
#pragma unroll
    for (int half = 0; half < 2; half++) {
        int idx = half * 256 + tid;      // 0..511
        int row = idx >> 3, u = idx & 7;
        uint32_t off = SWZ((uint32_t)(row * 128 + u * 16));
        size_t ao = (size_t)(m0 + row) * lda + k0 + u * 8;
        CP16(base + off,          Ah + ao);
        CP16(base + OFF_AL + off, Al + ao);
    }
    // B: 128 rows x 128B per slice (1024 segs each slice)
#pragma unroll
    for (int it = 0; it < 4; it++) {
        int idx = it * 256 + tid;        // 0..1023
        int row = idx >> 3, u = idx & 7;
        uint32_t off = SWZ((uint32_t)(row * 128 + u * 16));
        size_t bo = (size_t)(n0 + row) * ldb + k0 + u * 8;
        CP16(base + OFF_BH + off, Bh + bo);
        CP16(base + OFF_BL + off, Bl + bo);
    }
}

// mode: 0 = fp32 C (+bias,+relu,col-guard), 1 = split bf16 hi/lo C
__global__ __launch_bounds__(256, 2)
void gemm_bf3(const uint16_t* __restrict__ Ah, const uint16_t* __restrict__ Al, int lda,
              const uint16_t* __restrict__ Bh, const uint16_t* __restrict__ Bl, int ldb,
              const float* __restrict__ bias,
              float* __restrict__ Cf, uint16_t* __restrict__ Ch, uint16_t* __restrict__ Cl,
              int ldc, int nOut, int K, int relu, int mode)
{
    extern __shared__ char smem[];
    const uint32_t tiles = (smem_to_u32(smem) + 1023) & ~1023u;
    const int tid = threadIdx.x, wid = tid >> 5, lane = tid & 31;
    const int m0 = blockIdx.y * 64, n0 = blockIdx.x * 128;
    const int wm = (wid >> 2) * 32, wn = (wid & 3) * 32;

    float acc[2][4][4];
#pragma unroll
    for (int i = 0; i < 2; i++)
#pragma unroll
        for (int j = 0; j < 4; j++)
#pragma unroll
            for (int q = 0; q < 4; q++) acc[i][j][q] = 0.f;

    const uint32_t aRowByte = (uint32_t)(wm + (lane & 15)) * 128u;
    const uint32_t aKoff    = (uint32_t)((lane >> 4) * 16);
    const uint32_t bRowByte = (uint32_t)(wn + (lane & 7) + ((lane >> 4) << 3)) * 128u;
    const uint32_t bKoff    = (uint32_t)(((lane >> 3) & 1) * 16);

    const int S = K / 64;
    load_chunk(tiles, tid, m0, n0, 0, Ah, Al, lda, Bh, Bl, ldb);
    CP_COMMIT();

    for (int s = 0; s < S; s++) {
        if (s + 1 < S) {
            load_chunk(tiles + ((s + 1) & 1) * ST_BYTES, tid, m0, n0, (s + 1) * 64,
                       Ah, Al, lda, Bh, Bl, ldb);
            CP_COMMIT();
            CP_WAIT1();
        } else {
            CP_WAIT0();
        }
        __syncthreads();

        const uint32_t pah = tiles + (s & 1) * ST_BYTES;
        const uint32_t pal = pah + OFF_AL, pbh = pah + OFF_BH, pbl = pah + OFF_BL;
#pragma unroll
        for (int kk = 0; kk < 4; kk++) {
            const uint32_t kb = (uint32_t)(kk * 32);
            uint32_t ah[2][4], al[2][4], bh[2][4], bl[2][4];
#pragma unroll
            for (int mt = 0; mt < 2; mt++) {
                uint32_t ro = SWZ(aRowByte + (uint32_t)(mt * 2048) + kb + aKoff);
                ldsm_x4(ah[mt], pah + ro);
                ldsm_x4(al[mt], pal + ro);
            }
#pragma unroll
            for (int nb = 0; nb < 2; nb++) {
                uint32_t ro = SWZ(bRowByte + (uint32_t)(nb * 2048) + kb + bKoff);
                ldsm_x4(bh[nb], pbh + ro);
                ldsm_x4(bl[nb], pbl + ro);
            }
#pragma unroll
            for (int t3 = 0; t3 < 3; t3++)
#pragma unroll
                for (int mt = 0; mt < 2; mt++)
#pragma unroll
                    for (int nt = 0; nt < 4; nt++) {
                        const uint32_t* ap = (t3 == 1) ? al[mt] : ah[mt];
                        const uint32_t* bp = (t3 == 2) ? &bl[nt >> 1][(nt & 1) * 2]
                                                       : &bh[nt >> 1][(nt & 1) * 2];
                        mma16816(acc[mt][nt], ap, bp);
                    }
        }
        __syncthreads();
    }

    // ---- epilogue ----
    if (mode == 0) {
#pragma unroll
        for (int mt = 0; mt < 2; mt++) {
            const int r0 = m0 + wm + mt * 16 + (lane >> 2);
            float* crow0 = Cf + (size_t)r0 * ldc;
            float* crow8 = Cf + (size_t)(r0 + 8) * ldc;
#pragma unroll
            for (int nt = 0; nt < 4; nt++) {
                const int c = n0 + wn + nt * 8 + (lane & 3) * 2;
                if (c >= nOut) continue;
                float b0 = bias[c], b1 = bias[c + 1];
                float v0 = acc[mt][nt][0] + b0, v1 = acc[mt][nt][1] + b1;
                float v2 = acc[mt][nt][2] + b0, v3 = acc[mt][nt][3] + b1;
                if (relu) {
                    v0 = fmaxf(v0, 0.f); v1 = fmaxf(v1, 0.f);
                    v2 = fmaxf(v2, 0.f); v3 = fmaxf(v3, 0.f);
                }
                *reinterpret_cast<float2*>(crow0 + c) = make_float2(v0, v1);
                *reinterpret_cast<float2*>(crow8 + c) = make_float2(v2, v3);
            }
        }
    } else {
#pragma unroll
        for (int mt = 0; mt < 2; mt++) {
            const int r0 = m0 + wm + mt * 16 + (lane >> 2);
#pragma unroll
            for (int nt = 0; nt < 4; nt++) {
                const int c = n0 + wn + nt * 8 + (lane & 3) * 2;
                float b0 = bias[c], b1 = bias[c + 1];
                float v0 = acc[mt][nt][0] + b0, v1 = acc[mt][nt][1] + b1;
                float v2 = acc[mt][nt][2] + b0, v3 = acc[mt][nt][3] + b1;
                if (relu) {
                    v0 = fmaxf(v0, 0.f); v1 = fmaxf(v1, 0.f);
                    v2 = fmaxf(v2, 0.f); v3 = fmaxf(v3, 0.f);
                }
                uint32_t H, L;
                split2(v0, v1, H, L);
                *reinterpret_cast<uint32_t*>(Ch + (size_t)r0 * ldc + c) = H;
                *reinterpret_cast<uint32_t*>(Cl + (size_t)r0 * ldc + c) = L;
                split2(v2, v3, H, L);
                *reinterpret_cast<uint32_t*>(Ch + (size_t)(r0 + 8) * ldc + c) = H;
                *reinterpret_cast<uint32_t*>(Cl + (size_t)(r0 + 8) * ldc + c) = L;
            }
        }
    }
}

// ---------------- logits SGEMM: 64x64 tile, exact fp32 ----------------
__global__ __launch_bounds__(128)
void sgemm64(const float* __restrict__ A, const float* __restrict__ G,
             const float* __restrict__ lb, float* __restrict__ C)
{
    __shared__ float As[16][64];
    __shared__ float Bs[16][64];
    const int tid = threadIdx.x;
    const int m0 = blockIdx.x * 64;
    const int tx = tid & 15, ty = tid >> 4;
    const int lrow = tid >> 1, lhalf = tid & 1;
    float acc[8][4];
#pragma unroll
    for (int i = 0; i < 8; i++)
#pragma unroll
        for (int j = 0; j < 4; j++) acc[i][j] = 0.f;

    for (int k0 = 0; k0 < IN_DIM; k0 += 16) {
#pragma unroll
        for (int h = 0; h < 2; h++) {
            int kk = lhalf * 8 + h * 4;
            float4 va = *reinterpret_cast<const float4*>(A + (size_t)(m0 + lrow) * IN_DIM + k0 + kk);
            As[kk + 0][lrow] = va.x; As[kk + 1][lrow] = va.y;
            As[kk + 2][lrow] = va.z; As[kk + 3][lrow] = va.w;
            float4 vb = make_float4(0.f, 0.f, 0.f, 0.f);
            if (lrow < KCLS)
                vb = *reinterpret_cast<const float4*>(G + (size_t)lrow * IN_DIM + k0 + kk);
            Bs[kk + 0][lrow] = vb.x; Bs[kk + 1][lrow] = vb.y;
            Bs[kk + 2][lrow] = vb.z; Bs[kk + 3][lrow] = vb.w;
        }
        __syncthreads();
#pragma unroll
        for (int k = 0; k < 16; k++) {
            float4 a0 = *reinterpret_cast<const float4*>(&As[k][ty * 4]);
            float4 a1 = *reinterpret_cast<const float4*>(&As[k][32 + ty * 4]);
            float4 b  = *reinterpret_cast<const float4*>(&Bs[k][tx * 4]);
            float a[8] = {a0.x, a0.y, a0.z, a0.w, a1.x, a1.y, a1.z, a1.w};
            float bb[4] = {b.x, b.y, b.z, b.w};
#pragma unroll
            for (int i = 0; i < 8; i++)
#pragma unroll
                for (int j = 0; j < 4; j++)
                    acc[i][j] = fmaf(a[i], bb[j], acc[i][j]);
        }
        __syncthreads();
    }
#pragma unroll
    for (int i = 0; i < 8; i++) {
        int row = m0 + ((i < 4) ? (ty * 4 + i) : (32 + ty * 4 + i - 4));
#pragma unroll
        for (int j = 0; j < 4; j++) {
            int col = tx * 4 + j;
            if (col < KCLS) C[(size_t)row * KCLS + col] = acc[i][j] + lb[col];
        }
    }
}

// ---------------- prep kernels ----------------
__global__ void split_mat(const float* __restrict__ src, uint32_t* __restrict__ dh,
                          uint32_t* __restrict__ dl, long nPairs, long srcPairs)
{
    long i = (long)blockIdx.x * blockDim.x + threadIdx.x;
    if (i >= nPairs) return;
    float v0 = 0.f, v1 = 0.f;
    if (i < srcPairs) {
        float2 v = reinterpret_cast<const float2*>(src)[i];
        v0 = v.x; v1 = v.y;
    }
    uint32_t H, L;
    split2(v0, v1, H, L);
    dh[i] = H; dl[i] = L;
}

__global__ void split_wd(const float* __restrict__ Wd)
{
    int i = blockIdx.x * blockDim.x + threadIdx.x;
    const int ppr = CAT_LD / 2;
    if (i >= IN_DIM * ppr) return;
    int r = i / ppr, p = i - r * ppr;
    int c0 = 2 * p;
    float v0 = (c0 < CAT_RAW) ? Wd[(size_t)r * CAT_RAW + c0] : 0.f;
    float v1 = (c0 + 1 < CAT_RAW) ? Wd[(size_t)r * CAT_RAW + c0 + 1] : 0.f;
    uint32_t H, L;
    split2(v0, v1, H, L);
    g_wdh[i] = H; g_wdl[i] = L;
}

__global__ void build_G(const float* __restrict__ W_enc, const float* __restrict__ cb)
{
    int c = blockIdx.x;
    int i = blockIdx.y * 128 + threadIdx.x;
    float s = 0.f;
#pragma unroll 4
    for (int d = 0; d < ENC_DIM; d++)
        s = fmaf(cb[c * ENC_DIM + d], W_enc[(size_t)d * IN_DIM + i], s);
    g_G[(size_t)c * IN_DIM + i] = s;
}
__global__ void build_lb(const float* __restrict__ b_enc, const float* __restrict__ cb)
{
    int c = blockIdx.x;
    int t = threadIdx.x;
    float s = 0.f;
    for (int d = t; d < ENC_DIM; d += 128) s = fmaf(b_enc[d], cb[c * ENC_DIM + d], s);
    __shared__ float sm[128];
    sm[t] = s;
    __syncthreads();
    for (int st = 64; st > 0; st >>= 1) { if (t < st) sm[t] += sm[t + st]; __syncthreads(); }
    if (t == 0) g_lb[c] = sm[0];
}

__global__ void detect_mask_kernel(const unsigned int* __restrict__ w)
{
    __shared__ int s_int, s_flt;
    if (threadIdx.x == 0) { s_int = 1; s_flt = 1; }
    __syncthreads();
    int li = 1, lf = 1;
    for (int i = threadIdx.x; i < 4096; i += blockDim.x) {
        unsigned v = w[i];
        if (v > 1u) li = 0;
        if (v != 0u && v != 0x3F800000u) lf = 0;
    }
    if (!li) atomicAnd(&s_int, 0);
    if (!lf) atomicAnd(&s_flt, 0);
    __syncthreads();
    if (threadIdx.x == 0) g_mask_mode = s_int ? 1 : (s_flt ? 2 : 0);
}

__global__ void argmax_y_kernel(const float* __restrict__ logits,
                                const void* __restrict__ mask,
                                const int* __restrict__ labels,
                                const float* __restrict__ codebook,
                                float* __restrict__ zq)
{
    const int b = blockIdx.x;
    const int lane = threadIdx.x;
    const float NEG = __int_as_float(0xff800000u);
    const float* lr = logits + (size_t)b * KCLS;
    const int k0 = 2 * lane, k1 = 2 * lane + 1;
    float va = (k0 < KCLS) ? lr[k0] : NEG;
    float vb = (k1 < KCLS) ? lr[k1] : NEG;
    float m; int mi;
    if (va >= vb) { m = va; mi = k0; } else { m = vb; mi = k1; }
#pragma unroll
    for (int off = 16; off > 0; off >>= 1) {
        float om = __shfl_xor_sync(0xffffffffu, m, off);
        int oi = __shfl_xor_sync(0xffffffffu, mi, off);
        if (om > m || (om == m && oi < mi)) { m = om; mi = oi; }
    }
    float ea = (k0 < KCLS) ? expf(va - m) : 0.f;
    float eb = (k1 < KCLS) ? expf(vb - m) : 0.f;
    float s = ea + eb;
#pragma unroll
    for (int off = 16; off > 0; off >>= 1) s += __shfl_xor_sync(0xffffffffu, s, off);
    float inv = 1.0f / s;

    int mode = g_mask_mode;
    bool known;
    if (mode == 1)      known = ((const int*)mask)[b] != 0;
    else if (mode == 2) known = ((const float*)mask)[b] != 0.f;
    else                known = ((const unsigned char*)mask)[b] != 0;
    int lab = labels[b];

    float y0 = (k0 < KCLS) ? (known ? (k0 == lab ? 1.f : 0.f) : ea * inv) : 0.f;
    float y1 = (k1 < KCLS) ? (known ? (k1 == lab ? 1.f : 0.f) : eb * inv) : 0.f;
    uint32_t H, L;
    split2(y0, y1, H, L);
    const size_t pi = (size_t)b * (CAT_LD / 2) + (VDIM / 2) + lane;
    g_cath[pi] = H; g_catl[pi] = L;

    const float* cr = codebook + (size_t)mi * ENC_DIM;
    float* zr = zq + (size_t)b * ENC_DIM;
    for (int i = lane; i < ENC_DIM; i += 32) zr[i] = cr[i];
}

__global__ void vae_post_kernel(const float* __restrict__ eps)
{
    const int b = blockIdx.x;
    const int t = threadIdx.x;
    const float* mlr = g_ml + (size_t)b * (2 * VDIM);
    const float* er = eps + (size_t)b * VDIM;
    float kl = 0.f;
#pragma unroll
    for (int p = t; p < VDIM / 2; p += 256) {
        int i0 = 2 * p;
        float2 mu = *reinterpret_cast<const float2*>(mlr + i0);
        float2 lv = *reinterpret_cast<const float2*>(mlr + VDIM + i0);
        float2 ep = *reinterpret_cast<const float2*>(er + i0);
        kl += 0.5f * (fast_exp(lv.x) + mu.x * mu.x - 1.0f - lv.x);
        kl += 0.5f * (fast_exp(lv.y) + mu.y * mu.y - 1.0f - lv.y);
        float v0 = fmaf(fast_exp(0.5f * lv.x), ep.x, mu.x);
        float v1 = fmaf(fast_exp(0.5f * lv.y), ep.y, mu.y);
        uint32_t H, L;
        split2(v0, v1, H, L);
        const size_t pi = (size_t)b * (CAT_LD / 2) + p;
        g_cath[pi] = H; g_catl[pi] = L;
    }
    __shared__ float sm[256];
    sm[t] = kl;
    __syncthreads();
    for (int st = 128; st > 0; st >>= 1) { if (t < st) sm[t] += sm[t + st]; __syncthreads(); }
    if (t == 0) g_klp[b] = sm[0];
}

__global__ void kl_reduce_kernel(float* __restrict__ out)
{
    const int t = threadIdx.x;
    float s = 0.f;
    for (int i = t; i < B_ROWS; i += 256) s += g_klp[i];
    __shared__ float sm[256];
    sm[t] = s;
    __syncthreads();
    for (int st = 128; st > 0; st >>= 1) { if (t < st) sm[t] += sm[t + st]; __syncthreads(); }
    if (t == 0) *out = sm[0] / (float)B_ROWS;
}

// ---------------- host ----------------
static void launch_gemm(const void* Ah, const void* Al, int lda,
                        const void* Bh, const void* Bl, int ldb,
                        const float* bias, float* Cf, void* Ch, void* Cl,
                        int ldc, int nPad, int nOut, int K, int relu, int mode)
{
    cudaFuncSetAttribute(gemm_bf3, cudaFuncAttributeMaxDynamicSharedMemorySize, GEMM_DYN);
    dim3 grid(nPad / 128, B_ROWS / 64);
    gemm_bf3<<<grid, 256, GEMM_DYN>>>(
        (const uint16_t*)Ah, (const uint16_t*)Al, lda,
        (const uint16_t*)Bh, (const uint16_t*)Bl, ldb,
        bias, Cf, (uint16_t*)Ch, (uint16_t*)Cl, ldc, nOut, K, relu, mode);
}

extern "C" void kernel_launch(void* const* d_in, const int* in_sizes, int n_in,
                              void* d_out, int out_size)
{
    const float* x        = (const float*)d_in[0];
    const void*  mask     = d_in[1];
    const int*   labels   = (const int*)d_in[2];
    const float* eps      = (const float*)d_in[3];
    const float* W_enc    = (const float*)d_in[4];
    const float* b_enc    = (const float*)d_in[5];
    const float* codebook = (const float*)d_in[6];
    const float* W1       = (const float*)d_in[7];
    const float* b1       = (const float*)d_in[8];
    const float* W2       = (const float*)d_in[9];
    const float* b2       = (const float*)d_in[10];
    const float* Wd       = (const float*)d_in[11];
    const float* bd       = (const float*)d_in[12];
    float* out = (float*)d_out;

    void *p_xh, *p_xl, *p_weh, *p_wel, *p_w1h, *p_w1l, *p_w2h, *p_w2l, *p_wdh, *p_wdl;
    void *p_hh, *p_hl, *p_cath, *p_catl;
    float *p_ml, *p_G, *p_lb, *p_ze, *p_zq, *p_lg, *p_kl;
    cudaGetSymbolAddress(&p_xh, g_xh);   cudaGetSymbolAddress(&p_xl, g_xl);
    cudaGetSymbolAddress(&p_weh, g_weh); cudaGetSymbolAddress(&p_wel, g_wel);
    cudaGetSymbolAddress(&p_w1h, g_w1h); cudaGetSymbolAddress(&p_w1l, g_w1l);
    cudaGetSymbolAddress(&p_w2h, g_w2h); cudaGetSymbolAddress(&p_w2l, g_w2l);
    cudaGetSymbolAddress(&p_wdh, g_wdh); cudaGetSymbolAddress(&p_wdl, g_wdl);
    cudaGetSymbolAddress(&p_hh, g_hh);   cudaGetSymbolAddress(&p_hl, g_hl);
    cudaGetSymbolAddress(&p_cath, g_cath); cudaGetSymbolAddress(&p_catl, g_catl);
    cudaGetSymbolAddress((void**)&p_ml, g_ml);
    cudaGetSymbolAddress((void**)&p_G,  g_G);
    cudaGetSymbolAddress((void**)&p_lb, g_lb);
    cudaGetSymbolAddress((void**)&p_ze, g_ze_s);
    cudaGetSymbolAddress((void**)&p_zq, g_zq_s);
    cudaGetSymbolAddress((void**)&p_lg, g_lg_s);
    cudaGetSymbolAddress((void**)&p_kl, g_kl_s);

    const size_t full_elems = (size_t)B_ROWS * (IN_DIM + ENC_DIM + ENC_DIM + KCLS) + 1;
    const bool full = ((size_t)out_size >= full_elems);
    float* xt = out;
    float* ze = full ? out + (size_t)B_ROWS * IN_DIM : p_ze;
    float* zq = full ? ze + (size_t)B_ROWS * ENC_DIM : p_zq;
    float* lg = full ? zq + (size_t)B_ROWS * ENC_DIM : p_lg;
    float* kl = full ? lg + (size_t)B_ROWS * KCLS    : p_kl;

    // ---- prep: splits + logits weights + mask mode ----
    {
        long np = (long)B_ROWS * IN_DIM / 2;
        split_mat<<<(unsigned)((np + 255) / 256), 256>>>(x, (uint32_t*)p_xh, (uint32_t*)p_xl, np, np);
        long sp = (long)ENC_DIM * IN_DIM / 2, tp = (long)ZE_NPAD * IN_DIM / 2;
        split_mat<<<(unsigned)((tp + 255) / 256), 256>>>(W_enc, (uint32_t*)p_weh, (uint32_t*)p_wel, tp, sp);
        long w1p = (long)VDIM * IN_DIM / 2;
        split_mat<<<(unsigned)((w1p + 255) / 256), 256>>>(W1, (uint32_t*)p_w1h, (uint32_t*)p_w1l, w1p, w1p);
        long w2p = (long)2 * VDIM * VDIM / 2;
        split_mat<<<(unsigned)((w2p + 255) / 256), 256>>>(W2, (uint32_t*)p_w2h, (uint32_t*)p_w2l, w2p, w2p);
        split_wd<<<(IN_DIM * (CAT_LD / 2) + 255) / 256, 256>>>(Wd);
    }
    detect_mask_kernel<<<1, 256>>>((const unsigned int*)mask);
    build_G<<<dim3(KCLS, IN_DIM / 128), 128>>>(W_enc, codebook);
    build_lb<<<KCLS, 128>>>(b_enc, codebook);

    // logits (exact fp32 via G = codebook @ W_enc)
    sgemm64<<<B_ROWS / 64, 128>>>(x, p_G, p_lb, lg);

    // z_e_x
    launch_gemm(p_xh, p_xl, IN_DIM, p_weh, p_wel, IN_DIM, b_enc,
                ze, nullptr, nullptr, ENC_DIM, ZE_NPAD, ENC_DIM, IN_DIM, 0, 0);
    // h = relu(x@W1^T + b1) -> bf16 hi/lo
    launch_gemm(p_xh, p_xl, IN_DIM, p_w1h, p_w1l, IN_DIM, b1,
                nullptr, p_hh, p_hl, VDIM, VDIM, VDIM, IN_DIM, 1, 1);
    // mu||logvar
    launch_gemm(p_hh, p_hl, VDIM, p_w2h, p_w2l, VDIM, b2,
                p_ml, nullptr, nullptr, 2 * VDIM, 2 * VDIM, 2 * VDIM, VDIM, 0, 0);

    // argmax / y / z_q (fills cat y region)
    argmax_y_kernel<<<B_ROWS, 32>>>(lg, mask, labels, codebook, zq);
    // sampled_z (fills cat z region) + KL
    vae_post_kernel<<<B_ROWS, 256>>>(eps);
    kl_reduce_kernel<<<1, 256>>>(kl);

    // decoder
    launch_gemm(p_cath, p_catl, CAT_LD, p_wdh, p_wdl, CAT_LD, bd,
                xt, nullptr, nullptr, IN_DIM, IN_DIM, IN_DIM, CAT_LD, 0, 0);
}

// round 12
// speedup vs baseline: 1.9726x; 1.0061x over previous
#include <cuda_runtime.h>
#include <cuda_bf16.h>
#include <math.h>
#include <stdint.h>

#define B_ROWS 16384
#define IN_DIM 768
#define ENC_DIM 500
#define KCLS 43
#define VDIM 1024
#define CAT_RAW 1067
#define CAT_LD  1088
#define NCOMB 1536

__device__ uint32_t g_xh [(size_t)B_ROWS * IN_DIM / 2];
__device__ uint32_t g_xl [(size_t)B_ROWS * IN_DIM / 2];
__device__ uint32_t g_wch[(size_t)NCOMB * IN_DIM / 2];
__device__ uint32_t g_wcl[(size_t)NCOMB * IN_DIM / 2];
__device__ uint32_t g_w2h[(size_t)2 * VDIM * VDIM / 2];
__device__ uint32_t g_w2l[(size_t)2 * VDIM * VDIM / 2];
__device__ uint32_t g_wdh[(size_t)IN_DIM * CAT_LD / 2];
__device__ uint32_t g_wdl[(size_t)IN_DIM * CAT_LD / 2];
__device__ uint32_t g_hh [(size_t)B_ROWS * VDIM / 2];
__device__ uint32_t g_hl [(size_t)B_ROWS * VDIM / 2];
__device__ uint32_t g_cath[(size_t)B_ROWS * CAT_LD / 2];
__device__ uint32_t g_catl[(size_t)B_ROWS * CAT_LD / 2];
__device__ float g_G  [(size_t)KCLS * IN_DIM];
__device__ float g_lb [KCLS];
__device__ float g_klq[4096];
__device__ float g_ze_s[(size_t)B_ROWS * ENC_DIM];
__device__ float g_zq_s[(size_t)B_ROWS * ENC_DIM];
__device__ float g_lg_s[(size_t)B_ROWS * KCLS];
__device__ float g_kl_s[1];
__device__ int   g_mask_mode;

__device__ __forceinline__ uint32_t smem_to_u32(const void* p) {
    uint32_t a;
    asm("{ .reg .u64 t; cvta.to.shared.u64 t, %1; cvt.u32.u64 %0, t; }" : "=r"(a) : "l"(p));
    return a;
}
#define SWZ(b) ((b) ^ (((b) >> 3) & 0x70))
#define CP16(d, s)  asm volatile("cp.async.cg.shared.global [%0], [%1], 16;" :: "r"(d), "l"(s) : "memory")
#define CP_COMMIT() asm volatile("cp.async.commit_group;" ::: "memory")
#define CP_WAIT0()  asm volatile("cp.async.wait_group 0;" ::: "memory")
#define CP_WAIT1()  asm volatile("cp.async.wait_group 1;" ::: "memory")

__device__ __forceinline__ void ldsm_x4(uint32_t* r, uint32_t addr) {
    asm volatile("ldmatrix.sync.aligned.m8n8.x4.shared.b16 {%0,%1,%2,%3}, [%4];"
        : "=r"(r[0]), "=r"(r[1]), "=r"(r[2]), "=r"(r[3]) : "r"(addr));
}
__device__ __forceinline__ void mma16816(float* c, const uint32_t* a, const uint32_t* b) {
    asm volatile("mma.sync.aligned.m16n8k16.row.col.f32.bf16.bf16.f32 "
        "{%0,%1,%2,%3}, {%4,%5,%6,%7}, {%8,%9}, {%0,%1,%2,%3};"
        : "+f"(c[0]), "+f"(c[1]), "+f"(c[2]), "+f"(c[3])
        : "r"(a[0]), "r"(a[1]), "r"(a[2]), "r"(a[3]), "r"(b[0]), "r"(b[1]));
}
__device__ __forceinline__ void split2(float v0, float v1, uint32_t& H, uint32_t& L) {
    uint32_t u0 = __float_as_uint(v0), u1 = __float_as_uint(v1);
    H = __byte_perm(u0, u1, 0x7632);
    float l0 = v0 - __uint_as_float(u0 & 0xFFFF0000u);
    float l1 = v1 - __uint_as_float(u1 & 0xFFFF0000u);
    asm("cvt.rn.bf16x2.f32 %0, %1, %2;" : "=r"(L) : "f"(l1), "f"(l0));
}
__device__ __forceinline__ float fast_exp(float x) {
    float r;
    asm("ex2.approx.ftz.f32 %0, %1;" : "=f"(r) : "f"(x * 1.4426950408889634f));
    return r;
}

#define ST_BYTES 49152u
#define OFF_AL 8192u
#define OFF_BH 16384u
#define OFF_BL 32768u
#define GEMM_DYN (2 * 49152 + 1024)

__device__ __forceinline__ void load_chunk(uint32_t base, int tid, int m0, int n0, int k0,
    const uint16_t* Ah, const uint16_t* Al, int lda,
    const uint16_t* Bh, const uint16_t* Bl, int ldb)
{
#pragma unroll
    for (int half = 0; half < 2; half++) {
        int idx = half * 256 + tid;
        int row = idx >> 3, u = idx & 7;
        uint32_t off = SWZ((uint32_t)(row * 128 + u * 16));
        size_t ao = (size_t)(m0 + row) * lda + k0 + u * 8;
        CP16(base + off,          Ah + ao);
        CP16(base + OFF_AL + off, Al + ao);
    }
#pragma unroll
    for (int it = 0; it < 4; it++) {
        int idx = it * 256 + tid;
        int row = idx >> 3, u = idx & 7;
        uint32_t off = SWZ((uint32_t)(row * 128 + u * 16));
        size_t bo = (size_t)(n0 + row) * ldb + k0 + u * 8;
        CP16(base + OFF_BH + off, Bh + bo);
        CP16(base + OFF_BL + off, Bl + bo);
    }
}

// mode 0: fp32 C; mode 1: split bf16 C; mode 2: fused VAE; mode 3: combined ze|h
__global__ __launch_bounds__(256, 2)
void gemm_bf3(const uint16_t* __restrict__ Ah, const uint16_t* __restrict__ Al, int lda,
              const uint16_t* __restrict__ Bh, const uint16_t* __restrict__ Bl, int ldb,
              const float* __restrict__ bias,
              float* __restrict__ Cf, uint16_t* __restrict__ Ch, uint16_t* __restrict__ Cl,
              int ldc, int nOut, int K, int relu, int mode,
              const float* __restrict__ bias2, const float* __restrict__ eps,
              float* __restrict__ klq)
{
    extern __shared__ char smem[];
    const uint32_t tiles = (smem_to_u32(smem) + 1023) & ~1023u;
    const int tid = threadIdx.x, wid = tid >> 5, lane = tid & 31;
    const int m0 = blockIdx.y * 64, n0 = blockIdx.x * 128;
    const int wm = (wid >> 2) * 32, wn = (wid & 3) * 32;

    float acc[2][4][4];
#pragma unroll
    for (int i = 0; i < 2; i++)
#pragma unroll
        for (int j = 0; j < 4; j++)
#pragma unroll
            for (int q = 0; q < 4; q++) acc[i][j][q] = 0.f;

    const uint32_t aRowByte = (uint32_t)(wm + (lane & 15)) * 128u;
    const uint32_t aKoff    = (uint32_t)((lane >> 4) * 16);
    const uint32_t bRowByte = (uint32_t)(wn + (lane & 7) + ((lane >> 4) << 3)) * 128u;
    const uint32_t bKoff    = (uint32_t)(((lane >> 3) & 1) * 16);

    const int S = K / 64;
    load_chunk(tiles, tid, m0, n0, 0, Ah, Al, lda, Bh, Bl, ldb);
    CP_COMMIT();

    for (int s = 0; s < S; s++) {
        if (s + 1 < S) {
            load_chunk(tiles + ((s + 1) & 1) * ST_BYTES, tid, m0, n0, (s + 1) * 64,
                       Ah, Al, lda, Bh, Bl, ldb);
            CP_COMMIT();
            CP_WAIT1();
        } else {
            CP_WAIT0();
        }
        __syncthreads();

        const uint32_t pah = tiles + (s & 1) * ST_BYTES;
        const uint32_t pal = pah + OFF_AL, pbh = pah + OFF_BH, pbl = pah + OFF_BL;
#pragma unroll
        for (int kk = 0; kk < 4; kk++) {
            const uint32_t kb = (uint32_t)(kk * 32);
            uint32_t ah[2][4], al[2][4], bh[2][4], bl[2][4];
#pragma unroll
            for (int mt = 0; mt < 2; mt++) {
                uint32_t ro = SWZ(aRowByte + (uint32_t)(mt * 2048) + kb + aKoff);
                ldsm_x4(ah[mt], pah + ro);
                ldsm_x4(al[mt], pal + ro);
            }
#pragma unroll
            for (int nb = 0; nb < 2; nb++) {
                uint32_t ro = SWZ(bRowByte + (uint32_t)(nb * 2048) + kb + bKoff);
                ldsm_x4(bh[nb], pbh + ro);
                ldsm_x4(bl[nb], pbl + ro);
            }
#pragma unroll
            for (int t3 = 0; t3 < 3; t3++)
#pragma unroll
                for (int mt = 0; mt < 2; mt++)
#pragma unroll
                    for (int nt = 0; nt < 4; nt++) {
                        const uint32_t* ap = (t3 == 1) ? al[mt] : ah[mt];
                        const uint32_t* bp = (t3 == 2) ? &bl[nt >> 1][(nt & 1) * 2]
                                                       : &bh[nt >> 1][(nt & 1) * 2];
                        mma16816(acc[mt][nt], ap, bp);
                    }
        }
        __syncthreads();
    }

    // ---- epilogue ----
    int emode = mode;
    const float* eb = bias;
    int erelu = relu;
    int cbase = n0;
    int ldcEff = ldc;
    if (mode == 3) {
        if (n0 < 512) { emode = 0; }
        else { emode = 1; eb = bias2; erelu = 1; cbase = n0 - 512; ldcEff = VDIM; }
    }

    if (emode == 0) {
#pragma unroll
        for (int mt = 0; mt < 2; mt++) {
            const int r0 = m0 + wm + mt * 16 + (lane >> 2);
            float* crow0 = Cf + (size_t)r0 * ldcEff;
            float* crow8 = Cf + (size_t)(r0 + 8) * ldcEff;
#pragma unroll
            for (int nt = 0; nt < 4; nt++) {
                const int c = cbase + wn + nt * 8 + (lane & 3) * 2;
                if (c >= nOut) continue;
                float b0 = eb[c], b1 = eb[c + 1];
                float v0 = acc[mt][nt][0] + b0, v1 = acc[mt][nt][1] + b1;
                float v2 = acc[mt][nt][2] + b0, v3 = acc[mt][nt][3] + b1;
                if (erelu) {
                    v0 = fmaxf(v0, 0.f); v1 = fmaxf(v1, 0.f);
                    v2 = fmaxf(v2, 0.f); v3 = fmaxf(v3, 0.f);
                }
                *reinterpret_cast<float2*>(crow0 + c) = make_float2(v0, v1);
                *reinterpret_cast<float2*>(crow8 + c) = make_float2(v2, v3);
            }
        }
    } else if (emode == 1) {
#pragma unroll
        for (int mt = 0; mt < 2; mt++) {
            const int r0 = m0 + wm + mt * 16 + (lane >> 2);
#pragma unroll
            for (int nt = 0; nt < 4; nt++) {
                const int c = cbase + wn + nt * 8 + (lane & 3) * 2;
                float b0 = eb[c], b1 = eb[c + 1];
                float v0 = acc[mt][nt][0] + b0, v1 = acc[mt][nt][1] + b1;
                float v2 = acc[mt][nt][2] + b0, v3 = acc[mt][nt][3] + b1;
                if (erelu) {
                    v0 = fmaxf(v0, 0.f); v1 = fmaxf(v1, 0.f);
                    v2 = fmaxf(v2, 0.f); v3 = fmaxf(v3, 0.f);
                }
                uint32_t H, L;
                split2(v0, v1, H, L);
                *reinterpret_cast<uint32_t*>(Ch + (size_t)r0 * ldcEff + c) = H;
                *reinterpret_cast<uint32_t*>(Cl + (size_t)r0 * ldcEff + c) = L;
                split2(v2, v3, H, L);
                *reinterpret_cast<uint32_t*>(Ch + (size_t)(r0 + 8) * ldcEff + c) = H;
                *reinterpret_cast<uint32_t*>(Cl + (size_t)(r0 + 8) * ldcEff + c) = L;
            }
        }
    } else {
        float klsum = 0.f;
#pragma unroll
        for (int mt = 0; mt < 2; mt++) {
            const int r0 = m0 + wm + mt * 16 + (lane >> 2);
#pragma unroll
            for (int nt = 0; nt < 4; nt++) {
                const int c = n0 + wn + nt * 8 + (lane & 3) * 2;
                const int i = c >> 1;
                float bmu = bias[i], blv = bias[VDIM + i];
#pragma unroll
                for (int h = 0; h < 2; h++) {
                    const int r = r0 + h * 8;
                    float mu = acc[mt][nt][2 * h + 0] + bmu;
                    float lv = acc[mt][nt][2 * h + 1] + blv;
                    klsum += 0.5f * (fast_exp(lv) + mu * mu - 1.0f - lv);
                    float z = fmaf(fast_exp(0.5f * lv), eps[(size_t)r * VDIM + i], mu);
                    uint32_t uz = __float_as_uint(z);
                    float zl = z - __uint_as_float(uz & 0xFFFF0000u);
                    Ch[(size_t)r * ldc + i] = (uint16_t)(uz >> 16);
                    Cl[(size_t)r * ldc + i] = __bfloat16_as_ushort(__float2bfloat16(zl));
                }
            }
        }
        float* sred = reinterpret_cast<float*>(smem);
        sred[tid] = klsum;
        __syncthreads();
        for (int st = 128; st > 0; st >>= 1) {
            if (tid < st) sred[tid] += sred[tid + st];
            __syncthreads();
        }
        if (tid == 0) klq[blockIdx.y * gridDim.x + blockIdx.x] = sred[0];
    }
}

__global__ __launch_bounds__(128)
void sgemm64(const float* __restrict__ A, const float* __restrict__ G,
             const float* __restrict__ lb, float* __restrict__ C)
{
    __shared__ float As[16][64];
    __shared__ float Bs[16][64];
    const int tid = threadIdx.x;
    const int m0 = blockIdx.x * 64;
    const int tx = tid & 15, ty = tid >> 4;
    const int lrow = tid >> 1, lhalf = tid & 1;
    float acc[8][4];
#pragma unroll
    for (int i = 0; i < 8; i++)
#pragma unroll
        for (int j = 0; j < 4; j++) acc[i][j] = 0.f;

    for (int k0 = 0; k0 < IN_DIM; k0 += 16) {
#pragma unroll
        for (int h = 0; h < 2; h++) {
            int kk = lhalf * 8 + h * 4;
            float4 va = *reinterpret_cast<const float4*>(A + (size_t)(m0 + lrow) * IN_DIM + k0 + kk);
            As[kk + 0][lrow] = va.x; As[kk + 1][lrow] = va.y;
            As[kk + 2][lrow] = va.z; As[kk + 3][lrow] = va.w;
            float4 vb = make_float4(0.f, 0.f, 0.f, 0.f);
            if (lrow < KCLS)
                vb = *reinterpret_cast<const float4*>(G + (size_t)lrow * IN_DIM + k0 + kk);
            Bs[kk + 0][lrow] = vb.x; Bs[kk + 1][lrow] = vb.y;
            Bs[kk + 2][lrow] = vb.z; Bs[kk + 3][lrow] = vb.w;
        }
        __syncthreads();
#pragma unroll
        for (int k = 0; k < 16; k++) {
            float4 a0 = *reinterpret_cast<const float4*>(&As[k][ty * 4]);
            float4 a1 = *reinterpret_cast<const float4*>(&As[k][32 + ty * 4]);
            float4 b  = *reinterpret_cast<const float4*>(&Bs[k][tx * 4]);
            float a[8] = {a0.x, a0.y, a0.z, a0.w, a1.x, a1.y, a1.z, a1.w};
            float bb[4] = {b.x, b.y, b.z, b.w};
#pragma unroll
            for (int i = 0; i < 8; i++)
#pragma unroll
                for (int j = 0; j < 4; j++)
                    acc[i][j] = fmaf(a[i], bb[j], acc[i][j]);
        }
        __syncthreads();
    }
#pragma unroll
    for (int i = 0; i < 8; i++) {
        int row = m0 + ((i < 4) ? (ty * 4 + i) : (32 + ty * 4 + i - 4));
#pragma unroll
        for (int j = 0; j < 4; j++) {
            int col = tx * 4 + j;
            if (col < KCLS) C[(size_t)row * KCLS + col] = acc[i][j] + lb[col];
        }
    }
}

__global__ void split_mat(const float* __restrict__ src, uint32_t* __restrict__ dh,
                          uint32_t* __restrict__ dl, long nPairs, long srcPairs)
{
    long i = (long)blockIdx.x * blockDim.x + threadIdx.x;
    if (i >= nPairs) return;
    float v0 = 0.f, v1 = 0.f;
    if (i < srcPairs) {
        float2 v = reinterpret_cast<const float2*>(src)[i];
        v0 = v.x; v1 = v.y;
    }
    uint32_t H, L;
    split2(v0, v1, H, L);
    dh[i] = H; dl[i] = L;
}

__global__ void split_w2(const float* __restrict__ W2)
{
    int i = blockIdx.x * blockDim.x + threadIdx.x;
    const int ppr = VDIM / 2;
    if (i >= 2 * VDIM * ppr) return;
    int rr = i / ppr, p = i - rr * ppr;
    int orig = (rr & 1) ? (VDIM + (rr >> 1)) : (rr >> 1);
    float2 v = *reinterpret_cast<const float2*>(W2 + (size_t)orig * VDIM + 2 * p);
    uint32_t H, L;
    split2(v.x, v.y, H, L);
    g_w2h[i] = H; g_w2l[i] = L;
}

__global__ void split_wd(const float* __restrict__ Wd)
{
    int i = blockIdx.x * blockDim.x + threadIdx.x;
    const int ppr = CAT_LD / 2;
    if (i >= IN_DIM * ppr) return;
    int r = i / ppr, p = i - r * ppr;
    int c0 = 2 * p;
    float v0 = (c0 < CAT_RAW) ? Wd[(size_t)r * CAT_RAW + c0] : 0.f;
    float v1 = (c0 + 1 < CAT_RAW) ? Wd[(size_t)r * CAT_RAW + c0 + 1] : 0.f;
    uint32_t H, L;
    split2(v0, v1, H, L);
    g_wdh[i] = H; g_wdl[i] = L;
}

__global__ void build_G(const float* __restrict__ W_enc, const float* __restrict__ cb)
{
    int c = blockIdx.x;
    int i = blockIdx.y * 128 + threadIdx.x;
    float s = 0.f;
#pragma unroll 4
    for (int d = 0; d < ENC_DIM; d++)
        s = fmaf(cb[c * ENC_DIM + d], W_enc[(size_t)d * IN_DIM + i], s);
    g_G[(size_t)c * IN_DIM + i] = s;
}
__global__ void build_lb(const float* __restrict__ b_enc, const float* __restrict__ cb)
{
    int c = blockIdx.x;
    int t = threadIdx.x;
    float s = 0.f;
    for (int d = t; d < ENC_DIM; d += 128) s = fmaf(b_enc[d], cb[c * ENC_DIM + d], s);
    __shared__ float sm[128];
    sm[t] = s;
    __syncthreads();
    for (int st = 64; st > 0; st >>= 1) { if (t < st) sm[t] += sm[t + st]; __syncthreads(); }
    if (t == 0) g_lb[c] = sm[0];
}

__global__ void detect_mask_kernel(const unsigned int* __restrict__ w)
{
    __shared__ int s_int, s_flt;
    if (threadIdx.x == 0) { s_int = 1; s_flt = 1; }
    __syncthreads();
    int li = 1, lf = 1;
    for (int i = threadIdx.x; i < 4096; i += blockDim.x) {
        unsigned v = w[i];
        if (v > 1u) li = 0;
        if (v != 0u && v != 0x3F800000u) lf = 0;
    }
    if (!li) atomicAnd(&s_int, 0);
    if (!lf) atomicAnd(&s_flt, 0);
    __syncthreads();
    if (threadIdx.x == 0) g_mask_mode = s_int ? 1 : (s_flt ? 2 : 0);
}

__global__ void argmax_y_kernel(const float* __restrict__ logits,
                                const void* __restrict__ mask,
                                const int* __restrict__ labels,
                                const float* __restrict__ codebook,
                                float* __restrict__ zq)
{
    const int b = blockIdx.x;
    const int lane = threadIdx.x;
    const float NEG = __int_as_float(0xff800000u);
    const float* lr = logits + (size_t)b * KCLS;
    const int k0 = 2 * lane, k1 = 2 * lane + 1;
    float va = (k0 < KCLS) ? lr[k0] : NEG;
    float vb = (k1 < KCLS) ? lr[k1] : NEG;
    float m; int mi;
    if (va >= vb) { m = va; mi = k0; } else { m = vb; mi = k1; }
#pragma unroll
    for (int off = 16; off > 0; off >>= 1) {
        float om = __shfl_xor_sync(0xffffffffu, m, off);
        int oi = __shfl_xor_sync(0xffffffffu, mi, off);
        if (om > m || (om == m && oi < mi)) { m = om; mi = oi; }
    }
    float ea = (k0 < KCLS) ? expf(va - m) : 0.f;
    float eb = (k1 < KCLS) ? expf(vb - m) : 0.f;
    float s = ea + eb;
#pragma unroll
    for (int off = 16; off > 0; off >>= 1) s += __shfl_xor_sync(0xffffffffu, s, off);
    float inv = 1.0f / s;

    int mode = g_mask_mode;
    bool known;
    if (mode == 1)      known = ((const int*)mask)[b] != 0;
    else if (mode == 2) known = ((const float*)mask)[b] != 0.f;
    else                known = ((const unsigned char*)mask)[b] != 0;
    int lab = labels[b];

    float y0 = (k0 < KCLS) ? (known ? (k0 == lab ? 1.f : 0.f) : ea * inv) : 0.f;
    float y1 = (k1 < KCLS) ? (known ? (k1 == lab ? 1.f : 0.f) : eb * inv) : 0.f;
    uint32_t H, L;
    split2(y0, y1, H, L);
    const size_t pi = (size_t)b * (CAT_LD / 2) + (VDIM / 2) + lane;
    g_cath[pi] = H; g_catl[pi] = L;

    const float* cr = codebook + (size_t)mi * ENC_DIM;
    float* zr = zq + (size_t)b * ENC_DIM;
    for (int i = lane; i < ENC_DIM; i += 32) zr[i] = cr[i];
}

__global__ void kl_reduce_kernel(float* __restrict__ out, int n)
{
    const int t = threadIdx.x;
    float s = 0.f;
    for (int i = t; i < n; i += 256) s += g_klq[i];
    __shared__ float sm[256];
    sm[t] = s;
    __syncthreads();
    for (int st = 128; st > 0; st >>= 1) { if (t < st) sm[t] += sm[t + st]; __syncthreads(); }
    if (t == 0) *out = sm[0] / (float)B_ROWS;
}

static void launch_gemm(const void* Ah, const void* Al, int lda,
                        const void* Bh, const void* Bl, int ldb,
                        const float* bias, float* Cf, void* Ch, void* Cl,
                        int ldc, int nPad, int nOut, int K, int relu, int mode,
                        const float* bias2, const float* eps, float* klq)
{
    cudaFuncSetAttribute(gemm_bf3, cudaFuncAttributeMaxDynamicSharedMemorySize, GEMM_DYN);
    dim3 grid(nPad / 128, B_ROWS / 64);
    gemm_bf3<<<grid, 256, GEMM_DYN>>>(
        (const uint16_t*)Ah, (const uint16_t*)Al, lda,
        (const uint16_t*)Bh, (const uint16_t*)Bl, ldb,
        bias, Cf, (uint16_t*)Ch, (uint16_t*)Cl, ldc, nOut, K, relu, mode,
        bias2, eps, klq);
}

extern "C" void kernel_launch(void* const* d_in, const int* in_sizes, int n_in,
                              void* d_out, int out_size)
{
    const float* x        = (const float*)d_in[0];
    const void*  mask     = d_in[1];
    const int*   labels   = (const int*)d_in[2];
    const float* eps      = (const float*)d_in[3];
    const float* W_enc    = (const float*)d_in[4];
    const float* b_enc    = (const float*)d_in[5];
    const float* codebook = (const float*)d_in[6];
    const float* W1       = (const float*)d_in[7];
    const float* b1       = (const float*)d_in[8];
    const float* W2       = (const float*)d_in[9];
    const float* b2       = (const float*)d_in[10];
    const float* Wd       = (const float*)d_in[11];
    const float* bd       = (const float*)d_in[12];
    float* out = (float*)d_out;

    void *p_xh, *p_xl, *p_wch, *p_wcl, *p_w2h, *p_w2l, *p_wdh, *p_wdl;
    void *p_hh, *p_hl, *p_cath, *p_catl;
    float *p_G, *p_lb, *p_klq, *p_ze, *p_zq, *p_lg, *p_kl;
    cudaGetSymbolAddress(&p_xh, g_xh);   cudaGetSymbolAddress(&p_xl, g_xl);
    cudaGetSymbolAddress(&p_wch, g_wch); cudaGetSymbolAddress(&p_wcl, g_wcl);
    cudaGetSymbolAddress(&p_w2h, g_w2h); cudaGetSymbolAddress(&p_w2l, g_w2l);
    cudaGetSymbolAddress(&p_wdh, g_wdh); cudaGetSymbolAddress(&p_wdl, g_wdl);
    cudaGetSymbolAddress(&p_hh, g_hh);   cudaGetSymbolAddress(&p_hl, g_hl);
    cudaGetSymbolAddress(&p_cath, g_cath); cudaGetSymbolAddress(&p_catl, g_catl);
    cudaGetSymbolAddress((void**)&p_G,  g_G);
    cudaGetSymbolAddress((void**)&p_lb, g_lb);
    cudaGetSymbolAddress((void**)&p_klq, g_klq);
    cudaGetSymbolAddress((void**)&p_ze, g_ze_s);
    cudaGetSymbolAddress((void**)&p_zq, g_zq_s);
    cudaGetSymbolAddress((void**)&p_lg, g_lg_s);
    cudaGetSymbolAddress((void**)&p_kl, g_kl_s);

    const size_t full_elems = (size_t)B_ROWS * (IN_DIM + ENC_DIM + ENC_DIM + KCLS) + 1;
    const bool full = ((size_t)out_size >= full_elems);
    float* xt = out;
    float* ze = full ? out + (size_t)B_ROWS * IN_DIM : p_ze;
    float* zq = full ? ze + (size_t)B_ROWS * ENC_DIM : p_zq;
    float* lg = full ? zq + (size_t)B_ROWS * ENC_DIM : p_lg;
    float* kl = full ? lg + (size_t)B_ROWS * KCLS    : p_kl;

    {
        long np = (long)B_ROWS * IN_DIM / 2;
        split_mat<<<(unsigned)((np + 255) / 256), 256>>>(x, (uint32_t*)p_xh, (uint32_t*)p_xl, np, np);
        long wep = (long)512 * IN_DIM / 2, wes = (long)ENC_DIM * IN_DIM / 2;
        split_mat<<<(unsigned)((wep + 255) / 256), 256>>>(W_enc, (uint32_t*)p_wch, (uint32_t*)p_wcl, wep, wes);
        long w1p = (long)VDIM * IN_DIM / 2;
        split_mat<<<(unsigned)((w1p + 255) / 256), 256>>>(W1,
            (uint32_t*)p_wch + (size_t)512 * IN_DIM / 2,
            (uint32_t*)p_wcl + (size_t)512 * IN_DIM / 2, w1p, w1p);
        split_w2<<<(2 * VDIM * (VDIM / 2) + 255) / 256, 256>>>(W2);
        split_wd<<<(IN_DIM * (CAT_LD / 2) + 255) / 256, 256>>>(Wd);
    }
    detect_mask_kernel<<<1, 256>>>((const unsigned int*)mask);
    build_G<<<dim3(KCLS, IN_DIM / 128), 128>>>(W_enc, codebook);
    build_lb<<<KCLS, 128>>>(b_enc, codebook);

    sgemm64<<<B_ROWS / 64, 128>>>(x, p_G, p_lb, lg);

    // combined ze|h (mode 3)
    launch_gemm(p_xh, p_xl, IN_DIM, p_wch, p_wcl, IN_DIM, b_enc,
                ze, p_hh, p_hl, ENC_DIM, NCOMB, ENC_DIM, IN_DIM, 0, 3,
                b1, nullptr, nullptr);
    // ml + fused VAE (mode 2)
    launch_gemm(p_hh, p_hl, VDIM, p_w2h, p_w2l, VDIM, b2,
                nullptr, p_cath, p_catl, CAT_LD / 2 * 2, 2 * VDIM, 2 * VDIM, VDIM, 0, 2,
                nullptr, eps, p_klq);

    argmax_y_kernel<<<B_ROWS, 32>>>(lg, mask, labels, codebook, zq);
    kl_reduce_kernel<<<1, 256>>>(kl, (2 * VDIM / 128) * (B_ROWS / 64));

    // decoder
    launch_gemm(p_cath, p_catl, CAT_LD, p_wdh, p_wdl, CAT_LD, bd,
                xt, nullptr, nullptr, IN_DIM, IN_DIM, IN_DIM, CAT_LD, 0, 0,
                nullptr, nullptr, nullptr);
}

// round 13
// speedup vs baseline: 2.1865x; 1.1084x over previous
#include <cuda_runtime.h>
#include <cuda_fp16.h>
#include <math.h>
#include <stdint.h>

#define B_ROWS 16384
#define IN_DIM 768
#define ENC_DIM 500
#define KCLS 43
#define VDIM 1024
#define CAT_RAW 1067
#define CAT_LD  1088
#define NCOMB 1536

__device__ uint32_t g_xh [(size_t)B_ROWS * IN_DIM / 2];
__device__ uint32_t g_xl [(size_t)B_ROWS * IN_DIM / 2];
__device__ uint32_t g_wch[(size_t)NCOMB * IN_DIM / 2];
__device__ uint32_t g_wcl[(size_t)NCOMB * IN_DIM / 2];
__device__ uint32_t g_w2h[(size_t)2 * VDIM * VDIM / 2];
__device__ uint32_t g_w2l[(size_t)2 * VDIM * VDIM / 2];
__device__ uint32_t g_wdh[(size_t)IN_DIM * CAT_LD / 2];
__device__ uint32_t g_wdl[(size_t)IN_DIM * CAT_LD / 2];
__device__ uint32_t g_hh [(size_t)B_ROWS * VDIM / 2];
__device__ uint32_t g_hl [(size_t)B_ROWS * VDIM / 2];
__device__ uint32_t g_cath[(size_t)B_ROWS * CAT_LD / 2];
__device__ uint32_t g_catl[(size_t)B_ROWS * CAT_LD / 2];
__device__ float g_G  [(size_t)KCLS * IN_DIM];
__device__ float g_lb [KCLS];
__device__ float g_klq[4096];
__device__ float g_ze_s[(size_t)B_ROWS * ENC_DIM];
__device__ float g_zq_s[(size_t)B_ROWS * ENC_DIM];
__device__ float g_lg_s[(size_t)B_ROWS * KCLS];
__device__ float g_kl_s[1];
__device__ int   g_mask_mode;

__device__ __forceinline__ uint32_t smem_to_u32(const void* p) {
    uint32_t a;
    asm("{ .reg .u64 t; cvta.to.shared.u64 t, %1; cvt.u32.u64 %0, t; }" : "=r"(a) : "l"(p));
    return a;
}
#define SWZ(b) ((b) ^ (((b) >> 3) & 0x70))
#define CP16(d, s)  asm volatile("cp.async.cg.shared.global [%0], [%1], 16;" :: "r"(d), "l"(s) : "memory")
#define CP_COMMIT() asm volatile("cp.async.commit_group;" ::: "memory")
#define CP_WAIT0()  asm volatile("cp.async.wait_group 0;" ::: "memory")
#define CP_WAIT1()  asm volatile("cp.async.wait_group 1;" ::: "memory")

__device__ __forceinline__ void ldsm_x4(uint32_t* r, uint32_t addr) {
    asm volatile("ldmatrix.sync.aligned.m8n8.x4.shared.b16 {%0,%1,%2,%3}, [%4];"
        : "=r"(r[0]), "=r"(r[1]), "=r"(r[2]), "=r"(r[3]) : "r"(addr));
}
__device__ __forceinline__ void mma_f16(float* c, const uint32_t* a, const uint32_t* b) {
    asm volatile("mma.sync.aligned.m16n8k16.row.col.f32.f16.f16.f32 "
        "{%0,%1,%2,%3}, {%4,%5,%6,%7}, {%8,%9}, {%0,%1,%2,%3};"
        : "+f"(c[0]), "+f"(c[1]), "+f"(c[2]), "+f"(c[3])
        : "r"(a[0]), "r"(a[1]), "r"(a[2]), "r"(a[3]), "r"(b[0]), "r"(b[1]));
}
// fp16 round-to-nearest hi/lo split of two fp32 values
__device__ __forceinline__ void split2(float v0, float v1, uint32_t& H, uint32_t& L) {
    __half h0 = __float2half_rn(v0), h1 = __float2half_rn(v1);
    float r0 = v0 - __half2float(h0), r1 = v1 - __half2float(h1);
    __half l0 = __float2half_rn(r0), l1 = __float2half_rn(r1);
    __half2 hp = __halves2half2(h0, h1), lp = __halves2half2(l0, l1);
    H = *reinterpret_cast<uint32_t*>(&hp);
    L = *reinterpret_cast<uint32_t*>(&lp);
}
__device__ __forceinline__ float fast_exp(float x) {
    float r;
    asm("ex2.approx.ftz.f32 %0, %1;" : "=f"(r) : "f"(x * 1.4426950408889634f));
    return r;
}

#define ST_BYTES 49152u
#define OFF_AL 8192u
#define OFF_BH 16384u
#define OFF_BL 32768u
#define GEMM_DYN (2 * 49152 + 1024)

__device__ __forceinline__ void load_chunk(uint32_t base, int tid, int m0, int n0, int k0,
    const uint16_t* Ah, const uint16_t* Al, int lda,
    const uint16_t* Bh, const uint16_t* Bl, int ldb)
{
#pragma unroll
    for (int half = 0; half < 2; half++) {
        int idx = half * 256 + tid;
        int row = idx >> 3, u = idx & 7;
        uint32_t off = SWZ((uint32_t)(row * 128 + u * 16));
        size_t ao = (size_t)(m0 + row) * lda + k0 + u * 8;
        CP16(base + off,          Ah + ao);
        CP16(base + OFF_AL + off, Al + ao);
    }
#pragma unroll
    for (int it = 0; it < 4; it++) {
        int idx = it * 256 + tid;
        int row = idx >> 3, u = idx & 7;
        uint32_t off = SWZ((uint32_t)(row * 128 + u * 16));
        size_t bo = (size_t)(n0 + row) * ldb + k0 + u * 8;
        CP16(base + OFF_BH + off, Bh + bo);
        CP16(base + OFF_BL + off, Bl + bo);
    }
}

// PASSES=3: Ah*Bh + Al*Bh + Ah*Bl. PASSES=2: Ah*Bh + Al*Bh (= A*Bh).
// mode 0: fp32 C; mode 1: split fp16 C; mode 2: fused VAE; mode 3: combined ze|h
template<int PASSES>
__global__ __launch_bounds__(256, 2)
void gemm_f16x(const uint16_t* __restrict__ Ah, const uint16_t* __restrict__ Al, int lda,
               const uint16_t* __restrict__ Bh, const uint16_t* __restrict__ Bl, int ldb,
               const float* __restrict__ bias,
               float* __restrict__ Cf, uint16_t* __restrict__ Ch, uint16_t* __restrict__ Cl,
               int ldc, int nOut, int K, int relu, int mode,
               const float* __restrict__ bias2, const float* __restrict__ eps,
               float* __restrict__ klq)
{
    extern __shared__ char smem[];
    const uint32_t tiles = (smem_to_u32(smem) + 1023) & ~1023u;
    const int tid = threadIdx.x, wid = tid >> 5, lane = tid & 31;
    const int m0 = blockIdx.y * 64, n0 = blockIdx.x * 128;
    const int wm = (wid >> 2) * 32, wn = (wid & 3) * 32;

    float acc[2][4][4];
#pragma unroll
    for (int i = 0; i < 2; i++)
#pragma unroll
        for (int j = 0; j < 4; j++)
#pragma unroll
            for (int q = 0; q < 4; q++) acc[i][j][q] = 0.f;

    const uint32_t aRowByte = (uint32_t)(wm + (lane & 15)) * 128u;
    const uint32_t aKoff    = (uint32_t)((lane >> 4) * 16);
    const uint32_t bRowByte = (uint32_t)(wn + (lane & 7) + ((lane >> 4) << 3)) * 128u;
    const uint32_t bKoff    = (uint32_t)(((lane >> 3) & 1) * 16);

    const int S = K / 64;
    load_chunk(tiles, tid, m0, n0, 0, Ah, Al, lda, Bh, Bl, ldb);
    CP_COMMIT();

    for (int s = 0; s < S; s++) {
        if (s + 1 < S) {
            load_chunk(tiles + ((s + 1) & 1) * ST_BYTES, tid, m0, n0, (s + 1) * 64,
                       Ah, Al, lda, Bh, Bl, ldb);
            CP_COMMIT();
            CP_WAIT1();
        } else {
            CP_WAIT0();
        }
        __syncthreads();

        const uint32_t pah = tiles + (s & 1) * ST_BYTES;
        const uint32_t pal = pah + OFF_AL, pbh = pah + OFF_BH, pbl = pah + OFF_BL;
#pragma unroll
        for (int kk = 0; kk < 4; kk++) {
            const uint32_t kb = (uint32_t)(kk * 32);
            uint32_t ah[2][4], al[2][4], bh[2][4], bl[2][4];
#pragma unroll
            for (int mt = 0; mt < 2; mt++) {
                uint32_t ro = SWZ(aRowByte + (uint32_t)(mt * 2048) + kb + aKoff);
                ldsm_x4(ah[mt], pah + ro);
                ldsm_x4(al[mt], pal + ro);
            }
#pragma unroll
            for (int nb = 0; nb < 2; nb++) {
                uint32_t ro = SWZ(bRowByte + (uint32_t)(nb * 2048) + kb + bKoff);
                ldsm_x4(bh[nb], pbh + ro);
                if (PASSES == 3) ldsm_x4(bl[nb], pbl + ro);
            }
#pragma unroll
            for (int t3 = 0; t3 < PASSES; t3++)
#pragma unroll
                for (int mt = 0; mt < 2; mt++)
#pragma unroll
                    for (int nt = 0; nt < 4; nt++) {
                        const uint32_t* ap = (t3 == 1) ? al[mt] : ah[mt];
                        const uint32_t* bp = (t3 == 2) ? &bl[nt >> 1][(nt & 1) * 2]
                                                       : &bh[nt >> 1][(nt & 1) * 2];
                        mma_f16(acc[mt][nt], ap, bp);
                    }
        }
        __syncthreads();
    }

    // ---- epilogue ----
    int emode = mode;
    const float* eb = bias;
    int erelu = relu;
    int cbase = n0;
    int ldcEff = ldc;
    if (mode == 3) {
        if (n0 < 512) { emode = 0; }
        else { emode = 1; eb = bias2; erelu = 1; cbase = n0 - 512; ldcEff = VDIM; }
    }

    if (emode == 0) {
#pragma unroll
        for (int mt = 0; mt < 2; mt++) {
            const int r0 = m0 + wm + mt * 16 + (lane >> 2);
            float* crow0 = Cf + (size_t)r0 * ldcEff;
            float* crow8 = Cf + (size_t)(r0 + 8) * ldcEff;
#pragma unroll
            for (int nt = 0; nt < 4; nt++) {
                const int c = cbase + wn + nt * 8 + (lane & 3) * 2;
                if (c >= nOut) continue;
                float b0 = eb[c], b1 = eb[c + 1];
                float v0 = acc[mt][nt][0] + b0, v1 = acc[mt][nt][1] + b1;
                float v2 = acc[mt][nt][2] + b0, v3 = acc[mt][nt][3] + b1;
                if (erelu) {
                    v0 = fmaxf(v0, 0.f); v1 = fmaxf(v1, 0.f);
                    v2 = fmaxf(v2, 0.f); v3 = fmaxf(v3, 0.f);
                }
                *reinterpret_cast<float2*>(crow0 + c) = make_float2(v0, v1);
                *reinterpret_cast<float2*>(crow8 + c) = make_float2(v2, v3);
            }
        }
    } else if (emode == 1) {
#pragma unroll
        for (int mt = 0; mt < 2; mt++) {
            const int r0 = m0 + wm + mt * 16 + (lane >> 2);
#pragma unroll
            for (int nt = 0; nt < 4; nt++) {
                const int c = cbase + wn + nt * 8 + (lane & 3) * 2;
                float b0 = eb[c], b1 = eb[c + 1];
                float v0 = acc[mt][nt][0] + b0, v1 = acc[mt][nt][1] + b1;
                float v2 = acc[mt][nt][2] + b0, v3 = acc[mt][nt][3] + b1;
                if (erelu) {
                    v0 = fmaxf(v0, 0.f); v1 = fmaxf(v1, 0.f);
                    v2 = fmaxf(v2, 0.f); v3 = fmaxf(v3, 0.f);
                }
                uint32_t H, L;
                split2(v0, v1, H, L);
                *reinterpret_cast<uint32_t*>(Ch + (size_t)r0 * ldcEff + c) = H;
                *reinterpret_cast<uint32_t*>(Cl + (size_t)r0 * ldcEff + c) = L;
                split2(v2, v3, H, L);
                *reinterpret_cast<uint32_t*>(Ch + (size_t)(r0 + 8) * ldcEff + c) = H;
                *reinterpret_cast<uint32_t*>(Cl + (size_t)(r0 + 8) * ldcEff + c) = L;
            }
        }
    } else {
        float klsum = 0.f;
#pragma unroll
        for (int mt = 0; mt < 2; mt++) {
            const int r0 = m0 + wm + mt * 16 + (lane >> 2);
#pragma unroll
            for (int nt = 0; nt < 4; nt++) {
                const int c = n0 + wn + nt * 8 + (lane & 3) * 2;
                const int i = c >> 1;
                float bmu = bias[i], blv = bias[VDIM + i];
#pragma unroll
                for (int h = 0; h < 2; h++) {
                    const int r = r0 + h * 8;
                    float mu = acc[mt][nt][2 * h + 0] + bmu;
                    float lv = acc[mt][nt][2 * h + 1] + blv;
                    klsum += 0.5f * (fast_exp(lv) + mu * mu - 1.0f - lv);
                    float z = fmaf(fast_exp(0.5f * lv), eps[(size_t)r * VDIM + i], mu);
                    __half zh = __float2half_rn(z);
                    __half zl = __float2half_rn(z - __half2float(zh));
                    Ch[(size_t)r * ldc + i] = *reinterpret_cast<uint16_t*>(&zh);
                    Cl[(size_t)r * ldc + i] = *reinterpret_cast<uint16_t*>(&zl);
                }
            }
        }
        float* sred = reinterpret_cast<float*>(smem);
        sred[tid] = klsum;
        __syncthreads();
        for (int st = 128; st > 0; st >>= 1) {
            if (tid < st) sred[tid] += sred[tid + st];
            __syncthreads();
        }
        if (tid == 0) klq[blockIdx.y * gridDim.x + blockIdx.x] = sred[0];
    }
}

__global__ __launch_bounds__(128)
void sgemm64(const float* __restrict__ A, const float* __restrict__ G,
             const float* __restrict__ lb, float* __restrict__ C)
{
    __shared__ float As[16][64];
    __shared__ float Bs[16][64];
    const int tid = threadIdx.x;
    const int m0 = blockIdx.x * 64;
    const int tx = tid & 15, ty = tid >> 4;
    const int lrow = tid >> 1, lhalf = tid & 1;
    float acc[8][4];
#pragma unroll
    for (int i = 0; i < 8; i++)
#pragma unroll
        for (int j = 0; j < 4; j++) acc[i][j] = 0.f;

    for (int k0 = 0; k0 < IN_DIM; k0 += 16) {
#pragma unroll
        for (int h = 0; h < 2; h++) {
            int kk = lhalf * 8 + h * 4;
            float4 va = *reinterpret_cast<const float4*>(A + (size_t)(m0 + lrow) * IN_DIM + k0 + kk);
            As[kk + 0][lrow] = va.x; As[kk + 1][lrow] = va.y;
            As[kk + 2][lrow] = va.z; As[kk + 3][lrow] = va.w;
            float4 vb = make_float4(0.f, 0.f, 0.f, 0.f);
            if (lrow < KCLS)
                vb = *reinterpret_cast<const float4*>(G + (size_t)lrow * IN_DIM + k0 + kk);
            Bs[kk + 0][lrow] = vb.x; Bs[kk + 1][lrow] = vb.y;
            Bs[kk + 2][lrow] = vb.z; Bs[kk + 3][lrow] = vb.w;
        }
        __syncthreads();
#pragma unroll
        for (int k = 0; k < 16; k++) {
            float4 a0 = *reinterpret_cast<const float4*>(&As[k][ty * 4]);
            float4 a1 = *reinterpret_cast<const float4*>(&As[k][32 + ty * 4]);
            float4 b  = *reinterpret_cast<const float4*>(&Bs[k][tx * 4]);
            float a[8] = {a0.x, a0.y, a0.z, a0.w, a1.x, a1.y, a1.z, a1.w};
            float bb[4] = {b.x, b.y, b.z, b.w};
#pragma unroll
            for (int i = 0; i < 8; i++)
#pragma unroll
                for (int j = 0; j < 4; j++)
                    acc[i][j] = fmaf(a[i], bb[j], acc[i][j]);
        }
        __syncthreads();
    }
#pragma unroll
    for (int i = 0; i < 8; i++) {
        int row = m0 + ((i < 4) ? (ty * 4 + i) : (32 + ty * 4 + i - 4));
#pragma unroll
        for (int j = 0; j < 4; j++) {
            int col = tx * 4 + j;
            if (col < KCLS) C[(size_t)row * KCLS + col] = acc[i][j] + lb[col];
        }
    }
}

__global__ void split_mat(const float* __restrict__ src, uint32_t* __restrict__ dh,
                          uint32_t* __restrict__ dl, long nPairs, long srcPairs)
{
    long i = (long)blockIdx.x * blockDim.x + threadIdx.x;
    if (i >= nPairs) return;
    float v0 = 0.f, v1 = 0.f;
    if (i < srcPairs) {
        float2 v = reinterpret_cast<const float2*>(src)[i];
        v0 = v.x; v1 = v.y;
    }
    uint32_t H, L;
    split2(v0, v1, H, L);
    dh[i] = H; dl[i] = L;
}

__global__ void split_w2(const float* __restrict__ W2)
{
    int i = blockIdx.x * blockDim.x + threadIdx.x;
    const int ppr = VDIM / 2;
    if (i >= 2 * VDIM * ppr) return;
    int rr = i / ppr, p = i - rr * ppr;
    int orig = (rr & 1) ? (VDIM + (rr >> 1)) : (rr >> 1);
    float2 v = *reinterpret_cast<const float2*>(W2 + (size_t)orig * VDIM + 2 * p);
    uint32_t H, L;
    split2(v.x, v.y, H, L);
    g_w2h[i] = H; g_w2l[i] = L;
}

__global__ void split_wd(const float* __restrict__ Wd)
{
    int i = blockIdx.x * blockDim.x + threadIdx.x;
    const int ppr = CAT_LD / 2;
    if (i >= IN_DIM * ppr) return;
    int r = i / ppr, p = i - r * ppr;
    int c0 = 2 * p;
    float v0 = (c0 < CAT_RAW) ? Wd[(size_t)r * CAT_RAW + c0] : 0.f;
    float v1 = (c0 + 1 < CAT_RAW) ? Wd[(size_t)r * CAT_RAW + c0 + 1] : 0.f;
    uint32_t H, L;
    split2(v0, v1, H, L);
    g_wdh[i] = H; g_wdl[i] = L;
}

__global__ void build_G(const float* __restrict__ W_enc, const float* __restrict__ cb)
{
    int c = blockIdx.x;
    int i = blockIdx.y * 128 + threadIdx.x;
    float s = 0.f;
#pragma unroll 4
    for (int d = 0; d < ENC_DIM; d++)
        s = fmaf(cb[c * ENC_DIM + d], W_enc[(size_t)d * IN_DIM + i], s);
    g_G[(size_t)c * IN_DIM + i] = s;
}
__global__ void build_lb(const float* __restrict__ b_enc, const float* __restrict__ cb)
{
    int c = blockIdx.x;
    int t = threadIdx.x;
    float s = 0.f;
    for (int d = t; d < ENC_DIM; d += 128) s = fmaf(b_enc[d], cb[c * ENC_DIM + d], s);
    __shared__ float sm[128];
    sm[t] = s;
    __syncthreads();
    for (int st = 64; st > 0; st >>= 1) { if (t < st) sm[t] += sm[t + st]; __syncthreads(); }
    if (t == 0) g_lb[c] = sm[0];
}

__global__ void detect_mask_kernel(const unsigned int* __restrict__ w)
{
    __shared__ int s_int, s_flt;
    if (threadIdx.x == 0) { s_int = 1; s_flt = 1; }
    __syncthreads();
    int li = 1, lf = 1;
    for (int i = threadIdx.x; i < 4096; i += blockDim.x) {
        unsigned v = w[i];
        if (v > 1u) li = 0;
        if (v != 0u && v != 0x3F800000u) lf = 0;
    }
    if (!li) atomicAnd(&s_int, 0);
    if (!lf) atomicAnd(&s_flt, 0);
    __syncthreads();
    if (threadIdx.x == 0) g_mask_mode = s_int ? 1 : (s_flt ? 2 : 0);
}

__global__ void argmax_y_kernel(const float* __restrict__ logits,
                                const void* __restrict__ mask,
                                const int* __restrict__ labels,
                                const float* __restrict__ codebook,
                                float* __restrict__ zq)
{
    const int b = blockIdx.x;
    const int lane = threadIdx.x;
    const float NEG = __int_as_float(0xff800000u);
    const float* lr = logits + (size_t)b * KCLS;
    const int k0 = 2 * lane, k1 = 2 * lane + 1;
    float va = (k0 < KCLS) ? lr[k0] : NEG;
    float vb = (k1 < KCLS) ? lr[k1] : NEG;
    float m; int mi;
    if (va >= vb) { m = va; mi = k0; } else { m = vb; mi = k1; }
#pragma unroll
    for (int off = 16; off > 0; off >>= 1) {
        float om = __shfl_xor_sync(0xffffffffu, m, off);
        int oi = __shfl_xor_sync(0xffffffffu, mi, off);
        if (om > m || (om == m && oi < mi)) { m = om; mi = oi; }
    }
    float ea = (k0 < KCLS) ? expf(va - m) : 0.f;
    float eb = (k1 < KCLS) ? expf(vb - m) : 0.f;
    float s = ea + eb;
#pragma unroll
    for (int off = 16; off > 0; off >>= 1) s += __shfl_xor_sync(0xffffffffu, s, off);
    float inv = 1.0f / s;

    int mode = g_mask_mode;
    bool known;
    if (mode == 1)      known = ((const int*)mask)[b] != 0;
    else if (mode == 2) known = ((const float*)mask)[b] != 0.f;
    else                known = ((const unsigned char*)mask)[b] != 0;
    int lab = labels[b];

    float y0 = (k0 < KCLS) ? (known ? (k0 == lab ? 1.f : 0.f) : ea * inv) : 0.f;
    float y1 = (k1 < KCLS) ? (known ? (k1 == lab ? 1.f : 0.f) : eb * inv) : 0.f;
    uint32_t H, L;
    split2(y0, y1, H, L);
    const size_t pi = (size_t)b * (CAT_LD / 2) + (VDIM / 2) + lane;
    g_cath[pi] = H; g_catl[pi] = L;

    const float* cr = codebook + (size_t)mi * ENC_DIM;
    float* zr = zq + (size_t)b * ENC_DIM;
    for (int i = lane; i < ENC_DIM; i += 32) zr[i] = cr[i];
}

__global__ void kl_reduce_kernel(float* __restrict__ out, int n)
{
    const int t = threadIdx.x;
    float s = 0.f;
    for (int i = t; i < n; i += 256) s += g_klq[i];
    __shared__ float sm[256];
    sm[t] = s;
    __syncthreads();
    for (int st = 128; st > 0; st >>= 1) { if (t < st) sm[t] += sm[t + st]; __syncthreads(); }
    if (t == 0) *out = sm[0] / (float)B_ROWS;
}

static void launch_gemm(int passes,
                        const void* Ah, const void* Al, int lda,
                        const void* Bh, const void* Bl, int ldb,
                        const float* bias, float* Cf, void* Ch, void* Cl,
                        int ldc, int nPad, int nOut, int K, int relu, int mode,
                        const float* bias2, const float* eps, float* klq)
{
    dim3 grid(nPad / 128, B_ROWS / 64);
    if (passes == 2) {
        cudaFuncSetAttribute(gemm_f16x<2>, cudaFuncAttributeMaxDynamicSharedMemorySize, GEMM_DYN);
        gemm_f16x<2><<<grid, 256, GEMM_DYN>>>(
            (const uint16_t*)Ah, (const uint16_t*)Al, lda,
            (const uint16_t*)Bh, (const uint16_t*)Bl, ldb,
            bias, Cf, (uint16_t*)Ch, (uint16_t*)Cl, ldc, nOut, K, relu, mode,
            bias2, eps, klq);
    } else {
        cudaFuncSetAttribute(gemm_f16x<3>, cudaFuncAttributeMaxDynamicSharedMemorySize, GEMM_DYN);
        gemm_f16x<3><<<grid, 256, GEMM_DYN>>>(
            (const uint16_t*)Ah, (const uint16_t*)Al, lda,
            (const uint16_t*)Bh, (const uint16_t*)Bl, ldb,
            bias, Cf, (uint16_t*)Ch, (uint16_t*)Cl, ldc, nOut, K, relu, mode,
            bias2, eps, klq);
    }
}

extern "C" void kernel_launch(void* const* d_in, const int* in_sizes, int n_in,
                              void* d_out, int out_size)
{
    const float* x        = (const float*)d_in[0];
    const void*  mask     = d_in[1];
    const int*   labels   = (const int*)d_in[2];
    const float* eps      = (const float*)d_in[3];
    const float* W_enc    = (const float*)d_in[4];
    const float* b_enc    = (const float*)d_in[5];
    const float* codebook = (const float*)d_in[6];
    const float* W1       = (const float*)d_in[7];
    const float* b1       = (const float*)d_in[8];
    const float* W2       = (const float*)d_in[9];
    const float* b2       = (const float*)d_in[10];
    const float* Wd       = (const float*)d_in[11];
    const float* bd       = (const float*)d_in[12];
    float* out = (float*)d_out;

    void *p_xh, *p_xl, *p_wch, *p_wcl, *p_w2h, *p_w2l, *p_wdh, *p_wdl;
    void *p_hh, *p_hl, *p_cath, *p_catl;
    float *p_G, *p_lb, *p_klq, *p_ze, *p_zq, *p_lg, *p_kl;
    cudaGetSymbolAddress(&p_xh, g_xh);   cudaGetSymbolAddress(&p_xl, g_xl);
    cudaGetSymbolAddress(&p_wch, g_wch); cudaGetSymbolAddress(&p_wcl, g_wcl);
    cudaGetSymbolAddress(&p_w2h, g_w2h); cudaGetSymbolAddress(&p_w2l, g_w2l);
    cudaGetSymbolAddress(&p_wdh, g_wdh); cudaGetSymbolAddress(&p_wdl, g_wdl);
    cudaGetSymbolAddress(&p_hh, g_hh);   cudaGetSymbolAddress(&p_hl, g_hl);
    cudaGetSymbolAddress(&p_cath, g_cath); cudaGetSymbolAddress(&p_catl, g_catl);
    cudaGetSymbolAddress((void**)&p_G,  g_G);
    cudaGetSymbolAddress((void**)&p_lb, g_lb);
    cudaGetSymbolAddress((void**)&p_klq, g_klq);
    cudaGetSymbolAddress((void**)&p_ze, g_ze_s);
    cudaGetSymbolAddress((void**)&p_zq, g_zq_s);
    cudaGetSymbolAddress((void**)&p_lg, g_lg_s);
    cudaGetSymbolAddress((void**)&p_kl, g_kl_s);

    const size_t full_elems = (size_t)B_ROWS * (IN_DIM + ENC_DIM + ENC_DIM + KCLS) + 1;
    const bool full = ((size_t)out_size >= full_elems);
    float* xt = out;
    float* ze = full ? out + (size_t)B_ROWS * IN_DIM : p_ze;
    float* zq = full ? ze + (size_t)B_ROWS * ENC_DIM : p_zq;
    float* lg = full ? zq + (size_t)B_ROWS * ENC_DIM : p_lg;
    float* kl = full ? lg + (size_t)B_ROWS * KCLS    : p_kl;

    {
        long np = (long)B_ROWS * IN_DIM / 2;
        split_mat<<<(unsigned)((np + 255) / 256), 256>>>(x, (uint32_t*)p_xh, (uint32_t*)p_xl, np, np);
        long wep = (long)512 * IN_DIM / 2, wes = (long)ENC_DIM * IN_DIM / 2;
        split_mat<<<(unsigned)((wep + 255) / 256), 256>>>(W_enc, (uint32_t*)p_wch, (uint32_t*)p_wcl, wep, wes);
        long w1p = (long)VDIM * IN_DIM / 2;
        split_mat<<<(unsigned)((w1p + 255) / 256), 256>>>(W1,
            (uint32_t*)p_wch + (size_t)512 * IN_DIM / 2,
            (uint32_t*)p_wcl + (size_t)512 * IN_DIM / 2, w1p, w1p);
        split_w2<<<(2 * VDIM * (VDIM / 2) + 255) / 256, 256>>>(W2);
        split_wd<<<(IN_DIM * (CAT_LD / 2) + 255) / 256, 256>>>(Wd);
    }
    detect_mask_kernel<<<1, 256>>>((const unsigned int*)mask);
    build_G<<<dim3(KCLS, IN_DIM / 128), 128>>>(W_enc, codebook);
    build_lb<<<KCLS, 128>>>(b_enc, codebook);

    sgemm64<<<B_ROWS / 64, 128>>>(x, p_G, p_lb, lg);

    // combined ze|h (mode 3) — 2-pass fp16
    launch_gemm(2, p_xh, p_xl, IN_DIM, p_wch, p_wcl, IN_DIM, b_enc,
                ze, p_hh, p_hl, ENC_DIM, NCOMB, ENC_DIM, IN_DIM, 0, 3,
                b1, nullptr, nullptr);
    // ml + fused VAE (mode 2) — 3-pass fp16 (accuracy anchor)
    launch_gemm(3, p_hh, p_hl, VDIM, p_w2h, p_w2l, VDIM, b2,
                nullptr, p_cath, p_catl, CAT_LD, 2 * VDIM, 2 * VDIM, VDIM, 0, 2,
                nullptr, eps, p_klq);

    argmax_y_kernel<<<B_ROWS, 32>>>(lg, mask, labels, codebook, zq);
    kl_reduce_kernel<<<1, 256>>>(kl, (2 * VDIM / 128) * (B_ROWS / 64));

    // decoder — 2-pass fp16
    launch_gemm(2, p_cath, p_catl, CAT_LD, p_wdh, p_wdl, CAT_LD, bd,
                xt, nullptr, nullptr, IN_DIM, IN_DIM, IN_DIM, CAT_LD, 0, 0,
                nullptr, nullptr, nullptr);
}

// round 14
// speedup vs baseline: 2.5796x; 1.1798x over previous
#include <cuda_runtime.h>
#include <cuda_fp16.h>
#include <math.h>
#include <stdint.h>

#define B_ROWS 16384
#define IN_DIM 768
#define ENC_DIM 500
#define KCLS 43
#define VDIM 1024
#define CAT_RAW 1067
#define CAT_LD  1088
#define NCOMB 1536

__device__ uint32_t g_xh [(size_t)B_ROWS * IN_DIM / 2];
__device__ uint32_t g_xl [(size_t)B_ROWS * IN_DIM / 2];
__device__ uint32_t g_wch[(size_t)NCOMB * IN_DIM / 2];
__device__ uint32_t g_w2h[(size_t)2 * VDIM * VDIM / 2];
__device__ uint32_t g_wdh[(size_t)IN_DIM * CAT_LD / 2];
__device__ uint32_t g_hh [(size_t)B_ROWS * VDIM / 2];
__device__ uint32_t g_hl [(size_t)B_ROWS * VDIM / 2];
__device__ uint32_t g_cath[(size_t)B_ROWS * CAT_LD / 2];
__device__ uint32_t g_catl[(size_t)B_ROWS * CAT_LD / 2];
__device__ float g_G  [(size_t)KCLS * IN_DIM];
__device__ float g_lb [KCLS];
__device__ float g_klq[4096];
__device__ float g_ze_s[(size_t)B_ROWS * ENC_DIM];
__device__ float g_zq_s[(size_t)B_ROWS * ENC_DIM];
__device__ float g_lg_s[(size_t)B_ROWS * KCLS];
__device__ float g_kl_s[1];
__device__ int   g_mask_mode;

__device__ __forceinline__ uint32_t smem_to_u32(const void* p) {
    uint32_t a;
    asm("{ .reg .u64 t; cvta.to.shared.u64 t, %1; cvt.u32.u64 %0, t; }" : "=r"(a) : "l"(p));
    return a;
}
#define SWZ(b) ((b) ^ (((b) >> 3) & 0x70))
#define CP16(d, s)  asm volatile("cp.async.cg.shared.global [%0], [%1], 16;" :: "r"(d), "l"(s) : "memory")
#define CP_COMMIT() asm volatile("cp.async.commit_group;" ::: "memory")
#define CP_WAIT0()  asm volatile("cp.async.wait_group 0;" ::: "memory")
#define CP_WAIT1()  asm volatile("cp.async.wait_group 1;" ::: "memory")

__device__ __forceinline__ void ldsm_x4(uint32_t* r, uint32_t addr) {
    asm volatile("ldmatrix.sync.aligned.m8n8.x4.shared.b16 {%0,%1,%2,%3}, [%4];"
        : "=r"(r[0]), "=r"(r[1]), "=r"(r[2]), "=r"(r[3]) : "r"(addr));
}
__device__ __forceinline__ void mma_f16(float* c, const uint32_t* a, const uint32_t* b) {
    asm volatile("mma.sync.aligned.m16n8k16.row.col.f32.f16.f16.f32 "
        "{%0,%1,%2,%3}, {%4,%5,%6,%7}, {%8,%9}, {%0,%1,%2,%3};"
        : "+f"(c[0]), "+f"(c[1]), "+f"(c[2]), "+f"(c[3])
        : "r"(a[0]), "r"(a[1]), "r"(a[2]), "r"(a[3]), "r"(b[0]), "r"(b[1]));
}
__device__ __forceinline__ void split2(float v0, float v1, uint32_t& H, uint32_t& L) {
    __half h0 = __float2half_rn(v0), h1 = __float2half_rn(v1);
    float r0 = v0 - __half2float(h0), r1 = v1 - __half2float(h1);
    __half l0 = __float2half_rn(r0), l1 = __float2half_rn(r1);
    __half2 hp = __halves2half2(h0, h1), lp = __halves2half2(l0, l1);
    H = *reinterpret_cast<uint32_t*>(&hp);
    L = *reinterpret_cast<uint32_t*>(&lp);
}
__device__ __forceinline__ uint32_t pack_hi2(float v0, float v1) {
    __half2 hp = __halves2half2(__float2half_rn(v0), __float2half_rn(v1));
    return *reinterpret_cast<uint32_t*>(&hp);
}
__device__ __forceinline__ float fast_exp(float x) {
    float r;
    asm("ex2.approx.ftz.f32 %0, %1;" : "=f"(r) : "f"(x * 1.4426950408889634f));
    return r;
}

// ---------------- 2-pass fp16 GEMM: C = A @ Bh^T (+bias) ----------------
// Stage: Ah(8K) Al(8K) Bh(16K) = 32KB; 2 stages = 64KB.
#define ST_BYTES 32768u
#define OFF_AL 8192u
#define OFF_BH 16384u
#define GEMM_DYN (2 * 32768 + 1024)

__device__ __forceinline__ void load_chunk(uint32_t base, int tid, int m0, int n0, int k0,
    const uint16_t* Ah, const uint16_t* Al, int lda,
    const uint16_t* Bh, int ldb)
{
#pragma unroll
    for (int half = 0; half < 2; half++) {
        int idx = half * 256 + tid;
        int row = idx >> 3, u = idx & 7;
        uint32_t off = SWZ((uint32_t)(row * 128 + u * 16));
        size_t ao = (size_t)(m0 + row) * lda + k0 + u * 8;
        CP16(base + off,          Ah + ao);
        CP16(base + OFF_AL + off, Al + ao);
    }
#pragma unroll
    for (int it = 0; it < 4; it++) {
        int idx = it * 256 + tid;
        int row = idx >> 3, u = idx & 7;
        uint32_t off = SWZ((uint32_t)(row * 128 + u * 16));
        size_t bo = (size_t)(n0 + row) * ldb + k0 + u * 8;
        CP16(base + OFF_BH + off, Bh + bo);
    }
}

// mode 0: fp32 C; mode 1: split fp16 C; mode 2: fused VAE; mode 3: combined ze|h
__global__ __launch_bounds__(256, 2)
void gemm_f16(const uint16_t* __restrict__ Ah, const uint16_t* __restrict__ Al, int lda,
              const uint16_t* __restrict__ Bh, int ldb,
              const float* __restrict__ bias,
              float* __restrict__ Cf, uint16_t* __restrict__ Ch, uint16_t* __restrict__ Cl,
              int ldc, int nOut, int K, int relu, int mode,
              const float* __restrict__ bias2, const float* __restrict__ eps,
              float* __restrict__ klq)
{
    extern __shared__ char smem[];
    const uint32_t tiles = (smem_to_u32(smem) + 1023) & ~1023u;
    const int tid = threadIdx.x, wid = tid >> 5, lane = tid & 31;
    const int m0 = blockIdx.y * 64, n0 = blockIdx.x * 128;
    const int wm = (wid >> 2) * 32, wn = (wid & 3) * 32;

    float acc[2][4][4];
#pragma unroll
    for (int i = 0; i < 2; i++)
#pragma unroll
        for (int j = 0; j < 4; j++)
#pragma unroll
            for (int q = 0; q < 4; q++) acc[i][j][q] = 0.f;

    const uint32_t aRowByte = (uint32_t)(wm + (lane & 15)) * 128u;
    const uint32_t aKoff    = (uint32_t)((lane >> 4) * 16);
    const uint32_t bRowByte = (uint32_t)(wn + (lane & 7) + ((lane >> 4) << 3)) * 128u;
    const uint32_t bKoff    = (uint32_t)(((lane >> 3) & 1) * 16);

    const int S = K / 64;
    load_chunk(tiles, tid, m0, n0, 0, Ah, Al, lda, Bh, ldb);
    CP_COMMIT();

    for (int s = 0; s < S; s++) {
        if (s + 1 < S) {
            load_chunk(tiles + ((s + 1) & 1) * ST_BYTES, tid, m0, n0, (s + 1) * 64,
                       Ah, Al, lda, Bh, ldb);
            CP_COMMIT();
            CP_WAIT1();
        } else {
            CP_WAIT0();
        }
        __syncthreads();

        const uint32_t pah = tiles + (s & 1) * ST_BYTES;
        const uint32_t pal = pah + OFF_AL, pbh = pah + OFF_BH;
#pragma unroll
        for (int kk = 0; kk < 4; kk++) {
            const uint32_t kb = (uint32_t)(kk * 32);
            uint32_t ah[2][4], al[2][4], bh[2][4];
#pragma unroll
            for (int mt = 0; mt < 2; mt++) {
                uint32_t ro = SWZ(aRowByte + (uint32_t)(mt * 2048) + kb + aKoff);
                ldsm_x4(ah[mt], pah + ro);
                ldsm_x4(al[mt], pal + ro);
            }
#pragma unroll
            for (int nb = 0; nb < 2; nb++) {
                uint32_t ro = SWZ(bRowByte + (uint32_t)(nb * 2048) + kb + bKoff);
                ldsm_x4(bh[nb], pbh + ro);
            }
#pragma unroll
            for (int t2 = 0; t2 < 2; t2++)
#pragma unroll
                for (int mt = 0; mt < 2; mt++)
#pragma unroll
                    for (int nt = 0; nt < 4; nt++) {
                        const uint32_t* ap = t2 ? al[mt] : ah[mt];
                        mma_f16(acc[mt][nt], ap, &bh[nt >> 1][(nt & 1) * 2]);
                    }
        }
        __syncthreads();
    }

    // ---- epilogue ----
    int emode = mode;
    const float* eb = bias;
    int erelu = relu;
    int cbase = n0;
    int ldcEff = ldc;
    if (mode == 3) {
        if (n0 < 512) { emode = 0; }
        else { emode = 1; eb = bias2; erelu = 1; cbase = n0 - 512; ldcEff = VDIM; }
    }

    if (emode == 0) {
#pragma unroll
        for (int mt = 0; mt < 2; mt++) {
            const int r0 = m0 + wm + mt * 16 + (lane >> 2);
            float* crow0 = Cf + (size_t)r0 * ldcEff;
            float* crow8 = Cf + (size_t)(r0 + 8) * ldcEff;
#pragma unroll
            for (int nt = 0; nt < 4; nt++) {
                const int c = cbase + wn + nt * 8 + (lane & 3) * 2;
                if (c >= nOut) continue;
                float b0 = eb[c], b1 = eb[c + 1];
                float v0 = acc[mt][nt][0] + b0, v1 = acc[mt][nt][1] + b1;
                float v2 = acc[mt][nt][2] + b0, v3 = acc[mt][nt][3] + b1;
                if (erelu) {
                    v0 = fmaxf(v0, 0.f); v1 = fmaxf(v1, 0.f);
                    v2 = fmaxf(v2, 0.f); v3 = fmaxf(v3, 0.f);
                }
                *reinterpret_cast<float2*>(crow0 + c) = make_float2(v0, v1);
                *reinterpret_cast<float2*>(crow8 + c) = make_float2(v2, v3);
            }
        }
    } else if (emode == 1) {
#pragma unroll
        for (int mt = 0; mt < 2; mt++) {
            const int r0 = m0 + wm + mt * 16 + (lane >> 2);
#pragma unroll
            for (int nt = 0; nt < 4; nt++) {
                const int c = cbase + wn + nt * 8 + (lane & 3) * 2;
                float b0 = eb[c], b1 = eb[c + 1];
                float v0 = acc[mt][nt][0] + b0, v1 = acc[mt][nt][1] + b1;
                float v2 = acc[mt][nt][2] + b0, v3 = acc[mt][nt][3] + b1;
                if (erelu) {
                    v0 = fmaxf(v0, 0.f); v1 = fmaxf(v1, 0.f);
                    v2 = fmaxf(v2, 0.f); v3 = fmaxf(v3, 0.f);
                }
                uint32_t H, L;
                split2(v0, v1, H, L);
                *reinterpret_cast<uint32_t*>(Ch + (size_t)r0 * ldcEff + c) = H;
                *reinterpret_cast<uint32_t*>(Cl + (size_t)r0 * ldcEff + c) = L;
                split2(v2, v3, H, L);
                *reinterpret_cast<uint32_t*>(Ch + (size_t)(r0 + 8) * ldcEff + c) = H;
                *reinterpret_cast<uint32_t*>(Cl + (size_t)(r0 + 8) * ldcEff + c) = L;
            }
        }
    } else {
        float klsum = 0.f;
#pragma unroll
        for (int mt = 0; mt < 2; mt++) {
            const int r0 = m0 + wm + mt * 16 + (lane >> 2);
#pragma unroll
            for (int nt = 0; nt < 4; nt++) {
                const int c = n0 + wn + nt * 8 + (lane & 3) * 2;
                const int i = c >> 1;
                float bmu = bias[i], blv = bias[VDIM + i];
#pragma unroll
                for (int h = 0; h < 2; h++) {
                    const int r = r0 + h * 8;
                    float mu = acc[mt][nt][2 * h + 0] + bmu;
                    float lv = acc[mt][nt][2 * h + 1] + blv;
                    klsum += 0.5f * (fast_exp(lv) + mu * mu - 1.0f - lv);
                    float z = fmaf(fast_exp(0.5f * lv), eps[(size_t)r * VDIM + i], mu);
                    __half zh = __float2half_rn(z);
                    __half zl = __float2half_rn(z - __half2float(zh));
                    Ch[(size_t)r * ldc + i] = *reinterpret_cast<uint16_t*>(&zh);
                    Cl[(size_t)r * ldc + i] = *reinterpret_cast<uint16_t*>(&zl);
                }
            }
        }
        float* sred = reinterpret_cast<float*>(smem);
        sred[tid] = klsum;
        __syncthreads();
        for (int st = 128; st > 0; st >>= 1) {
            if (tid < st) sred[tid] += sred[tid + st];
            __syncthreads();
        }
        if (tid == 0) klq[blockIdx.y * gridDim.x + blockIdx.x] = sred[0];
    }
}

__global__ __launch_bounds__(128)
void sgemm64(const float* __restrict__ A, const float* __restrict__ G,
             const float* __restrict__ lb, float* __restrict__ C)
{
    __shared__ float As[16][64];
    __shared__ float Bs[16][64];
    const int tid = threadIdx.x;
    const int m0 = blockIdx.x * 64;
    const int tx = tid & 15, ty = tid >> 4;
    const int lrow = tid >> 1, lhalf = tid & 1;
    float acc[8][4];
#pragma unroll
    for (int i = 0; i < 8; i++)
#pragma unroll
        for (int j = 0; j < 4; j++) acc[i][j] = 0.f;

    for (int k0 = 0; k0 < IN_DIM; k0 += 16) {
#pragma unroll
        for (int h = 0; h < 2; h++) {
            int kk = lhalf * 8 + h * 4;
            float4 va = *reinterpret_cast<const float4*>(A + (size_t)(m0 + lrow) * IN_DIM + k0 + kk);
            As[kk + 0][lrow] = va.x; As[kk + 1][lrow] = va.y;
            As[kk + 2][lrow] = va.z; As[kk + 3][lrow] = va.w;
            float4 vb = make_float4(0.f, 0.f, 0.f, 0.f);
            if (lrow < KCLS)
                vb = *reinterpret_cast<const float4*>(G + (size_t)lrow * IN_DIM + k0 + kk);
            Bs[kk + 0][lrow] = vb.x; Bs[kk + 1][lrow] = vb.y;
            Bs[kk + 2][lrow] = vb.z; Bs[kk + 3][lrow] = vb.w;
        }
        __syncthreads();
#pragma unroll
        for (int k = 0; k < 16; k++) {
            float4 a0 = *reinterpret_cast<const float4*>(&As[k][ty * 4]);
            float4 a1 = *reinterpret_cast<const float4*>(&As[k][32 + ty * 4]);
            float4 b  = *reinterpret_cast<const float4*>(&Bs[k][tx * 4]);
            float a[8] = {a0.x, a0.y, a0.z, a0.w, a1.x, a1.y, a1.z, a1.w};
            float bb[4] = {b.x, b.y, b.z, b.w};
#pragma unroll
            for (int i = 0; i < 8; i++)
#pragma unroll
                for (int j = 0; j < 4; j++)
                    acc[i][j] = fmaf(a[i], bb[j], acc[i][j]);
        }
        __syncthreads();
    }
#pragma unroll
    for (int i = 0; i < 8; i++) {
        int row = m0 + ((i < 4) ? (ty * 4 + i) : (32 + ty * 4 + i - 4));
#pragma unroll
        for (int j = 0; j < 4; j++) {
            int col = tx * 4 + j;
            if (col < KCLS) C[(size_t)row * KCLS + col] = acc[i][j] + lb[col];
        }
    }
}

// splits: activations need hi+lo; weights need hi only
__global__ void split_mat(const float* __restrict__ src, uint32_t* __restrict__ dh,
                          uint32_t* __restrict__ dl, long nPairs, long srcPairs)
{
    long i = (long)blockIdx.x * blockDim.x + threadIdx.x;
    if (i >= nPairs) return;
    float v0 = 0.f, v1 = 0.f;
    if (i < srcPairs) {
        float2 v = reinterpret_cast<const float2*>(src)[i];
        v0 = v.x; v1 = v.y;
    }
    uint32_t H, L;
    split2(v0, v1, H, L);
    dh[i] = H;
    if (dl) dl[i] = L;
}

__global__ void split_w2(const float* __restrict__ W2)
{
    int i = blockIdx.x * blockDim.x + threadIdx.x;
    const int ppr = VDIM / 2;
    if (i >= 2 * VDIM * ppr) return;
    int rr = i / ppr, p = i - rr * ppr;
    int orig = (rr & 1) ? (VDIM + (rr >> 1)) : (rr >> 1);
    float2 v = *reinterpret_cast<const float2*>(W2 + (size_t)orig * VDIM + 2 * p);
    g_w2h[i] = pack_hi2(v.x, v.y);
}

__global__ void split_wd(const float* __restrict__ Wd)
{
    int i = blockIdx.x * blockDim.x + threadIdx.x;
    const int ppr = CAT_LD / 2;
    if (i >= IN_DIM * ppr) return;
    int r = i / ppr, p = i - r * ppr;
    int c0 = 2 * p;
    float v0 = (c0 < CAT_RAW) ? Wd[(size_t)r * CAT_RAW + c0] : 0.f;
    float v1 = (c0 + 1 < CAT_RAW) ? Wd[(size_t)r * CAT_RAW + c0 + 1] : 0.f;
    g_wdh[i] = pack_hi2(v0, v1);
}

__global__ void build_G(const float* __restrict__ W_enc, const float* __restrict__ cb)
{
    int c = blockIdx.x;
    int i = blockIdx.y * 128 + threadIdx.x;
    float s = 0.f;
#pragma unroll 4
    for (int d = 0; d < ENC_DIM; d++)
        s = fmaf(cb[c * ENC_DIM + d], W_enc[(size_t)d * IN_DIM + i], s);
    g_G[(size_t)c * IN_DIM + i] = s;
}
__global__ void build_lb(const float* __restrict__ b_enc, const float* __restrict__ cb)
{
    int c = blockIdx.x;
    int t = threadIdx.x;
    float s = 0.f;
    for (int d = t; d < ENC_DIM; d += 128) s = fmaf(b_enc[d], cb[c * ENC_DIM + d], s);
    __shared__ float sm[128];
    sm[t] = s;
    __syncthreads();
    for (int st = 64; st > 0; st >>= 1) { if (t < st) sm[t] += sm[t + st]; __syncthreads(); }
    if (t == 0) g_lb[c] = sm[0];
}

__global__ void detect_mask_kernel(const unsigned int* __restrict__ w)
{
    __shared__ int s_int, s_flt;
    if (threadIdx.x == 0) { s_int = 1; s_flt = 1; }
    __syncthreads();
    int li = 1, lf = 1;
    for (int i = threadIdx.x; i < 4096; i += blockDim.x) {
        unsigned v = w[i];
        if (v > 1u) li = 0;
        if (v != 0u && v != 0x3F800000u) lf = 0;
    }
    if (!li) atomicAnd(&s_int, 0);
    if (!lf) atomicAnd(&s_flt, 0);
    __syncthreads();
    if (threadIdx.x == 0) g_mask_mode = s_int ? 1 : (s_flt ? 2 : 0);
}

__global__ void argmax_y_kernel(const float* __restrict__ logits,
                                const void* __restrict__ mask,
                                const int* __restrict__ labels,
                                const float* __restrict__ codebook,
                                float* __restrict__ zq)
{
    const int b = blockIdx.x;
    const int lane = threadIdx.x;
    const float NEG = __int_as_float(0xff800000u);
    const float* lr = logits + (size_t)b * KCLS;
    const int k0 = 2 * lane, k1 = 2 * lane + 1;
    float va = (k0 < KCLS) ? lr[k0] : NEG;
    float vb = (k1 < KCLS) ? lr[k1] : NEG;
    float m; int mi;
    if (va >= vb) { m = va; mi = k0; } else { m = vb; mi = k1; }
#pragma unroll
    for (int off = 16; off > 0; off >>= 1) {
        float om = __shfl_xor_sync(0xffffffffu, m, off);
        int oi = __shfl_xor_sync(0xffffffffu, mi, off);
        if (om > m || (om == m && oi < mi)) { m = om; mi = oi; }
    }
    float ea = (k0 < KCLS) ? expf(va - m) : 0.f;
    float eb = (k1 < KCLS) ? expf(vb - m) : 0.f;
    float s = ea + eb;
#pragma unroll
    for (int off = 16; off > 0; off >>= 1) s += __shfl_xor_sync(0xffffffffu, s, off);
    float inv = 1.0f / s;

    int mode = g_mask_mode;
    bool known;
    if (mode == 1)      known = ((const int*)mask)[b] != 0;
    else if (mode == 2) known = ((const float*)mask)[b] != 0.f;
    else                known = ((const unsigned char*)mask)[b] != 0;
    int lab = labels[b];

    float y0 = (k0 < KCLS) ? (known ? (k0 == lab ? 1.f : 0.f) : ea * inv) : 0.f;
    float y1 = (k1 < KCLS) ? (known ? (k1 == lab ? 1.f : 0.f) : eb * inv) : 0.f;
    uint32_t H, L;
    split2(y0, y1, H, L);
    const size_t pi = (size_t)b * (CAT_LD / 2) + (VDIM / 2) + lane;
    g_cath[pi] = H; g_catl[pi] = L;

    const float* cr = codebook + (size_t)mi * ENC_DIM;
    float* zr = zq + (size_t)b * ENC_DIM;
    for (int i = lane; i < ENC_DIM; i += 32) zr[i] = cr[i];
}

__global__ void kl_reduce_kernel(float* __restrict__ out, int n)
{
    const int t = threadIdx.x;
    float s = 0.f;
    for (int i = t; i < n; i += 256) s += g_klq[i];
    __shared__ float sm[256];
    sm[t] = s;
    __syncthreads();
    for (int st = 128; st > 0; st >>= 1) { if (t < st) sm[t] += sm[t + st]; __syncthreads(); }
    if (t == 0) *out = sm[0] / (float)B_ROWS;
}

static void launch_gemm(const void* Ah, const void* Al, int lda,
                        const void* Bh, int ldb,
                        const float* bias, float* Cf, void* Ch, void* Cl,
                        int ldc, int nPad, int nOut, int K, int relu, int mode,
                        const float* bias2, const float* eps, float* klq)
{
    cudaFuncSetAttribute(gemm_f16, cudaFuncAttributeMaxDynamicSharedMemorySize, GEMM_DYN);
    dim3 grid(nPad / 128, B_ROWS / 64);
    gemm_f16<<<grid, 256, GEMM_DYN>>>(
        (const uint16_t*)Ah, (const uint16_t*)Al, lda,
        (const uint16_t*)Bh, ldb,
        bias, Cf, (uint16_t*)Ch, (uint16_t*)Cl, ldc, nOut, K, relu, mode,
        bias2, eps, klq);
}

extern "C" void kernel_launch(void* const* d_in, const int* in_sizes, int n_in,
                              void* d_out, int out_size)
{
    const float* x        = (const float*)d_in[0];
    const void*  mask     = d_in[1];
    const int*   labels   = (const int*)d_in[2];
    const float* eps      = (const float*)d_in[3];
    const float* W_enc    = (const float*)d_in[4];
    const float* b_enc    = (const float*)d_in[5];
    const float* codebook = (const float*)d_in[6];
    const float* W1       = (const float*)d_in[7];
    const float* b1       = (const float*)d_in[8];
    const float* W2       = (const float*)d_in[9];
    const float* b2       = (const float*)d_in[10];
    const float* Wd       = (const float*)d_in[11];
    const float* bd       = (const float*)d_in[12];
    float* out = (float*)d_out;

    void *p_xh, *p_xl, *p_wch, *p_w2h, *p_wdh;
    void *p_hh, *p_hl, *p_cath, *p_catl;
    float *p_G, *p_lb, *p_klq, *p_ze, *p_zq, *p_lg, *p_kl;
    cudaGetSymbolAddress(&p_xh, g_xh);   cudaGetSymbolAddress(&p_xl, g_xl);
    cudaGetSymbolAddress(&p_wch, g_wch);
    cudaGetSymbolAddress(&p_w2h, g_w2h);
    cudaGetSymbolAddress(&p_wdh, g_wdh);
    cudaGetSymbolAddress(&p_hh, g_hh);   cudaGetSymbolAddress(&p_hl, g_hl);
    cudaGetSymbolAddress(&p_cath, g_cath); cudaGetSymbolAddress(&p_catl, g_catl);
    cudaGetSymbolAddress((void**)&p_G,  g_G);
    cudaGetSymbolAddress((void**)&p_lb, g_lb);
    cudaGetSymbolAddress((void**)&p_klq, g_klq);
    cudaGetSymbolAddress((void**)&p_ze, g_ze_s);
    cudaGetSymbolAddress((void**)&p_zq, g_zq_s);
    cudaGetSymbolAddress((void**)&p_lg, g_lg_s);
    cudaGetSymbolAddress((void**)&p_kl, g_kl_s);

    const size_t full_elems = (size_t)B_ROWS * (IN_DIM + ENC_DIM + ENC_DIM + KCLS) + 1;
    const bool full = ((size_t)out_size >= full_elems);
    float* xt = out;
    float* ze = full ? out + (size_t)B_ROWS * IN_DIM : p_ze;
    float* zq = full ? ze + (size_t)B_ROWS * ENC_DIM : p_zq;
    float* lg = full ? zq + (size_t)B_ROWS * ENC_DIM : p_lg;
    float* kl = full ? lg + (size_t)B_ROWS * KCLS    : p_kl;

    {
        long np = (long)B_ROWS * IN_DIM / 2;
        split_mat<<<(unsigned)((np + 255) / 256), 256>>>(x, (uint32_t*)p_xh, (uint32_t*)p_xl, np, np);
        long wep = (long)512 * IN_DIM / 2, wes = (long)ENC_DIM * IN_DIM / 2;
        split_mat<<<(unsigned)((wep + 255) / 256), 256>>>(W_enc, (uint32_t*)p_wch, nullptr, wep, wes);
        long w1p = (long)VDIM * IN_DIM / 2;
        split_mat<<<(unsigned)((w1p + 255) / 256), 256>>>(W1,
            (uint32_t*)p_wch + (size_t)512 * IN_DIM / 2, nullptr, w1p, w1p);
        split_w2<<<(2 * VDIM * (VDIM / 2) + 255) / 256, 256>>>(W2);
        split_wd<<<(IN_DIM * (CAT_LD / 2) + 255) / 256, 256>>>(Wd);
    }
    detect_mask_kernel<<<1, 256>>>((const unsigned int*)mask);
    build_G<<<dim3(KCLS, IN_DIM / 128), 128>>>(W_enc, codebook);
    build_lb<<<KCLS, 128>>>(b_enc, codebook);

    sgemm64<<<B_ROWS / 64, 128>>>(x, p_G, p_lb, lg);

    // combined ze|h (mode 3)
    launch_gemm(p_xh, p_xl, IN_DIM, p_wch, IN_DIM, b_enc,
                ze, p_hh, p_hl, ENC_DIM, NCOMB, ENC_DIM, IN_DIM, 0, 3,
                b1, nullptr, nullptr);
    // ml + fused VAE (mode 2)
    launch_gemm(p_hh, p_hl, VDIM, p_w2h, VDIM, b2,
                nullptr, p_cath, p_catl, CAT_LD, 2 * VDIM, 2 * VDIM, VDIM, 0, 2,
                nullptr, eps, p_klq);

    argmax_y_kernel<<<B_ROWS, 32>>>(lg, mask, labels, codebook, zq);
    kl_reduce_kernel<<<1, 256>>>(kl, (2 * VDIM / 128) * (B_ROWS / 64));

    // decoder
    launch_gemm(p_cath, p_catl, CAT_LD, p_wdh, CAT_LD, bd,
                xt, nullptr, nullptr, IN_DIM, IN_DIM, IN_DIM, CAT_LD, 0, 0,
                nullptr, nullptr, nullptr);
}

// round 15
// speedup vs baseline: 3.0545x; 1.1841x over previous
#include <cuda_runtime.h>
#include <cuda_fp16.h>
#include <math.h>
#include <stdint.h>

#define B_ROWS 16384
#define IN_DIM 768
#define ENC_DIM 500
#define KCLS 43
#define VDIM 1024
#define CAT_RAW 1067
#define CAT_LD  1088
#define NCOMB 1536

__device__ uint32_t g_xh [(size_t)B_ROWS * IN_DIM / 2];
__device__ uint32_t g_wch[(size_t)NCOMB * IN_DIM / 2];
__device__ uint32_t g_w2h[(size_t)2 * VDIM * VDIM / 2];
__device__ uint32_t g_wdh[(size_t)IN_DIM * CAT_LD / 2];
__device__ uint32_t g_hh [(size_t)B_ROWS * VDIM / 2];
__device__ uint32_t g_hl [(size_t)B_ROWS * VDIM / 2];
__device__ uint32_t g_cath[(size_t)B_ROWS * CAT_LD / 2];
__device__ float g_G  [(size_t)KCLS * IN_DIM];
__device__ float g_lb [KCLS];
__device__ float g_klq[4096];
__device__ float g_ze_s[(size_t)B_ROWS * ENC_DIM];
__device__ float g_zq_s[(size_t)B_ROWS * ENC_DIM];
__device__ float g_lg_s[(size_t)B_ROWS * KCLS];
__device__ float g_kl_s[1];
__device__ int   g_mask_mode;

__device__ __forceinline__ uint32_t smem_to_u32(const void* p) {
    uint32_t a;
    asm("{ .reg .u64 t; cvta.to.shared.u64 t, %1; cvt.u32.u64 %0, t; }" : "=r"(a) : "l"(p));
    return a;
}
#define SWZ(b) ((b) ^ (((b) >> 3) & 0x70))
#define CP16(d, s)  asm volatile("cp.async.cg.shared.global [%0], [%1], 16;" :: "r"(d), "l"(s) : "memory")
#define CP_COMMIT() asm volatile("cp.async.commit_group;" ::: "memory")
#define CP_WAIT0()  asm volatile("cp.async.wait_group 0;" ::: "memory")
#define CP_WAIT1()  asm volatile("cp.async.wait_group 1;" ::: "memory")

__device__ __forceinline__ void ldsm_x4(uint32_t* r, uint32_t addr) {
    asm volatile("ldmatrix.sync.aligned.m8n8.x4.shared.b16 {%0,%1,%2,%3}, [%4];"
        : "=r"(r[0]), "=r"(r[1]), "=r"(r[2]), "=r"(r[3]) : "r"(addr));
}
__device__ __forceinline__ void mma_f16(float* c, const uint32_t* a, const uint32_t* b) {
    asm volatile("mma.sync.aligned.m16n8k16.row.col.f32.f16.f16.f32 "
        "{%0,%1,%2,%3}, {%4,%5,%6,%7}, {%8,%9}, {%0,%1,%2,%3};"
        : "+f"(c[0]), "+f"(c[1]), "+f"(c[2]), "+f"(c[3])
        : "r"(a[0]), "r"(a[1]), "r"(a[2]), "r"(a[3]), "r"(b[0]), "r"(b[1]));
}
__device__ __forceinline__ void split2(float v0, float v1, uint32_t& H, uint32_t& L) {
    __half h0 = __float2half_rn(v0), h1 = __float2half_rn(v1);
    float r0 = v0 - __half2float(h0), r1 = v1 - __half2float(h1);
    __half l0 = __float2half_rn(r0), l1 = __float2half_rn(r1);
    __half2 hp = __halves2half2(h0, h1), lp = __halves2half2(l0, l1);
    H = *reinterpret_cast<uint32_t*>(&hp);
    L = *reinterpret_cast<uint32_t*>(&lp);
}
__device__ __forceinline__ uint32_t pack_hi2(float v0, float v1) {
    __half2 hp = __halves2half2(__float2half_rn(v0), __float2half_rn(v1));
    return *reinterpret_cast<uint32_t*>(&hp);
}
__device__ __forceinline__ float fast_exp(float x) {
    float r;
    asm("ex2.approx.ftz.f32 %0, %1;" : "=f"(r) : "f"(x * 1.4426950408889634f));
    return r;
}

// ---------------- fp16 GEMM (AP passes: 1 = A*Bh, 2 = (Ah+Al)*Bh) ----------------
#define ST_BYTES 32768u
#define OFF_AL 8192u
#define OFF_BH 16384u
#define GEMM_DYN (2 * 32768 + 1024)

template<int AP>
__device__ __forceinline__ void load_chunk(uint32_t base, int tid, int m0, int n0, int k0,
    const uint16_t* Ah, const uint16_t* Al, int lda,
    const uint16_t* Bh, int ldb)
{
#pragma unroll
    for (int half = 0; half < 2; half++) {
        int idx = half * 256 + tid;
        int row = idx >> 3, u = idx & 7;
        uint32_t off = SWZ((uint32_t)(row * 128 + u * 16));
        size_t ao = (size_t)(m0 + row) * lda + k0 + u * 8;
        CP16(base + off, Ah + ao);
        if (AP == 2) CP16(base + OFF_AL + off, Al + ao);
    }
#pragma unroll
    for (int it = 0; it < 4; it++) {
        int idx = it * 256 + tid;
        int row = idx >> 3, u = idx & 7;
        uint32_t off = SWZ((uint32_t)(row * 128 + u * 16));
        size_t bo = (size_t)(n0 + row) * ldb + k0 + u * 8;
        CP16(base + OFF_BH + off, Bh + bo);
    }
}

// mode 0: fp32 C; mode 1: split fp16 C; mode 2: fused VAE (hi only); mode 3: combined ze|h
template<int AP>
__global__ __launch_bounds__(256, 2)
void gemm_f16x(const uint16_t* __restrict__ Ah, const uint16_t* __restrict__ Al, int lda,
               const uint16_t* __restrict__ Bh, int ldb,
               const float* __restrict__ bias,
               float* __restrict__ Cf, uint16_t* __restrict__ Ch, uint16_t* __restrict__ Cl,
               int ldc, int nOut, int K, int relu, int mode,
               const float* __restrict__ bias2, const float* __restrict__ eps,
               float* __restrict__ klq)
{
    extern __shared__ char smem[];
    const uint32_t tiles = (smem_to_u32(smem) + 1023) & ~1023u;
    const int tid = threadIdx.x, wid = tid >> 5, lane = tid & 31;
    const int m0 = blockIdx.y * 64, n0 = blockIdx.x * 128;
    const int wm = (wid >> 2) * 32, wn = (wid & 3) * 32;

    float acc[2][4][4];
#pragma unroll
    for (int i = 0; i < 2; i++)
#pragma unroll
        for (int j = 0; j < 4; j++)
#pragma unroll
            for (int q = 0; q < 4; q++) acc[i][j][q] = 0.f;

    const uint32_t aRowByte = (uint32_t)(wm + (lane & 15)) * 128u;
    const uint32_t aKoff    = (uint32_t)((lane >> 4) * 16);
    const uint32_t bRowByte = (uint32_t)(wn + (lane & 7) + ((lane >> 4) << 3)) * 128u;
    const uint32_t bKoff    = (uint32_t)(((lane >> 3) & 1) * 16);

    const int S = K / 64;
    load_chunk<AP>(tiles, tid, m0, n0, 0, Ah, Al, lda, Bh, ldb);
    CP_COMMIT();

    for (int s = 0; s < S; s++) {
        if (s + 1 < S) {
            load_chunk<AP>(tiles + ((s + 1) & 1) * ST_BYTES, tid, m0, n0, (s + 1) * 64,
                           Ah, Al, lda, Bh, ldb);
            CP_COMMIT();
            CP_WAIT1();
        } else {
            CP_WAIT0();
        }
        __syncthreads();

        const uint32_t pah = tiles + (s & 1) * ST_BYTES;
        const uint32_t pal = pah + OFF_AL, pbh = pah + OFF_BH;
#pragma unroll
        for (int kk = 0; kk < 4; kk++) {
            const uint32_t kb = (uint32_t)(kk * 32);
            uint32_t ah[2][4], al[2][4], bh[2][4];
#pragma unroll
            for (int mt = 0; mt < 2; mt++) {
                uint32_t ro = SWZ(aRowByte + (uint32_t)(mt * 2048) + kb + aKoff);
                ldsm_x4(ah[mt], pah + ro);
                if (AP == 2) ldsm_x4(al[mt], pal + ro);
            }
#pragma unroll
            for (int nb = 0; nb < 2; nb++) {
                uint32_t ro = SWZ(bRowByte + (uint32_t)(nb * 2048) + kb + bKoff);
                ldsm_x4(bh[nb], pbh + ro);
            }
#pragma unroll
            for (int t2 = 0; t2 < AP; t2++)
#pragma unroll
                for (int mt = 0; mt < 2; mt++)
#pragma unroll
                    for (int nt = 0; nt < 4; nt++) {
                        const uint32_t* ap = t2 ? al[mt] : ah[mt];
                        mma_f16(acc[mt][nt], ap, &bh[nt >> 1][(nt & 1) * 2]);
                    }
        }
        __syncthreads();
    }

    // ---- epilogue ----
    int emode = mode;
    const float* eb = bias;
    int erelu = relu;
    int cbase = n0;
    int ldcEff = ldc;
    if (mode == 3) {
        if (n0 < 512) { emode = 0; }
        else { emode = 1; eb = bias2; erelu = 1; cbase = n0 - 512; ldcEff = VDIM; }
    }

    if (emode == 0) {
#pragma unroll
        for (int mt = 0; mt < 2; mt++) {
            const int r0 = m0 + wm + mt * 16 + (lane >> 2);
            float* crow0 = Cf + (size_t)r0 * ldcEff;
            float* crow8 = Cf + (size_t)(r0 + 8) * ldcEff;
#pragma unroll
            for (int nt = 0; nt < 4; nt++) {
                const int c = cbase + wn + nt * 8 + (lane & 3) * 2;
                if (c >= nOut) continue;
                float b0 = eb[c], b1 = eb[c + 1];
                float v0 = acc[mt][nt][0] + b0, v1 = acc[mt][nt][1] + b1;
                float v2 = acc[mt][nt][2] + b0, v3 = acc[mt][nt][3] + b1;
                if (erelu) {
                    v0 = fmaxf(v0, 0.f); v1 = fmaxf(v1, 0.f);
                    v2 = fmaxf(v2, 0.f); v3 = fmaxf(v3, 0.f);
                }
                *reinterpret_cast<float2*>(crow0 + c) = make_float2(v0, v1);
                *reinterpret_cast<float2*>(crow8 + c) = make_float2(v2, v3);
            }
        }
    } else if (emode == 1) {
#pragma unroll
        for (int mt = 0; mt < 2; mt++) {
            const int r0 = m0 + wm + mt * 16 + (lane >> 2);
#pragma unroll
            for (int nt = 0; nt < 4; nt++) {
                const int c = cbase + wn + nt * 8 + (lane & 3) * 2;
                float b0 = eb[c], b1 = eb[c + 1];
                float v0 = acc[mt][nt][0] + b0, v1 = acc[mt][nt][1] + b1;
                float v2 = acc[mt][nt][2] + b0, v3 = acc[mt][nt][3] + b1;
                if (erelu) {
                    v0 = fmaxf(v0, 0.f); v1 = fmaxf(v1, 0.f);
                    v2 = fmaxf(v2, 0.f); v3 = fmaxf(v3, 0.f);
                }
                uint32_t H, L;
                split2(v0, v1, H, L);
                *reinterpret_cast<uint32_t*>(Ch + (size_t)r0 * ldcEff + c) = H;
                *reinterpret_cast<uint32_t*>(Cl + (size_t)r0 * ldcEff + c) = L;
                split2(v2, v3, H, L);
                *reinterpret_cast<uint32_t*>(Ch + (size_t)(r0 + 8) * ldcEff + c) = H;
                *reinterpret_cast<uint32_t*>(Cl + (size_t)(r0 + 8) * ldcEff + c) = L;
            }
        }
    } else {
        // mode 2: fused reparam + KL; z written hi-only (decoder is 1-pass)
        float klsum = 0.f;
#pragma unroll
        for (int mt = 0; mt < 2; mt++) {
            const int r0 = m0 + wm + mt * 16 + (lane >> 2);
#pragma unroll
            for (int nt = 0; nt < 4; nt++) {
                const int c = n0 + wn + nt * 8 + (lane & 3) * 2;
                const int i = c >> 1;
                float bmu = bias[i], blv = bias[VDIM + i];
#pragma unroll
                for (int h = 0; h < 2; h++) {
                    const int r = r0 + h * 8;
                    float mu = acc[mt][nt][2 * h + 0] + bmu;
                    float lv = acc[mt][nt][2 * h + 1] + blv;
                    klsum += 0.5f * (fast_exp(lv) + mu * mu - 1.0f - lv);
                    float z = fmaf(fast_exp(0.5f * lv), eps[(size_t)r * VDIM + i], mu);
                    __half zh = __float2half_rn(z);
                    Ch[(size_t)r * ldc + i] = *reinterpret_cast<uint16_t*>(&zh);
                }
            }
        }
        float* sred = reinterpret_cast<float*>(smem);
        sred[tid] = klsum;
        __syncthreads();
        for (int st = 128; st > 0; st >>= 1) {
            if (tid < st) sred[tid] += sred[tid + st];
            __syncthreads();
        }
        if (tid == 0) klq[blockIdx.y * gridDim.x + blockIdx.x] = sred[0];
    }
}

__global__ __launch_bounds__(128)
void sgemm64(const float* __restrict__ A, const float* __restrict__ G,
             const float* __restrict__ lb, float* __restrict__ C)
{
    __shared__ float As[16][64];
    __shared__ float Bs[16][64];
    const int tid = threadIdx.x;
    const int m0 = blockIdx.x * 64;
    const int tx = tid & 15, ty = tid >> 4;
    const int lrow = tid >> 1, lhalf = tid & 1;
    float acc[8][4];
#pragma unroll
    for (int i = 0; i < 8; i++)
#pragma unroll
        for (int j = 0; j < 4; j++) acc[i][j] = 0.f;

    for (int k0 = 0; k0 < IN_DIM; k0 += 16) {
#pragma unroll
        for (int h = 0; h < 2; h++) {
            int kk = lhalf * 8 + h * 4;
            float4 va = *reinterpret_cast<const float4*>(A + (size_t)(m0 + lrow) * IN_DIM + k0 + kk);
            As[kk + 0][lrow] = va.x; As[kk + 1][lrow] = va.y;
            As[kk + 2][lrow] = va.z; As[kk + 3][lrow] = va.w;
            float4 vb = make_float4(0.f, 0.f, 0.f, 0.f);
            if (lrow < KCLS)
                vb = *reinterpret_cast<const float4*>(G + (size_t)lrow * IN_DIM + k0 + kk);
            Bs[kk + 0][lrow] = vb.x; Bs[kk + 1][lrow] = vb.y;
            Bs[kk + 2][lrow] = vb.z; Bs[kk + 3][lrow] = vb.w;
        }
        __syncthreads();
#pragma unroll
        for (int k = 0; k < 16; k++) {
            float4 a0 = *reinterpret_cast<const float4*>(&As[k][ty * 4]);
            float4 a1 = *reinterpret_cast<const float4*>(&As[k][32 + ty * 4]);
            float4 b  = *reinterpret_cast<const float4*>(&Bs[k][tx * 4]);
            float a[8] = {a0.x, a0.y, a0.z, a0.w, a1.x, a1.y, a1.z, a1.w};
            float bb[4] = {b.x, b.y, b.z, b.w};
#pragma unroll
            for (int i = 0; i < 8; i++)
#pragma unroll
                for (int j = 0; j < 4; j++)
                    acc[i][j] = fmaf(a[i], bb[j], acc[i][j]);
        }
        __syncthreads();
    }
#pragma unroll
    for (int i = 0; i < 8; i++) {
        int row = m0 + ((i < 4) ? (ty * 4 + i) : (32 + ty * 4 + i - 4));
#pragma unroll
        for (int j = 0; j < 4; j++) {
            int col = tx * 4 + j;
            if (col < KCLS) C[(size_t)row * KCLS + col] = acc[i][j] + lb[col];
        }
    }
}

// splits
__global__ void split_mat(const float* __restrict__ src, uint32_t* __restrict__ dh,
                          uint32_t* __restrict__ dl, long nPairs, long srcPairs)
{
    long i = (long)blockIdx.x * blockDim.x + threadIdx.x;
    if (i >= nPairs) return;
    float v0 = 0.f, v1 = 0.f;
    if (i < srcPairs) {
        float2 v = reinterpret_cast<const float2*>(src)[i];
        v0 = v.x; v1 = v.y;
    }
    uint32_t H, L;
    split2(v0, v1, H, L);
    dh[i] = H;
    if (dl) dl[i] = L;
}

__global__ void split_w2(const float* __restrict__ W2)
{
    int i = blockIdx.x * blockDim.x + threadIdx.x;
    const int ppr = VDIM / 2;
    if (i >= 2 * VDIM * ppr) return;
    int rr = i / ppr, p = i - rr * ppr;
    int orig = (rr & 1) ? (VDIM + (rr >> 1)) : (rr >> 1);
    float2 v = *reinterpret_cast<const float2*>(W2 + (size_t)orig * VDIM + 2 * p);
    g_w2h[i] = pack_hi2(v.x, v.y);
}

__global__ void split_wd(const float* __restrict__ Wd)
{
    int i = blockIdx.x * blockDim.x + threadIdx.x;
    const int ppr = CAT_LD / 2;
    if (i >= IN_DIM * ppr) return;
    int r = i / ppr, p = i - r * ppr;
    int c0 = 2 * p;
    float v0 = (c0 < CAT_RAW) ? Wd[(size_t)r * CAT_RAW + c0] : 0.f;
    float v1 = (c0 + 1 < CAT_RAW) ? Wd[(size_t)r * CAT_RAW + c0 + 1] : 0.f;
    g_wdh[i] = pack_hi2(v0, v1);
}

__global__ void build_G(const float* __restrict__ W_enc, const float* __restrict__ cb)
{
    int c = blockIdx.x;
    int i = blockIdx.y * 128 + threadIdx.x;
    float s = 0.f;
#pragma unroll 4
    for (int d = 0; d < ENC_DIM; d++)
        s = fmaf(cb[c * ENC_DIM + d], W_enc[(size_t)d * IN_DIM + i], s);
    g_G[(size_t)c * IN_DIM + i] = s;
}
__global__ void build_lb(const float* __restrict__ b_enc, const float* __restrict__ cb)
{
    int c = blockIdx.x;
    int t = threadIdx.x;
    float s = 0.f;
    for (int d = t; d < ENC_DIM; d += 128) s = fmaf(b_enc[d], cb[c * ENC_DIM + d], s);
    __shared__ float sm[128];
    sm[t] = s;
    __syncthreads();
    for (int st = 64; st > 0; st >>= 1) { if (t < st) sm[t] += sm[t + st]; __syncthreads(); }
    if (t == 0) g_lb[c] = sm[0];
}

__global__ void detect_mask_kernel(const unsigned int* __restrict__ w)
{
    __shared__ int s_int, s_flt;
    if (threadIdx.x == 0) { s_int = 1; s_flt = 1; }
    __syncthreads();
    int li = 1, lf = 1;
    for (int i = threadIdx.x; i < 4096; i += blockDim.x) {
        unsigned v = w[i];
        if (v > 1u) li = 0;
        if (v != 0u && v != 0x3F800000u) lf = 0;
    }
    if (!li) atomicAnd(&s_int, 0);
    if (!lf) atomicAnd(&s_flt, 0);
    __syncthreads();
    if (threadIdx.x == 0) g_mask_mode = s_int ? 1 : (s_flt ? 2 : 0);
}

__global__ void argmax_y_kernel(const float* __restrict__ logits,
                                const void* __restrict__ mask,
                                const int* __restrict__ labels,
                                const float* __restrict__ codebook,
                                float* __restrict__ zq)
{
    const int b = blockIdx.x;
    const int lane = threadIdx.x;
    const float NEG = __int_as_float(0xff800000u);
    const float* lr = logits + (size_t)b * KCLS;
    const int k0 = 2 * lane, k1 = 2 * lane + 1;
    float va = (k0 < KCLS) ? lr[k0] : NEG;
    float vb = (k1 < KCLS) ? lr[k1] : NEG;
    float m; int mi;
    if (va >= vb) { m = va; mi = k0; } else { m = vb; mi = k1; }
#pragma unroll
    for (int off = 16; off > 0; off >>= 1) {
        float om = __shfl_xor_sync(0xffffffffu, m, off);
        int oi = __shfl_xor_sync(0xffffffffu, mi, off);
        if (om > m || (om == m && oi < mi)) { m = om; mi = oi; }
    }
    float ea = (k0 < KCLS) ? expf(va - m) : 0.f;
    float eb = (k1 < KCLS) ? expf(vb - m) : 0.f;
    float s = ea + eb;
#pragma unroll
    for (int off = 16; off > 0; off >>= 1) s += __shfl_xor_sync(0xffffffffu, s, off);
    float inv = 1.0f / s;

    int mode = g_mask_mode;
    bool known;
    if (mode == 1)      known = ((const int*)mask)[b] != 0;
    else if (mode == 2) known = ((const float*)mask)[b] != 0.f;
    else                known = ((const unsigned char*)mask)[b] != 0;
    int lab = labels[b];

    float y0 = (k0 < KCLS) ? (known ? (k0 == lab ? 1.f : 0.f) : ea * inv) : 0.f;
    float y1 = (k1 < KCLS) ? (known ? (k1 == lab ? 1.f : 0.f) : eb * inv) : 0.f;
    g_cath[(size_t)b * (CAT_LD / 2) + (VDIM / 2) + lane] = pack_hi2(y0, y1);

    const float* cr = codebook + (size_t)mi * ENC_DIM;
    float* zr = zq + (size_t)b * ENC_DIM;
    for (int i = lane; i < ENC_DIM; i += 32) zr[i] = cr[i];
}

__global__ void kl_reduce_kernel(float* __restrict__ out, int n)
{
    const int t = threadIdx.x;
    float s = 0.f;
    for (int i = t; i < n; i += 256) s += g_klq[i];
    __shared__ float sm[256];
    sm[t] = s;
    __syncthreads();
    for (int st = 128; st > 0; st >>= 1) { if (t < st) sm[t] += sm[t + st]; __syncthreads(); }
    if (t == 0) *out = sm[0] / (float)B_ROWS;
}

static void launch_gemm(int ap,
                        const void* Ah, const void* Al, int lda,
                        const void* Bh, int ldb,
                        const float* bias, float* Cf, void* Ch, void* Cl,
                        int ldc, int nPad, int nOut, int K, int relu, int mode,
                        const float* bias2, const float* eps, float* klq)
{
    dim3 grid(nPad / 128, B_ROWS / 64);
    if (ap == 1) {
        cudaFuncSetAttribute(gemm_f16x<1>, cudaFuncAttributeMaxDynamicSharedMemorySize, GEMM_DYN);
        gemm_f16x<1><<<grid, 256, GEMM_DYN>>>(
            (const uint16_t*)Ah, (const uint16_t*)Al, lda, (const uint16_t*)Bh, ldb,
            bias, Cf, (uint16_t*)Ch, (uint16_t*)Cl, ldc, nOut, K, relu, mode,
            bias2, eps, klq);
    } else {
        cudaFuncSetAttribute(gemm_f16x<2>, cudaFuncAttributeMaxDynamicSharedMemorySize, GEMM_DYN);
        gemm_f16x<2><<<grid, 256, GEMM_DYN>>>(
            (const uint16_t*)Ah, (const uint16_t*)Al, lda, (const uint16_t*)Bh, ldb,
            bias, Cf, (uint16_t*)Ch, (uint16_t*)Cl, ldc, nOut, K, relu, mode,
            bias2, eps, klq);
    }
}

extern "C" void kernel_launch(void* const* d_in, const int* in_sizes, int n_in,
                              void* d_out, int out_size)
{
    const float* x        = (const float*)d_in[0];
    const void*  mask     = d_in[1];
    const int*   labels   = (const int*)d_in[2];
    const float* eps      = (const float*)d_in[3];
    const float* W_enc    = (const float*)d_in[4];
    const float* b_enc    = (const float*)d_in[5];
    const float* codebook = (const float*)d_in[6];
    const float* W1       = (const float*)d_in[7];
    const float* b1       = (const float*)d_in[8];
    const float* W2       = (const float*)d_in[9];
    const float* b2       = (const float*)d_in[10];
    const float* Wd       = (const float*)d_in[11];
    const float* bd       = (const float*)d_in[12];
    float* out = (float*)d_out;

    void *p_xh, *p_wch, *p_w2h, *p_wdh, *p_hh, *p_hl, *p_cath;
    float *p_G, *p_lb, *p_klq, *p_ze, *p_zq, *p_lg, *p_kl;
    cudaGetSymbolAddress(&p_xh, g_xh);
    cudaGetSymbolAddress(&p_wch, g_wch);
    cudaGetSymbolAddress(&p_w2h, g_w2h);
    cudaGetSymbolAddress(&p_wdh, g_wdh);
    cudaGetSymbolAddress(&p_hh, g_hh);   cudaGetSymbolAddress(&p_hl, g_hl);
    cudaGetSymbolAddress(&p_cath, g_cath);
    cudaGetSymbolAddress((void**)&p_G,  g_G);
    cudaGetSymbolAddress((void**)&p_lb, g_lb);
    cudaGetSymbolAddress((void**)&p_klq, g_klq);
    cudaGetSymbolAddress((void**)&p_ze, g_ze_s);
    cudaGetSymbolAddress((void**)&p_zq, g_zq_s);
    cudaGetSymbolAddress((void**)&p_lg, g_lg_s);
    cudaGetSymbolAddress((void**)&p_kl, g_kl_s);

    const size_t full_elems = (size_t)B_ROWS * (IN_DIM + ENC_DIM + ENC_DIM + KCLS) + 1;
    const bool full = ((size_t)out_size >= full_elems);
    float* xt = out;
    float* ze = full ? out + (size_t)B_ROWS * IN_DIM : p_ze;
    float* zq = full ? ze + (size_t)B_ROWS * ENC_DIM : p_zq;
    float* lg = full ? zq + (size_t)B_ROWS * ENC_DIM : p_lg;
    float* kl = full ? lg + (size_t)B_ROWS * KCLS    : p_kl;

    {
        long np = (long)B_ROWS * IN_DIM / 2;
        split_mat<<<(unsigned)((np + 255) / 256), 256>>>(x, (uint32_t*)p_xh, nullptr, np, np);
        long wep = (long)512 * IN_DIM / 2, wes = (long)ENC_DIM * IN_DIM / 2;
        split_mat<<<(unsigned)((wep + 255) / 256), 256>>>(W_enc, (uint32_t*)p_wch, nullptr, wep, wes);
        long w1p = (long)VDIM * IN_DIM / 2;
        split_mat<<<(unsigned)((w1p + 255) / 256), 256>>>(W1,
            (uint32_t*)p_wch + (size_t)512 * IN_DIM / 2, nullptr, w1p, w1p);
        split_w2<<<(2 * VDIM * (VDIM / 2) + 255) / 256, 256>>>(W2);
        split_wd<<<(IN_DIM * (CAT_LD / 2) + 255) / 256, 256>>>(Wd);
    }
    detect_mask_kernel<<<1, 256>>>((const unsigned int*)mask);
    build_G<<<dim3(KCLS, IN_DIM / 128), 128>>>(W_enc, codebook);
    build_lb<<<KCLS, 128>>>(b_enc, codebook);

    sgemm64<<<B_ROWS / 64, 128>>>(x, p_G, p_lb, lg);

    // combined ze|h (mode 3) — 1-pass fp16, h written split (ml needs hi+lo A)
    launch_gemm(1, p_xh, nullptr, IN_DIM, p_wch, IN_DIM, b_enc,
                ze, p_hh, p_hl, ENC_DIM, NCOMB, ENC_DIM, IN_DIM, 0, 3,
                b1, nullptr, nullptr);
    // ml + fused VAE (mode 2) — 2-pass (accuracy anchor), cat written hi-only
    launch_gemm(2, p_hh, p_hl, VDIM, p_w2h, VDIM, b2,
                nullptr, p_cath, nullptr, CAT_LD, 2 * VDIM, 2 * VDIM, VDIM, 0, 2,
                nullptr, eps, p_klq);

    argmax_y_kernel<<<B_ROWS, 32>>>(lg, mask, labels, codebook, zq);
    kl_reduce_kernel<<<1, 256>>>(kl, (2 * VDIM / 128) * (B_ROWS / 64));

    // decoder — 1-pass fp16 (A = cat hi)
    launch_gemm(1, p_cath, nullptr, CAT_LD, p_wdh, CAT_LD, bd,
                xt, nullptr, nullptr, IN_DIM, IN_DIM, IN_DIM, CAT_LD, 0, 0,
                nullptr, nullptr, nullptr);
}

// round 16
// speedup vs baseline: 3.6054x; 1.1804x over previous
#include <cuda_runtime.h>
#include <cuda_fp16.h>
#include <math.h>
#include <stdint.h>

#define B_ROWS 16384
#define IN_DIM 768
#define ENC_DIM 500
#define KCLS 43
#define VDIM 1024
#define CAT_RAW 1067
#define CAT_LD  1088
#define NCOMB 1536

__device__ uint32_t g_xh [(size_t)B_ROWS * IN_DIM / 2];
__device__ uint32_t g_wch[(size_t)NCOMB * IN_DIM / 2];
__device__ uint32_t g_w2h[(size_t)2 * VDIM * VDIM / 2];
__device__ uint32_t g_wdh[(size_t)IN_DIM * CAT_LD / 2];
__device__ uint32_t g_hh [(size_t)B_ROWS * VDIM / 2];
__device__ uint32_t g_cath[(size_t)B_ROWS * CAT_LD / 2];
__device__ float g_G  [(size_t)KCLS * IN_DIM];
__device__ float g_lb [KCLS];
__device__ float g_klq[4096];
__device__ float g_ze_s[(size_t)B_ROWS * ENC_DIM];
__device__ float g_zq_s[(size_t)B_ROWS * ENC_DIM];
__device__ float g_lg_s[(size_t)B_ROWS * KCLS];
__device__ float g_kl_s[1];
__device__ int   g_mask_mode;

__device__ __forceinline__ uint32_t smem_to_u32(const void* p) {
    uint32_t a;
    asm("{ .reg .u64 t; cvta.to.shared.u64 t, %1; cvt.u32.u64 %0, t; }" : "=r"(a) : "l"(p));
    return a;
}
#define SWZ(b) ((b) ^ (((b) >> 3) & 0x70))
#define CP16(d, s)  asm volatile("cp.async.cg.shared.global [%0], [%1], 16;" :: "r"(d), "l"(s) : "memory")
#define CP_COMMIT() asm volatile("cp.async.commit_group;" ::: "memory")
#define CP_WAIT0()  asm volatile("cp.async.wait_group 0;" ::: "memory")
#define CP_WAIT1()  asm volatile("cp.async.wait_group 1;" ::: "memory")

__device__ __forceinline__ void ldsm_x4(uint32_t* r, uint32_t addr) {
    asm volatile("ldmatrix.sync.aligned.m8n8.x4.shared.b16 {%0,%1,%2,%3}, [%4];"
        : "=r"(r[0]), "=r"(r[1]), "=r"(r[2]), "=r"(r[3]) : "r"(addr));
}
__device__ __forceinline__ void mma_f16(float* c, const uint32_t* a, const uint32_t* b) {
    asm volatile("mma.sync.aligned.m16n8k16.row.col.f32.f16.f16.f32 "
        "{%0,%1,%2,%3}, {%4,%5,%6,%7}, {%8,%9}, {%0,%1,%2,%3};"
        : "+f"(c[0]), "+f"(c[1]), "+f"(c[2]), "+f"(c[3])
        : "r"(a[0]), "r"(a[1]), "r"(a[2]), "r"(a[3]), "r"(b[0]), "r"(b[1]));
}
__device__ __forceinline__ void split2(float v0, float v1, uint32_t& H, uint32_t& L) {
    __half h0 = __float2half_rn(v0), h1 = __float2half_rn(v1);
    float r0 = v0 - __half2float(h0), r1 = v1 - __half2float(h1);
    __half l0 = __float2half_rn(r0), l1 = __float2half_rn(r1);
    __half2 hp = __halves2half2(h0, h1), lp = __halves2half2(l0, l1);
    H = *reinterpret_cast<uint32_t*>(&hp);
    L = *reinterpret_cast<uint32_t*>(&lp);
}
__device__ __forceinline__ uint32_t pack_hi2(float v0, float v1) {
    __half2 hp = __halves2half2(__float2half_rn(v0), __float2half_rn(v1));
    return *reinterpret_cast<uint32_t*>(&hp);
}
__device__ __forceinline__ float fast_exp(float x) {
    float r;
    asm("ex2.approx.ftz.f32 %0, %1;" : "=f"(r) : "f"(x * 1.4426950408889634f));
    return r;
}

// ---------------- fp16 GEMM (AP passes: 1 = A*Bh, 2 = (Ah+Al)*Bh) ----------------
#define ST_BYTES 32768u
#define OFF_AL 8192u
#define OFF_BH 16384u
#define GEMM_DYN (2 * 32768 + 1024)

template<int AP>
__device__ __forceinline__ void load_chunk(uint32_t base, int tid, int m0, int n0, int k0,
    const uint16_t* Ah, const uint16_t* Al, int lda,
    const uint16_t* Bh, int ldb)
{
#pragma unroll
    for (int half = 0; half < 2; half++) {
        int idx = half * 256 + tid;
        int row = idx >> 3, u = idx & 7;
        uint32_t off = SWZ((uint32_t)(row * 128 + u * 16));
        size_t ao = (size_t)(m0 + row) * lda + k0 + u * 8;
        CP16(base + off, Ah + ao);
        if (AP == 2) CP16(base + OFF_AL + off, Al + ao);
    }
#pragma unroll
    for (int it = 0; it < 4; it++) {
        int idx = it * 256 + tid;
        int row = idx >> 3, u = idx & 7;
        uint32_t off = SWZ((uint32_t)(row * 128 + u * 16));
        size_t bo = (size_t)(n0 + row) * ldb + k0 + u * 8;
        CP16(base + OFF_BH + off, Bh + bo);
    }
}

// mode 0: fp32 C; mode 1: fp16-hi C (Cl null) or split; mode 2: fused VAE; mode 3: combined ze|h
template<int AP>
__global__ __launch_bounds__(256, 2)
void gemm_f16x(const uint16_t* __restrict__ Ah, const uint16_t* __restrict__ Al, int lda,
               const uint16_t* __restrict__ Bh, int ldb,
               const float* __restrict__ bias,
               float* __restrict__ Cf, uint16_t* __restrict__ Ch, uint16_t* __restrict__ Cl,
               int ldc, int nOut, int K, int relu, int mode,
               const float* __restrict__ bias2, const float* __restrict__ eps,
               float* __restrict__ klq)
{
    extern __shared__ char smem[];
    const uint32_t tiles = (smem_to_u32(smem) + 1023) & ~1023u;
    const int tid = threadIdx.x, wid = tid >> 5, lane = tid & 31;
    const int m0 = blockIdx.y * 64, n0 = blockIdx.x * 128;
    const int wm = (wid >> 2) * 32, wn = (wid & 3) * 32;

    float acc[2][4][4];
#pragma unroll
    for (int i = 0; i < 2; i++)
#pragma unroll
        for (int j = 0; j < 4; j++)
#pragma unroll
            for (int q = 0; q < 4; q++) acc[i][j][q] = 0.f;

    const uint32_t aRowByte = (uint32_t)(wm + (lane & 15)) * 128u;
    const uint32_t aKoff    = (uint32_t)((lane >> 4) * 16);
    const uint32_t bRowByte = (uint32_t)(wn + (lane & 7) + ((lane >> 4) << 3)) * 128u;
    const uint32_t bKoff    = (uint32_t)(((lane >> 3) & 1) * 16);

    const int S = K / 64;
    load_chunk<AP>(tiles, tid, m0, n0, 0, Ah, Al, lda, Bh, ldb);
    CP_COMMIT();

    for (int s = 0; s < S; s++) {
        if (s + 1 < S) {
            load_chunk<AP>(tiles + ((s + 1) & 1) * ST_BYTES, tid, m0, n0, (s + 1) * 64,
                           Ah, Al, lda, Bh, ldb);
            CP_COMMIT();
            CP_WAIT1();
        } else {
            CP_WAIT0();
        }
        __syncthreads();

        const uint32_t pah = tiles + (s & 1) * ST_BYTES;
        const uint32_t pal = pah + OFF_AL, pbh = pah + OFF_BH;
#pragma unroll
        for (int kk = 0; kk < 4; kk++) {
            const uint32_t kb = (uint32_t)(kk * 32);
            uint32_t ah[2][4], al[2][4], bh[2][4];
#pragma unroll
            for (int mt = 0; mt < 2; mt++) {
                uint32_t ro = SWZ(aRowByte + (uint32_t)(mt * 2048) + kb + aKoff);
                ldsm_x4(ah[mt], pah + ro);
                if (AP == 2) ldsm_x4(al[mt], pal + ro);
            }
#pragma unroll
            for (int nb = 0; nb < 2; nb++) {
                uint32_t ro = SWZ(bRowByte + (uint32_t)(nb * 2048) + kb + bKoff);
                ldsm_x4(bh[nb], pbh + ro);
            }
#pragma unroll
            for (int t2 = 0; t2 < AP; t2++)
#pragma unroll
                for (int mt = 0; mt < 2; mt++)
#pragma unroll
                    for (int nt = 0; nt < 4; nt++) {
                        const uint32_t* ap = t2 ? al[mt] : ah[mt];
                        mma_f16(acc[mt][nt], ap, &bh[nt >> 1][(nt & 1) * 2]);
                    }
        }
        __syncthreads();
    }

    // ---- epilogue ----
    int emode = mode;
    const float* eb = bias;
    int erelu = relu;
    int cbase = n0;
    int ldcEff = ldc;
    if (mode == 3) {
        if (n0 < 512) { emode = 0; }
        else { emode = 1; eb = bias2; erelu = 1; cbase = n0 - 512; ldcEff = VDIM; }
    }

    if (emode == 0) {
#pragma unroll
        for (int mt = 0; mt < 2; mt++) {
            const int r0 = m0 + wm + mt * 16 + (lane >> 2);
            float* crow0 = Cf + (size_t)r0 * ldcEff;
            float* crow8 = Cf + (size_t)(r0 + 8) * ldcEff;
#pragma unroll
            for (int nt = 0; nt < 4; nt++) {
                const int c = cbase + wn + nt * 8 + (lane & 3) * 2;
                if (c >= nOut) continue;
                float b0 = eb[c], b1 = eb[c + 1];
                float v0 = acc[mt][nt][0] + b0, v1 = acc[mt][nt][1] + b1;
                float v2 = acc[mt][nt][2] + b0, v3 = acc[mt][nt][3] + b1;
                if (erelu) {
                    v0 = fmaxf(v0, 0.f); v1 = fmaxf(v1, 0.f);
                    v2 = fmaxf(v2, 0.f); v3 = fmaxf(v3, 0.f);
                }
                *reinterpret_cast<float2*>(crow0 + c) = make_float2(v0, v1);
                *reinterpret_cast<float2*>(crow8 + c) = make_float2(v2, v3);
            }
        }
    } else if (emode == 1) {
#pragma unroll
        for (int mt = 0; mt < 2; mt++) {
            const int r0 = m0 + wm + mt * 16 + (lane >> 2);
#pragma unroll
            for (int nt = 0; nt < 4; nt++) {
                const int c = cbase + wn + nt * 8 + (lane & 3) * 2;
                float b0 = eb[c], b1 = eb[c + 1];
                float v0 = acc[mt][nt][0] + b0, v1 = acc[mt][nt][1] + b1;
                float v2 = acc[mt][nt][2] + b0, v3 = acc[mt][nt][3] + b1;
                if (erelu) {
                    v0 = fmaxf(v0, 0.f); v1 = fmaxf(v1, 0.f);
                    v2 = fmaxf(v2, 0.f); v3 = fmaxf(v3, 0.f);
                }
                if (Cl) {
                    uint32_t H, L;
                    split2(v0, v1, H, L);
                    *reinterpret_cast<uint32_t*>(Ch + (size_t)r0 * ldcEff + c) = H;
                    *reinterpret_cast<uint32_t*>(Cl + (size_t)r0 * ldcEff + c) = L;
                    split2(v2, v3, H, L);
                    *reinterpret_cast<uint32_t*>(Ch + (size_t)(r0 + 8) * ldcEff + c) = H;
                    *reinterpret_cast<uint32_t*>(Cl + (size_t)(r0 + 8) * ldcEff + c) = L;
                } else {
                    *reinterpret_cast<uint32_t*>(Ch + (size_t)r0 * ldcEff + c) = pack_hi2(v0, v1);
                    *reinterpret_cast<uint32_t*>(Ch + (size_t)(r0 + 8) * ldcEff + c) = pack_hi2(v2, v3);
                }
            }
        }
    } else {
        // mode 2: fused reparam + KL; z written hi-only
        float klsum = 0.f;
#pragma unroll
        for (int mt = 0; mt < 2; mt++) {
            const int r0 = m0 + wm + mt * 16 + (lane >> 2);
#pragma unroll
            for (int nt = 0; nt < 4; nt++) {
                const int c = n0 + wn + nt * 8 + (lane & 3) * 2;
                const int i = c >> 1;
                float bmu = bias[i], blv = bias[VDIM + i];
#pragma unroll
                for (int h = 0; h < 2; h++) {
                    const int r = r0 + h * 8;
                    float mu = acc[mt][nt][2 * h + 0] + bmu;
                    float lv = acc[mt][nt][2 * h + 1] + blv;
                    klsum += 0.5f * (fast_exp(lv) + mu * mu - 1.0f - lv);
                    float z = fmaf(fast_exp(0.5f * lv), eps[(size_t)r * VDIM + i], mu);
                    __half zh = __float2half_rn(z);
                    Ch[(size_t)r * ldc + i] = *reinterpret_cast<uint16_t*>(&zh);
                }
            }
        }
        float* sred = reinterpret_cast<float*>(smem);
        sred[tid] = klsum;
        __syncthreads();
        for (int st = 128; st > 0; st >>= 1) {
            if (tid < st) sred[tid] += sred[tid + st];
            __syncthreads();
        }
        if (tid == 0) klq[blockIdx.y * gridDim.x + blockIdx.x] = sred[0];
    }
}

__global__ __launch_bounds__(128)
void sgemm64(const float* __restrict__ A, const float* __restrict__ G,
             const float* __restrict__ lb, float* __restrict__ C)
{
    __shared__ float As[16][64];
    __shared__ float Bs[16][64];
    const int tid = threadIdx.x;
    const int m0 = blockIdx.x * 64;
    const int tx = tid & 15, ty = tid >> 4;
    const int lrow = tid >> 1, lhalf = tid & 1;
    float acc[8][4];
#pragma unroll
    for (int i = 0; i < 8; i++)
#pragma unroll
        for (int j = 0; j < 4; j++) acc[i][j] = 0.f;

    for (int k0 = 0; k0 < IN_DIM; k0 += 16) {
#pragma unroll
        for (int h = 0; h < 2; h++) {
            int kk = lhalf * 8 + h * 4;
            float4 va = *reinterpret_cast<const float4*>(A + (size_t)(m0 + lrow) * IN_DIM + k0 + kk);
            As[kk + 0][lrow] = va.x; As[kk + 1][lrow] = va.y;
            As[kk + 2][lrow] = va.z; As[kk + 3][lrow] = va.w;
            float4 vb = make_float4(0.f, 0.f, 0.f, 0.f);
            if (lrow < KCLS)
                vb = *reinterpret_cast<const float4*>(G + (size_t)lrow * IN_DIM + k0 + kk);
            Bs[kk + 0][lrow] = vb.x; Bs[kk + 1][lrow] = vb.y;
            Bs[kk + 2][lrow] = vb.z; Bs[kk + 3][lrow] = vb.w;
        }
        __syncthreads();
#pragma unroll
        for (int k = 0; k < 16; k++) {
            float4 a0 = *reinterpret_cast<const float4*>(&As[k][ty * 4]);
            float4 a1 = *reinterpret_cast<const float4*>(&As[k][32 + ty * 4]);
            float4 b  = *reinterpret_cast<const float4*>(&Bs[k][tx * 4]);
            float a[8] = {a0.x, a0.y, a0.z, a0.w, a1.x, a1.y, a1.z, a1.w};
            float bb[4] = {b.x, b.y, b.z, b.w};
#pragma unroll
            for (int i = 0; i < 8; i++)
#pragma unroll
                for (int j = 0; j < 4; j++)
                    acc[i][j] = fmaf(a[i], bb[j], acc[i][j]);
        }
        __syncthreads();
    }
#pragma unroll
    for (int i = 0; i < 8; i++) {
        int row = m0 + ((i < 4) ? (ty * 4 + i) : (32 + ty * 4 + i - 4));
#pragma unroll
        for (int j = 0; j < 4; j++) {
            int col = tx * 4 + j;
            if (col < KCLS) C[(size_t)row * KCLS + col] = acc[i][j] + lb[col];
        }
    }
}

__global__ void split_mat(const float* __restrict__ src, uint32_t* __restrict__ dh,
                          long nPairs, long srcPairs)
{
    long i = (long)blockIdx.x * blockDim.x + threadIdx.x;
    if (i >= nPairs) return;
    float v0 = 0.f, v1 = 0.f;
    if (i < srcPairs) {
        float2 v = reinterpret_cast<const float2*>(src)[i];
        v0 = v.x; v1 = v.y;
    }
    dh[i] = pack_hi2(v0, v1);
}

__global__ void split_w2(const float* __restrict__ W2)
{
    int i = blockIdx.x * blockDim.x + threadIdx.x;
    const int ppr = VDIM / 2;
    if (i >= 2 * VDIM * ppr) return;
    int rr = i / ppr, p = i - rr * ppr;
    int orig = (rr & 1) ? (VDIM + (rr >> 1)) : (rr >> 1);
    float2 v = *reinterpret_cast<const float2*>(W2 + (size_t)orig * VDIM + 2 * p);
    g_w2h[i] = pack_hi2(v.x, v.y);
}

__global__ void split_wd(const float* __restrict__ Wd)
{
    int i = blockIdx.x * blockDim.x + threadIdx.x;
    const int ppr = CAT_LD / 2;
    if (i >= IN_DIM * ppr) return;
    int r = i / ppr, p = i - r * ppr;
    int c0 = 2 * p;
    float v0 = (c0 < CAT_RAW) ? Wd[(size_t)r * CAT_RAW + c0] : 0.f;
    float v1 = (c0 + 1 < CAT_RAW) ? Wd[(size_t)r * CAT_RAW + c0 + 1] : 0.f;
    g_wdh[i] = pack_hi2(v0, v1);
}

__global__ void build_G(const float* __restrict__ W_enc, const float* __restrict__ cb)
{
    int c = blockIdx.x;
    int i = blockIdx.y * 128 + threadIdx.x;
    float s = 0.f;
#pragma unroll 4
    for (int d = 0; d < ENC_DIM; d++)
        s = fmaf(cb[c * ENC_DIM + d], W_enc[(size_t)d * IN_DIM + i], s);
    g_G[(size_t)c * IN_DIM + i] = s;
}
__global__ void build_lb(const float* __restrict__ b_enc, const float* __restrict__ cb)
{
    int c = blockIdx.x;
    int t = threadIdx.x;
    float s = 0.f;
    for (int d = t; d < ENC_DIM; d += 128) s = fmaf(b_enc[d], cb[c * ENC_DIM + d], s);
    __shared__ float sm[128];
    sm[t] = s;
    __syncthreads();
    for (int st = 64; st > 0; st >>= 1) { if (t < st) sm[t] += sm[t + st]; __syncthreads(); }
    if (t == 0) g_lb[c] = sm[0];
}

__global__ void detect_mask_kernel(const unsigned int* __restrict__ w)
{
    __shared__ int s_int, s_flt;
    if (threadIdx.x == 0) { s_int = 1; s_flt = 1; }
    __syncthreads();
    int li = 1, lf = 1;
    for (int i = threadIdx.x; i < 4096; i += blockDim.x) {
        unsigned v = w[i];
        if (v > 1u) li = 0;
        if (v != 0u && v != 0x3F800000u) lf = 0;
    }
    if (!li) atomicAnd(&s_int, 0);
    if (!lf) atomicAnd(&s_flt, 0);
    __syncthreads();
    if (threadIdx.x == 0) g_mask_mode = s_int ? 1 : (s_flt ? 2 : 0);
}

__global__ void argmax_y_kernel(const float* __restrict__ logits,
                                const void* __restrict__ mask,
                                const int* __restrict__ labels,
                                const float* __restrict__ codebook,
                                float* __restrict__ zq)
{
    const int b = blockIdx.x;
    const int lane = threadIdx.x;
    const float NEG = __int_as_float(0xff800000u);
    const float* lr = logits + (size_t)b * KCLS;
    const int k0 = 2 * lane, k1 = 2 * lane + 1;
    float va = (k0 < KCLS) ? lr[k0] : NEG;
    float vb = (k1 < KCLS) ? lr[k1] : NEG;
    float m; int mi;
    if (va >= vb) { m = va; mi = k0; } else { m = vb; mi = k1; }
#pragma unroll
    for (int off = 16; off > 0; off >>= 1) {
        float om = __shfl_xor_sync(0xffffffffu, m, off);
        int oi = __shfl_xor_sync(0xffffffffu, mi, off);
        if (om > m || (om == m && oi < mi)) { m = om; mi = oi; }
    }
    float ea = (k0 < KCLS) ? expf(va - m) : 0.f;
    float eb = (k1 < KCLS) ? expf(vb - m) : 0.f;
    float s = ea + eb;
#pragma unroll
    for (int off = 16; off > 0; off >>= 1) s += __shfl_xor_sync(0xffffffffu, s, off);
    float inv = 1.0f / s;

    int mode = g_mask_mode;
    bool known;
    if (mode == 1)      known = ((const int*)mask)[b] != 0;
    else if (mode == 2) known = ((const float*)mask)[b] != 0.f;
    else                known = ((const unsigned char*)mask)[b] != 0;
    int lab = labels[b];

    float y0 = (k0 < KCLS) ? (known ? (k0 == lab ? 1.f : 0.f) : ea * inv) : 0.f;
    float y1 = (k1 < KCLS) ? (known ? (k1 == lab ? 1.f : 0.f) : eb * inv) : 0.f;
    g_cath[(size_t)b * (CAT_LD / 2) + (VDIM / 2) + lane] = pack_hi2(y0, y1);

    const float* cr = codebook + (size_t)mi * ENC_DIM;
    float* zr = zq + (size_t)b * ENC_DIM;
    for (int i = lane; i < ENC_DIM; i += 32) zr[i] = cr[i];
}

__global__ void kl_reduce_kernel(float* __restrict__ out, int n)
{
    const int t = threadIdx.x;
    float s = 0.f;
    for (int i = t; i < n; i += 256) s += g_klq[i];
    __shared__ float sm[256];
    sm[t] = s;
    __syncthreads();
    for (int st = 128; st > 0; st >>= 1) { if (t < st) sm[t] += sm[t + st]; __syncthreads(); }
    if (t == 0) *out = sm[0] / (float)B_ROWS;
}

static void launch_gemm(const void* Ah, int lda,
                        const void* Bh, int ldb,
                        const float* bias, float* Cf, void* Ch, void* Cl,
                        int ldc, int nPad, int nOut, int K, int relu, int mode,
                        const float* bias2, const float* eps, float* klq)
{
    cudaFuncSetAttribute(gemm_f16x<1>, cudaFuncAttributeMaxDynamicSharedMemorySize, GEMM_DYN);
    dim3 grid(nPad / 128, B_ROWS / 64);
    gemm_f16x<1><<<grid, 256, GEMM_DYN>>>(
        (const uint16_t*)Ah, nullptr, lda, (const uint16_t*)Bh, ldb,
        bias, Cf, (uint16_t*)Ch, (uint16_t*)Cl, ldc, nOut, K, relu, mode,
        bias2, eps, klq);
}

extern "C" void kernel_launch(void* const* d_in, const int* in_sizes, int n_in,
                              void* d_out, int out_size)
{
    const float* x        = (const float*)d_in[0];
    const void*  mask     = d_in[1];
    const int*   labels   = (const int*)d_in[2];
    const float* eps      = (const float*)d_in[3];
    const float* W_enc    = (const float*)d_in[4];
    const float* b_enc    = (const float*)d_in[5];
    const float* codebook = (const float*)d_in[6];
    const float* W1       = (const float*)d_in[7];
    const float* b1       = (const float*)d_in[8];
    const float* W2       = (const float*)d_in[9];
    const float* b2       = (const float*)d_in[10];
    const float* Wd       = (const float*)d_in[11];
    const float* bd       = (const float*)d_in[12];
    float* out = (float*)d_out;

    void *p_xh, *p_wch, *p_w2h, *p_wdh, *p_hh, *p_cath;
    float *p_G, *p_lb, *p_klq, *p_ze, *p_zq, *p_lg, *p_kl;
    cudaGetSymbolAddress(&p_xh, g_xh);
    cudaGetSymbolAddress(&p_wch, g_wch);
    cudaGetSymbolAddress(&p_w2h, g_w2h);
    cudaGetSymbolAddress(&p_wdh, g_wdh);
    cudaGetSymbolAddress(&p_hh, g_hh);
    cudaGetSymbolAddress(&p_cath, g_cath);
    cudaGetSymbolAddress((void**)&p_G,  g_G);
    cudaGetSymbolAddress((void**)&p_lb, g_lb);
    cudaGetSymbolAddress((void**)&p_klq, g_klq);
    cudaGetSymbolAddress((void**)&p_ze, g_ze_s);
    cudaGetSymbolAddress((void**)&p_zq, g_zq_s);
    cudaGetSymbolAddress((void**)&p_lg, g_lg_s);
    cudaGetSymbolAddress((void**)&p_kl, g_kl_s);

    const size_t full_elems = (size_t)B_ROWS * (IN_DIM + ENC_DIM + ENC_DIM + KCLS) + 1;
    const bool full = ((size_t)out_size >= full_elems);
    float* xt = out;
    float* ze = full ? out + (size_t)B_ROWS * IN_DIM : p_ze;
    float* zq = full ? ze + (size_t)B_ROWS * ENC_DIM : p_zq;
    float* lg = full ? zq + (size_t)B_ROWS * ENC_DIM : p_lg;
    float* kl = full ? lg + (size_t)B_ROWS * KCLS    : p_kl;

    {
        long np = (long)B_ROWS * IN_DIM / 2;
        split_mat<<<(unsigned)((np + 255) / 256), 256>>>(x, (uint32_t*)p_xh, np, np);
        long wep = (long)512 * IN_DIM / 2, wes = (long)ENC_DIM * IN_DIM / 2;
        split_mat<<<(unsigned)((wep + 255) / 256), 256>>>(W_enc, (uint32_t*)p_wch, wep, wes);
        long w1p = (long)VDIM * IN_DIM / 2;
        split_mat<<<(unsigned)((w1p + 255) / 256), 256>>>(W1,
            (uint32_t*)p_wch + (size_t)512 * IN_DIM / 2, w1p, w1p);
        split_w2<<<(2 * VDIM * (VDIM / 2) + 255) / 256, 256>>>(W2);
        split_wd<<<(IN_DIM * (CAT_LD / 2) + 255) / 256, 256>>>(Wd);
    }
    detect_mask_kernel<<<1, 256>>>((const unsigned int*)mask);
    build_G<<<dim3(KCLS, IN_DIM / 128), 128>>>(W_enc, codebook);
    build_lb<<<KCLS, 128>>>(b_enc, codebook);

    sgemm64<<<B_ROWS / 64, 128>>>(x, p_G, p_lb, lg);

    // combined ze|h (mode 3) — 1-pass fp16; h written hi-only (Cl = null)
    launch_gemm(p_xh, IN_DIM, p_wch, IN_DIM, b_enc,
                ze, p_hh, nullptr, ENC_DIM, NCOMB, ENC_DIM, IN_DIM, 0, 3,
                b1, nullptr, nullptr);
    // ml + fused VAE (mode 2) — 1-pass fp16, cat hi-only
    launch_gemm(p_hh, VDIM, p_w2h, VDIM, b2,
                nullptr, p_cath, nullptr, CAT_LD, 2 * VDIM, 2 * VDIM, VDIM, 0, 2,
                nullptr, eps, p_klq);

    argmax_y_kernel<<<B_ROWS, 32>>>(lg, mask, labels, codebook, zq);
    kl_reduce_kernel<<<1, 256>>>(kl, (2 * VDIM / 128) * (B_ROWS / 64));

    // decoder — 1-pass fp16
    launch_gemm(p_cath, CAT_LD, p_wdh, CAT_LD, bd,
                xt, nullptr, nullptr, IN_DIM, IN_DIM, IN_DIM, CAT_LD, 0, 0,
                nullptr, nullptr, nullptr);
}

// round 17
// speedup vs baseline: 4.0288x; 1.1174x over previous
#include <cuda_runtime.h>
#include <cuda_fp16.h>
#include <math.h>
#include <stdint.h>

#define B_ROWS 16384
#define IN_DIM 768
#define ENC_DIM 500
#define KCLS 43
#define VDIM 1024
#define CAT_RAW 1067
#define CAT_LD  1088
#define NCOMB 1536

__device__ uint32_t g_xh [(size_t)B_ROWS * IN_DIM / 2];
__device__ uint32_t g_wch[(size_t)NCOMB * IN_DIM / 2];
__device__ uint32_t g_w2h[(size_t)2 * VDIM * VDIM / 2];
__device__ uint32_t g_wdh[(size_t)IN_DIM * CAT_LD / 2];
__device__ uint32_t g_hh [(size_t)B_ROWS * VDIM / 2];
__device__ uint32_t g_cath[(size_t)B_ROWS * CAT_LD / 2];
__device__ float g_G  [(size_t)KCLS * IN_DIM];
__device__ float g_lb [KCLS];
__device__ float g_klq[4096];
__device__ float g_ze_s[(size_t)B_ROWS * ENC_DIM];
__device__ float g_zq_s[(size_t)B_ROWS * ENC_DIM];
__device__ float g_lg_s[(size_t)B_ROWS * KCLS];
__device__ float g_kl_s[1];
__device__ int   g_mask_mode;

__device__ __forceinline__ uint32_t smem_to_u32(const void* p) {
    uint32_t a;
    asm("{ .reg .u64 t; cvta.to.shared.u64 t, %1; cvt.u32.u64 %0, t; }" : "=r"(a) : "l"(p));
    return a;
}
#define SWZ(b) ((b) ^ (((b) >> 3) & 0x70))
#define CP16(d, s)  asm volatile("cp.async.cg.shared.global [%0], [%1], 16;" :: "r"(d), "l"(s) : "memory")
#define CP_COMMIT() asm volatile("cp.async.commit_group;" ::: "memory")
#define CP_WAIT0()  asm volatile("cp.async.wait_group 0;" ::: "memory")
#define CP_WAIT1()  asm volatile("cp.async.wait_group 1;" ::: "memory")

__device__ __forceinline__ void ldsm_x4(uint32_t* r, uint32_t addr) {
    asm volatile("ldmatrix.sync.aligned.m8n8.x4.shared.b16 {%0,%1,%2,%3}, [%4];"
        : "=r"(r[0]), "=r"(r[1]), "=r"(r[2]), "=r"(r[3]) : "r"(addr));
}
__device__ __forceinline__ void mma_f16(float* c, const uint32_t* a, const uint32_t* b) {
    asm volatile("mma.sync.aligned.m16n8k16.row.col.f32.f16.f16.f32 "
        "{%0,%1,%2,%3}, {%4,%5,%6,%7}, {%8,%9}, {%0,%1,%2,%3};"
        : "+f"(c[0]), "+f"(c[1]), "+f"(c[2]), "+f"(c[3])
        : "r"(a[0]), "r"(a[1]), "r"(a[2]), "r"(a[3]), "r"(b[0]), "r"(b[1]));
}
__device__ __forceinline__ uint32_t pack_hi2(float v0, float v1) {
    __half2 hp = __halves2half2(__float2half_rn(v0), __float2half_rn(v1));
    return *reinterpret_cast<uint32_t*>(&hp);
}
__device__ __forceinline__ float fast_exp(float x) {
    float r;
    asm("ex2.approx.ftz.f32 %0, %1;" : "=f"(r) : "f"(x * 1.4426950408889634f));
    return r;
}

// ---------------- 1-pass fp16 GEMM: C = A @ Bh^T (+bias) ----------------
// CTA tile 128(M) x 128(N), 8 warps, warp tile 64x32, K chunk 64, 2 CTAs/SM.
// Stage: A(16K) + B(16K) = 32KB; 2 stages = 64KB.
#define ST_BYTES 32768u
#define OFF_BH 16384u
#define GEMM_DYN (2 * 32768 + 1024)

__device__ __forceinline__ void load_chunk(uint32_t base, int tid, int m0, int n0, int k0,
    const uint16_t* Ah, int lda, const uint16_t* Bh, int ldb)
{
#pragma unroll
    for (int it = 0; it < 4; it++) {
        int idx = it * 256 + tid;          // 0..1023
        int row = idx >> 3, u = idx & 7;
        uint32_t off = SWZ((uint32_t)(row * 128 + u * 16));
        CP16(base + off,          Ah + (size_t)(m0 + row) * lda + k0 + u * 8);
        CP16(base + OFF_BH + off, Bh + (size_t)(n0 + row) * ldb + k0 + u * 8);
    }
}

// mode 0: fp32 C; mode 1: fp16-hi C; mode 2: fused VAE; mode 3: combined ze|h
__global__ __launch_bounds__(256, 2)
void gemm_f16(const uint16_t* __restrict__ Ah, int lda,
              const uint16_t* __restrict__ Bh, int ldb,
              const float* __restrict__ bias,
              float* __restrict__ Cf, uint16_t* __restrict__ Ch,
              int ldc, int nOut, int K, int relu, int mode,
              const float* __restrict__ bias2, const float* __restrict__ eps,
              float* __restrict__ klq)
{
    extern __shared__ char smem[];
    const uint32_t tiles = (smem_to_u32(smem) + 1023) & ~1023u;
    const int tid = threadIdx.x, wid = tid >> 5, lane = tid & 31;
    const int m0 = blockIdx.y * 128, n0 = blockIdx.x * 128;
    const int wm = (wid >> 2) * 64, wn = (wid & 3) * 32;

    float acc[4][4][4];
#pragma unroll
    for (int i = 0; i < 4; i++)
#pragma unroll
        for (int j = 0; j < 4; j++)
#pragma unroll
            for (int q = 0; q < 4; q++) acc[i][j][q] = 0.f;

    const uint32_t aRowByte = (uint32_t)(wm + (lane & 15)) * 128u;
    const uint32_t aKoff    = (uint32_t)((lane >> 4) * 16);
    const uint32_t bRowByte = (uint32_t)(wn + (lane & 7) + ((lane >> 4) << 3)) * 128u;
    const uint32_t bKoff    = (uint32_t)(((lane >> 3) & 1) * 16);

    const int S = K / 64;
    load_chunk(tiles, tid, m0, n0, 0, Ah, lda, Bh, ldb);
    CP_COMMIT();

    for (int s = 0; s < S; s++) {
        if (s + 1 < S) {
            load_chunk(tiles + ((s + 1) & 1) * ST_BYTES, tid, m0, n0, (s + 1) * 64,
                       Ah, lda, Bh, ldb);
            CP_COMMIT();
            CP_WAIT1();
        } else {
            CP_WAIT0();
        }
        __syncthreads();

        const uint32_t pah = tiles + (s & 1) * ST_BYTES;
        const uint32_t pbh = pah + OFF_BH;
#pragma unroll
        for (int kk = 0; kk < 4; kk++) {
            const uint32_t kb = (uint32_t)(kk * 32);
            uint32_t ah[4][4], bh[2][4];
#pragma unroll
            for (int mt = 0; mt < 4; mt++)
                ldsm_x4(ah[mt], pah + SWZ(aRowByte + (uint32_t)(mt * 2048) + kb + aKoff));
#pragma unroll
            for (int nb = 0; nb < 2; nb++)
                ldsm_x4(bh[nb], pbh + SWZ(bRowByte + (uint32_t)(nb * 2048) + kb + bKoff));
#pragma unroll
            for (int mt = 0; mt < 4; mt++)
#pragma unroll
                for (int nt = 0; nt < 4; nt++)
                    mma_f16(acc[mt][nt], ah[mt], &bh[nt >> 1][(nt & 1) * 2]);
        }
        __syncthreads();
    }

    // ---- epilogue ----
    int emode = mode;
    const float* eb = bias;
    int erelu = relu;
    int cbase = n0;
    int ldcEff = ldc;
    if (mode == 3) {
        if (n0 < 512) { emode = 0; }
        else { emode = 1; eb = bias2; erelu = 1; cbase = n0 - 512; ldcEff = VDIM; }
    }

    if (emode == 0) {
#pragma unroll
        for (int mt = 0; mt < 4; mt++) {
            const int r0 = m0 + wm + mt * 16 + (lane >> 2);
            float* crow0 = Cf + (size_t)r0 * ldcEff;
            float* crow8 = Cf + (size_t)(r0 + 8) * ldcEff;
#pragma unroll
            for (int nt = 0; nt < 4; nt++) {
                const int c = cbase + wn + nt * 8 + (lane & 3) * 2;
                if (c >= nOut) continue;
                float b0 = eb[c], b1 = eb[c + 1];
                float v0 = acc[mt][nt][0] + b0, v1 = acc[mt][nt][1] + b1;
                float v2 = acc[mt][nt][2] + b0, v3 = acc[mt][nt][3] + b1;
                if (erelu) {
                    v0 = fmaxf(v0, 0.f); v1 = fmaxf(v1, 0.f);
                    v2 = fmaxf(v2, 0.f); v3 = fmaxf(v3, 0.f);
                }
                *reinterpret_cast<float2*>(crow0 + c) = make_float2(v0, v1);
                *reinterpret_cast<float2*>(crow8 + c) = make_float2(v2, v3);
            }
        }
    } else if (emode == 1) {
#pragma unroll
        for (int mt = 0; mt < 4; mt++) {
            const int r0 = m0 + wm + mt * 16 + (lane >> 2);
#pragma unroll
            for (int nt = 0; nt < 4; nt++) {
                const int c = cbase + wn + nt * 8 + (lane & 3) * 2;
                float b0 = eb[c], b1 = eb[c + 1];
                float v0 = acc[mt][nt][0] + b0, v1 = acc[mt][nt][1] + b1;
                float v2 = acc[mt][nt][2] + b0, v3 = acc[mt][nt][3] + b1;
                if (erelu) {
                    v0 = fmaxf(v0, 0.f); v1 = fmaxf(v1, 0.f);
                    v2 = fmaxf(v2, 0.f); v3 = fmaxf(v3, 0.f);
                }
                *reinterpret_cast<uint32_t*>(Ch + (size_t)r0 * ldcEff + c) = pack_hi2(v0, v1);
                *reinterpret_cast<uint32_t*>(Ch + (size_t)(r0 + 8) * ldcEff + c) = pack_hi2(v2, v3);
            }
        }
    } else {
        // mode 2: fused reparam + KL; z written hi-only
        float klsum = 0.f;
#pragma unroll
        for (int mt = 0; mt < 4; mt++) {
            const int r0 = m0 + wm + mt * 16 + (lane >> 2);
#pragma unroll
            for (int nt = 0; nt < 4; nt++) {
                const int c = n0 + wn + nt * 8 + (lane & 3) * 2;
                const int i = c >> 1;
                float bmu = bias[i], blv = bias[VDIM + i];
#pragma unroll
                for (int h = 0; h < 2; h++) {
                    const int r = r0 + h * 8;
                    float mu = acc[mt][nt][2 * h + 0] + bmu;
                    float lv = acc[mt][nt][2 * h + 1] + blv;
                    klsum += 0.5f * (fast_exp(lv) + mu * mu - 1.0f - lv);
                    float z = fmaf(fast_exp(0.5f * lv), eps[(size_t)r * VDIM + i], mu);
                    __half zh = __float2half_rn(z);
                    Ch[(size_t)r * ldc + i] = *reinterpret_cast<uint16_t*>(&zh);
                }
            }
        }
        float* sred = reinterpret_cast<float*>(smem);
        sred[tid] = klsum;
        __syncthreads();
        for (int st = 128; st > 0; st >>= 1) {
            if (tid < st) sred[tid] += sred[tid + st];
            __syncthreads();
        }
        if (tid == 0) klq[blockIdx.y * gridDim.x + blockIdx.x] = sred[0];
    }
}

__global__ __launch_bounds__(128)
void sgemm64(const float* __restrict__ A, const float* __restrict__ G,
             const float* __restrict__ lb, float* __restrict__ C)
{
    __shared__ float As[16][64];
    __shared__ float Bs[16][64];
    const int tid = threadIdx.x;
    const int m0 = blockIdx.x * 64;
    const int tx = tid & 15, ty = tid >> 4;
    const int lrow = tid >> 1, lhalf = tid & 1;
    float acc[8][4];
#pragma unroll
    for (int i = 0; i < 8; i++)
#pragma unroll
        for (int j = 0; j < 4; j++) acc[i][j] = 0.f;

    for (int k0 = 0; k0 < IN_DIM; k0 += 16) {
#pragma unroll
        for (int h = 0; h < 2; h++) {
            int kk = lhalf * 8 + h * 4;
            float4 va = *reinterpret_cast<const float4*>(A + (size_t)(m0 + lrow) * IN_DIM + k0 + kk);
            As[kk + 0][lrow] = va.x; As[kk + 1][lrow] = va.y;
            As[kk + 2][lrow] = va.z; As[kk + 3][lrow] = va.w;
            float4 vb = make_float4(0.f, 0.f, 0.f, 0.f);
            if (lrow < KCLS)
                vb = *reinterpret_cast<const float4*>(G + (size_t)lrow * IN_DIM + k0 + kk);
            Bs[kk + 0][lrow] = vb.x; Bs[kk + 1][lrow] = vb.y;
            Bs[kk + 2][lrow] = vb.z; Bs[kk + 3][lrow] = vb.w;
        }
        __syncthreads();
#pragma unroll
        for (int k = 0; k < 16; k++) {
            float4 a0 = *reinterpret_cast<const float4*>(&As[k][ty * 4]);
            float4 a1 = *reinterpret_cast<const float4*>(&As[k][32 + ty * 4]);
            float4 b  = *reinterpret_cast<const float4*>(&Bs[k][tx * 4]);
            float a[8] = {a0.x, a0.y, a0.z, a0.w, a1.x, a1.y, a1.z, a1.w};
            float bb[4] = {b.x, b.y, b.z, b.w};
#pragma unroll
            for (int i = 0; i < 8; i++)
#pragma unroll
                for (int j = 0; j < 4; j++)
                    acc[i][j] = fmaf(a[i], bb[j], acc[i][j]);
        }
        __syncthreads();
    }
#pragma unroll
    for (int i = 0; i < 8; i++) {
        int row = m0 + ((i < 4) ? (ty * 4 + i) : (32 + ty * 4 + i - 4));
#pragma unroll
        for (int j = 0; j < 4; j++) {
            int col = tx * 4 + j;
            if (col < KCLS) C[(size_t)row * KCLS + col] = acc[i][j] + lb[col];
        }
    }
}

__global__ void split_mat(const float* __restrict__ src, uint32_t* __restrict__ dh,
                          long nPairs, long srcPairs)
{
    long i = (long)blockIdx.x * blockDim.x + threadIdx.x;
    if (i >= nPairs) return;
    float v0 = 0.f, v1 = 0.f;
    if (i < srcPairs) {
        float2 v = reinterpret_cast<const float2*>(src)[i];
        v0 = v.x; v1 = v.y;
    }
    dh[i] = pack_hi2(v0, v1);
}

__global__ void split_w2(const float* __restrict__ W2)
{
    int i = blockIdx.x * blockDim.x + threadIdx.x;
    const int ppr = VDIM / 2;
    if (i >= 2 * VDIM * ppr) return;
    int rr = i / ppr, p = i - rr * ppr;
    int orig = (rr & 1) ? (VDIM + (rr >> 1)) : (rr >> 1);
    float2 v = *reinterpret_cast<const float2*>(W2 + (size_t)orig * VDIM + 2 * p);
    g_w2h[i] = pack_hi2(v.x, v.y);
}

__global__ void split_wd(const float* __restrict__ Wd)
{
    int i = blockIdx.x * blockDim.x + threadIdx.x;
    const int ppr = CAT_LD / 2;
    if (i >= IN_DIM * ppr) return;
    int r = i / ppr, p = i - r * ppr;
    int c0 = 2 * p;
    float v0 = (c0 < CAT_RAW) ? Wd[(size_t)r * CAT_RAW + c0] : 0.f;
    float v1 = (c0 + 1 < CAT_RAW) ? Wd[(size_t)r * CAT_RAW + c0 + 1] : 0.f;
    g_wdh[i] = pack_hi2(v0, v1);
}

__global__ void build_G(const float* __restrict__ W_enc, const float* __restrict__ cb)
{
    int c = blockIdx.x;
    int i = blockIdx.y * 128 + threadIdx.x;
    float s = 0.f;
#pragma unroll 4
    for (int d = 0; d < ENC_DIM; d++)
        s = fmaf(cb[c * ENC_DIM + d], W_enc[(size_t)d * IN_DIM + i], s);
    g_G[(size_t)c * IN_DIM + i] = s;
}
__global__ void build_lb(const float* __restrict__ b_enc, const float* __restrict__ cb)
{
    int c = blockIdx.x;
    int t = threadIdx.x;
    float s = 0.f;
    for (int d = t; d < ENC_DIM; d += 128) s = fmaf(b_enc[d], cb[c * ENC_DIM + d], s);
    __shared__ float sm[128];
    sm[t] = s;
    __syncthreads();
    for (int st = 64; st > 0; st >>= 1) { if (t < st) sm[t] += sm[t + st]; __syncthreads(); }
    if (t == 0) g_lb[c] = sm[0];
}

__global__ void detect_mask_kernel(const unsigned int* __restrict__ w)
{
    __shared__ int s_int, s_flt;
    if (threadIdx.x == 0) { s_int = 1; s_flt = 1; }
    __syncthreads();
    int li = 1, lf = 1;
    for (int i = threadIdx.x; i < 4096; i += blockDim.x) {
        unsigned v = w[i];
        if (v > 1u) li = 0;
        if (v != 0u && v != 0x3F800000u) lf = 0;
    }
    if (!li) atomicAnd(&s_int, 0);
    if (!lf) atomicAnd(&s_flt, 0);
    __syncthreads();
    if (threadIdx.x == 0) g_mask_mode = s_int ? 1 : (s_flt ? 2 : 0);
}

__global__ void argmax_y_kernel(const float* __restrict__ logits,
                                const void* __restrict__ mask,
                                const int* __restrict__ labels,
                                const float* __restrict__ codebook,
                                float* __restrict__ zq)
{
    const int b = blockIdx.x;
    const int lane = threadIdx.x;
    const float NEG = __int_as_float(0xff800000u);
    const float* lr = logits + (size_t)b * KCLS;
    const int k0 = 2 * lane, k1 = 2 * lane + 1;
    float va = (k0 < KCLS) ? lr[k0] : NEG;
    float vb = (k1 < KCLS) ? lr[k1] : NEG;
    float m; int mi;
    if (va >= vb) { m = va; mi = k0; } else { m = vb; mi = k1; }
#pragma unroll
    for (int off = 16; off > 0; off >>= 1) {
        float om = __shfl_xor_sync(0xffffffffu, m, off);
        int oi = __shfl_xor_sync(0xffffffffu, mi, off);
        if (om > m || (om == m && oi < mi)) { m = om; mi = oi; }
    }
    float ea = (k0 < KCLS) ? expf(va - m) : 0.f;
    float eb = (k1 < KCLS) ? expf(vb - m) : 0.f;
    float s = ea + eb;
#pragma unroll
    for (int off = 16; off > 0; off >>= 1) s += __shfl_xor_sync(0xffffffffu, s, off);
    float inv = 1.0f / s;

    int mode = g_mask_mode;
    bool known;
    if (mode == 1)      known = ((const int*)mask)[b] != 0;
    else if (mode == 2) known = ((const float*)mask)[b] != 0.f;
    else                known = ((const unsigned char*)mask)[b] != 0;
    int lab = labels[b];

    float y0 = (k0 < KCLS) ? (known ? (k0 == lab ? 1.f : 0.f) : ea * inv) : 0.f;
    float y1 = (k1 < KCLS) ? (known ? (k1 == lab ? 1.f : 0.f) : eb * inv) : 0.f;
    g_cath[(size_t)b * (CAT_LD / 2) + (VDIM / 2) + lane] = pack_hi2(y0, y1);

    const float* cr = codebook + (size_t)mi * ENC_DIM;
    float* zr = zq + (size_t)b * ENC_DIM;
    for (int i = lane; i < ENC_DIM; i += 32) zr[i] = cr[i];
}

__global__ void kl_reduce_kernel(float* __restrict__ out, int n)
{
    const int t = threadIdx.x;
    float s = 0.f;
    for (int i = t; i < n; i += 256) s += g_klq[i];
    __shared__ float sm[256];
    sm[t] = s;
    __syncthreads();
    for (int st = 128; st > 0; st >>= 1) { if (t < st) sm[t] += sm[t + st]; __syncthreads(); }
    if (t == 0) *out = sm[0] / (float)B_ROWS;
}

static void launch_gemm(const void* Ah, int lda,
                        const void* Bh, int ldb,
                        const float* bias, float* Cf, void* Ch,
                        int ldc, int nPad, int nOut, int K, int relu, int mode,
                        const float* bias2, const float* eps, float* klq)
{
    cudaFuncSetAttribute(gemm_f16, cudaFuncAttributeMaxDynamicSharedMemorySize, GEMM_DYN);
    dim3 grid(nPad / 128, B_ROWS / 128);
    gemm_f16<<<grid, 256, GEMM_DYN>>>(
        (const uint16_t*)Ah, lda, (const uint16_t*)Bh, ldb,
        bias, Cf, (uint16_t*)Ch, ldc, nOut, K, relu, mode,
        bias2, eps, klq);
}

extern "C" void kernel_launch(void* const* d_in, const int* in_sizes, int n_in,
                              void* d_out, int out_size)
{
    const float* x        = (const float*)d_in[0];
    const void*  mask     = d_in[1];
    const int*   labels   = (const int*)d_in[2];
    const float* eps      = (const float*)d_in[3];
    const float* W_enc    = (const float*)d_in[4];
    const float* b_enc    = (const float*)d_in[5];
    const float* codebook = (const float*)d_in[6];
    const float* W1       = (const float*)d_in[7];
    const float* b1       = (const float*)d_in[8];
    const float* W2       = (const float*)d_in[9];
    const float* b2       = (const float*)d_in[10];
    const float* Wd       = (const float*)d_in[11];
    const float* bd       = (const float*)d_in[12];
    float* out = (float*)d_out;

    void *p_xh, *p_wch, *p_w2h, *p_wdh, *p_hh, *p_cath;
    float *p_G, *p_lb, *p_klq, *p_ze, *p_zq, *p_lg, *p_kl;
    cudaGetSymbolAddress(&p_xh, g_xh);
    cudaGetSymbolAddress(&p_wch, g_wch);
    cudaGetSymbolAddress(&p_w2h, g_w2h);
    cudaGetSymbolAddress(&p_wdh, g_wdh);
    cudaGetSymbolAddress(&p_hh, g_hh);
    cudaGetSymbolAddress(&p_cath, g_cath);
    cudaGetSymbolAddress((void**)&p_G,  g_G);
    cudaGetSymbolAddress((void**)&p_lb, g_lb);
    cudaGetSymbolAddress((void**)&p_klq, g_klq);
    cudaGetSymbolAddress((void**)&p_ze, g_ze_s);
    cudaGetSymbolAddress((void**)&p_zq, g_zq_s);
    cudaGetSymbolAddress((void**)&p_lg, g_lg_s);
    cudaGetSymbolAddress((void**)&p_kl, g_kl_s);

    const size_t full_elems = (size_t)B_ROWS * (IN_DIM + ENC_DIM + ENC_DIM + KCLS) + 1;
    const bool full = ((size_t)out_size >= full_elems);
    float* xt = out;
    float* ze = full ? out + (size_t)B_ROWS * IN_DIM : p_ze;
    float* zq = full ? ze + (size_t)B_ROWS * ENC_DIM : p_zq;
    float* lg = full ? zq + (size_t)B_ROWS * ENC_DIM : p_lg;
    float* kl = full ? lg + (size_t)B_ROWS * KCLS    : p_kl;

    {
        long np = (long)B_ROWS * IN_DIM / 2;
        split_mat<<<(unsigned)((np + 255) / 256), 256>>>(x, (uint32_t*)p_xh, np, np);
        long wep = (long)512 * IN_DIM / 2, wes = (long)ENC_DIM * IN_DIM / 2;
        split_mat<<<(unsigned)((wep + 255) / 256), 256>>>(W_enc, (uint32_t*)p_wch, wep, wes);
        long w1p = (long)VDIM * IN_DIM / 2;
        split_mat<<<(unsigned)((w1p + 255) / 256), 256>>>(W1,
            (uint32_t*)p_wch + (size_t)512 * IN_DIM / 2, w1p, w1p);
        split_w2<<<(2 * VDIM * (VDIM / 2) + 255) / 256, 256>>>(W2);
        split_wd<<<(IN_DIM * (CAT_LD / 2) + 255) / 256, 256>>>(Wd);
    }
    detect_mask_kernel<<<1, 256>>>((const unsigned int*)mask);
    build_G<<<dim3(KCLS, IN_DIM / 128), 128>>>(W_enc, codebook);
    build_lb<<<KCLS, 128>>>(b_enc, codebook);

    sgemm64<<<B_ROWS / 64, 128>>>(x, p_G, p_lb, lg);

    // combined ze|h (mode 3) — 1-pass fp16
    launch_gemm(p_xh, IN_DIM, p_wch, IN_DIM, b_enc,
                ze, p_hh, ENC_DIM, NCOMB, ENC_DIM, IN_DIM, 0, 3,
                b1, nullptr, nullptr);
    // ml + fused VAE (mode 2)
    launch_gemm(p_hh, VDIM, p_w2h, VDIM, b2,
                nullptr, p_cath, CAT_LD, 2 * VDIM, 2 * VDIM, VDIM, 0, 2,
                nullptr, eps, p_klq);

    argmax_y_kernel<<<B_ROWS, 32>>>(lg, mask, labels, codebook, zq);
    kl_reduce_kernel<<<1, 256>>>(kl, (2 * VDIM / 128) * (B_ROWS / 128));

    // decoder — 1-pass fp16
    launch_gemm(p_cath, CAT_LD, p_wdh, CAT_LD, bd,
                xt, nullptr, IN_DIM, IN_DIM, IN_DIM, CAT_LD, 0, 0,
                nullptr, nullptr, nullptr);
}